// round 8
// baseline (speedup 1.0000x reference)
#include <cuda_runtime.h>
#include <cuda_bf16.h>
#include <math.h>
#include <stdint.h>

#define Bn  8
#define Tn  512
#define En  1024
#define Hn  16
#define Dn  64
#define Ln  4
#define FFn 4096

// fp32 scratch
__device__ float g_x[Bn * Tn * En];
__device__ float g_scores[Bn * Hn * Tn * Tn];
__device__ float g_proj[Bn * Tn * En];
// bf16 hi/lo activation pairs
__device__ __nv_bfloat16 g_xh[Bn * Tn * En],  g_xl[Bn * Tn * En];
__device__ __nv_bfloat16 g_ah[Bn * Tn * En],  g_al[Bn * Tn * En];
__device__ __nv_bfloat16 g_fh[Bn * Tn * FFn], g_fl[Bn * Tn * FFn];
__device__ __nv_bfloat16 g_qkvh[Bn * Tn * 3 * En], g_qkvl[Bn * Tn * 3 * En];
__device__ __nv_bfloat16 g_wprh[Bn * Hn * Tn * Tn], g_wprl[Bn * Hn * Tn * Tn];
// bf16 hi/lo weight pairs
__device__ __nv_bfloat16 g_wih[Ln * 3 * En * En], g_wil[Ln * 3 * En * En];
__device__ __nv_bfloat16 g_woh[Ln * En * En],     g_wol[Ln * En * En];
__device__ __nv_bfloat16 g_w1h[Ln * FFn * En],    g_w1l[Ln * FFn * En];
__device__ __nv_bfloat16 g_w2h[Ln * En * FFn],    g_w2l[Ln * En * FFn];

// ---------------- PTX helpers (sm_80+ only) ----------------
__device__ __forceinline__ uint32_t smem_u32(const void* p) {
    uint32_t a;
    asm("{ .reg .u64 t; cvta.to.shared.u64 t, %1; cvt.u32.u64 %0, t; }" : "=r"(a) : "l"(p));
    return a;
}
__device__ __forceinline__ void cpasync16(uint32_t dst, const void* src) {
    asm volatile("cp.async.cg.shared.global [%0], [%1], 16;" :: "r"(dst), "l"(src));
}
__device__ __forceinline__ void cp_commit() { asm volatile("cp.async.commit_group;" ::: "memory"); }
template <int N> __device__ __forceinline__ void cp_wait() {
    asm volatile("cp.async.wait_group %0;" :: "n"(N) : "memory");
}
__device__ __forceinline__ void ldsm4(uint32_t& r0, uint32_t& r1, uint32_t& r2,
                                      uint32_t& r3, uint32_t a) {
    asm volatile("ldmatrix.sync.aligned.m8n8.x4.shared.b16 {%0,%1,%2,%3}, [%4];"
                 : "=r"(r0), "=r"(r1), "=r"(r2), "=r"(r3) : "r"(a));
}
__device__ __forceinline__ void mma16816(float* d, const uint32_t* a, uint32_t b0, uint32_t b1) {
    asm volatile("mma.sync.aligned.m16n8k16.row.col.f32.bf16.bf16.f32 "
                 "{%0,%1,%2,%3}, {%4,%5,%6,%7}, {%8,%9}, {%0,%1,%2,%3};"
                 : "+f"(d[0]), "+f"(d[1]), "+f"(d[2]), "+f"(d[3])
                 : "r"(a[0]), "r"(a[1]), "r"(a[2]), "r"(a[3]), "r"(b0), "r"(b1));
}
__device__ __forceinline__ void split_hl(float v, __nv_bfloat16& h, __nv_bfloat16& l) {
    h = __float2bfloat16(v);
    l = __float2bfloat16(v - __bfloat162float(h));
}

// ---------------- reductions ----------------
__device__ __forceinline__ float warpSum(float v) {
#pragma unroll
    for (int o = 16; o; o >>= 1) v += __shfl_xor_sync(~0u, v, o);
    return v;
}
__device__ __forceinline__ float warpMax(float v) {
#pragma unroll
    for (int o = 16; o; o >>= 1) v = fmaxf(v, __shfl_xor_sync(~0u, v, o));
    return v;
}
__device__ __forceinline__ float blockSum(float v) {
    __shared__ float sm[8];
    int lane = threadIdx.x & 31, wid = threadIdx.x >> 5;
    v = warpSum(v);
    __syncthreads();
    if (lane == 0) sm[wid] = v;
    __syncthreads();
    v = sm[lane & 7];
#pragma unroll
    for (int o = 4; o; o >>= 1) v += __shfl_xor_sync(~0u, v, o);
    return v;
}
__device__ __forceinline__ float blockMax(float v) {
    __shared__ float sm[8];
    int lane = threadIdx.x & 31, wid = threadIdx.x >> 5;
    v = warpMax(v);
    __syncthreads();
    if (lane == 0) sm[wid] = v;
    __syncthreads();
    v = sm[lane & 7];
#pragma unroll
    for (int o = 4; o; o >>= 1) v = fmaxf(v, __shfl_xor_sync(~0u, v, o));
    return v;
}
__device__ __forceinline__ float2 blockSum2(float a, float b) {
    __shared__ float2 sm[8];
    int lane = threadIdx.x & 31, wid = threadIdx.x >> 5;
#pragma unroll
    for (int o = 16; o; o >>= 1) {
        a += __shfl_xor_sync(~0u, a, o);
        b += __shfl_xor_sync(~0u, b, o);
    }
    __syncthreads();
    if (lane == 0) sm[wid] = make_float2(a, b);
    __syncthreads();
    float2 v = sm[lane & 7];
#pragma unroll
    for (int o = 4; o; o >>= 1) {
        v.x += __shfl_xor_sync(~0u, v.x, o);
        v.y += __shfl_xor_sync(~0u, v.y, o);
    }
    return v;
}

// ---------------- small kernels ----------------
__global__ void convert_hl4(const float4* __restrict__ s,
                            __nv_bfloat162* __restrict__ h,
                            __nv_bfloat162* __restrict__ l) {
    int i = blockIdx.x * 256 + threadIdx.x;
    float4 v = s[i];
    __nv_bfloat16 h0,l0,h1,l1,h2,l2,h3,l3;
    split_hl(v.x, h0, l0); split_hl(v.y, h1, l1);
    split_hl(v.z, h2, l2); split_hl(v.w, h3, l3);
    __nv_bfloat162 a, b, c, d;
    a.x = h0; a.y = h1; b.x = h2; b.y = h3;
    c.x = l0; c.y = l1; d.x = l2; d.y = l3;
    h[2*i] = a; h[2*i+1] = b;
    l[2*i] = c; l[2*i+1] = d;
}

__global__ void pe_add_kernel(const float* __restrict__ src, float* __restrict__ x,
                              __nv_bfloat16* __restrict__ xh, __nv_bfloat16* __restrict__ xl) {
    int idx = blockIdx.x * 256 + threadIdx.x;
    int e = idx & (En - 1);
    int b = idx / (Tn * En);
    float dv = expf((float)(e & ~1) * (-9.210340371976184f / (float)En));
    float ang = (float)b * dv;
    float pe = (e & 1) ? cosf(ang) : sinf(ang);
    float v = src[idx] + pe;
    x[idx] = v;
    split_hl(v, xh[idx], xl[idx]);
}

// ---------------- fused hi/lo bf16 GEMM: CTA 128x256, warp 64x64 ----------------
// C[M, N] = (Ah+Al)[M,K] @ (Bh+Bl)[N,K]^T + bias  (AlBl dropped)
// 8 warps (2x4), BK=32, 3-stage cp.async pipeline, 48 KB/stage.
#define BM 128
#define BN2 256
#define BK 32
#define RGA 8192                    // A half region: 128x32 bf16
#define RGBB 16384                  // B half region: 256x32 bf16
#define STG2 (2 * RGA + 2 * RGBB)   // 48 KB per stage

__global__ __launch_bounds__(256, 1) void gemm_mma(
    const __nv_bfloat16* __restrict__ Ah, const __nv_bfloat16* __restrict__ Al,
    const __nv_bfloat16* __restrict__ Bh, const __nv_bfloat16* __restrict__ Bl,
    const float* __restrict__ bias, float* __restrict__ Cf,
    __nv_bfloat16* __restrict__ Ch, __nv_bfloat16* __restrict__ Cl,
    int K, int N, int relu)
{
    extern __shared__ __align__(128) uint8_t dsm[];
    __shared__ float sh_bias[BN2];

    const int tid = threadIdx.x;
    const uint32_t sbase = smem_u32(dsm);
    sh_bias[tid] = bias[blockIdx.x * BN2 + tid];

    const int wid = tid >> 5, lane = tid & 31;
    const int wm = wid >> 2, wn = wid & 3;   // 2 x 4 warp grid, warp tile 64x64

    const __nv_bfloat16* Abh = Ah + (size_t)blockIdx.y * BM * K;
    const __nv_bfloat16* Abl = Al + (size_t)blockIdx.y * BM * K;
    const __nv_bfloat16* Bbh = Bh + (size_t)blockIdx.x * BN2 * K;
    const __nv_bfloat16* Bbl = Bl + (size_t)blockIdx.x * BN2 * K;

    const int cps = K / BK;

    auto load_chunk = [&](int c, int st) {
        int kc = c * BK;
        uint32_t sg = sbase + (uint32_t)st * STG2;
        // A: 128 rows x 64B, hi+lo
#pragma unroll
        for (int j = 0; j < 2; j++) {
            int idx = tid + j * 256;
            int r = idx >> 2, cc = idx & 3;
            uint32_t off = r * 64 + ((cc ^ ((r >> 1) & 3)) << 4);
            size_t go = (size_t)r * K + kc + cc * 8;
            cpasync16(sg + off,       Abh + go);
            cpasync16(sg + RGA + off, Abl + go);
        }
        // B: 256 rows x 64B, hi+lo
        uint32_t sgB = sg + 2 * RGA;
#pragma unroll
        for (int j = 0; j < 4; j++) {
            int idx = tid + j * 256;
            int r = idx >> 2, cc = idx & 3;
            uint32_t off = r * 64 + ((cc ^ ((r >> 1) & 3)) << 4);
            size_t go = (size_t)r * K + kc + cc * 8;
            cpasync16(sgB + off,        Bbh + go);
            cpasync16(sgB + RGBB + off, Bbl + go);
        }
        cp_commit();
    };

    float acc[4][8][4] = {};
    load_chunk(0, 0);
    load_chunk(1, 1);

    int st = 0;
    for (int c = 0; c < cps; c++) {
        if (c + 1 < cps) cp_wait<1>(); else cp_wait<0>();
        __syncthreads();
        if (c + 2 < cps) {
            int ns = st + 2; if (ns >= 3) ns -= 3;
            load_chunk(c + 2, ns);
        }

        uint32_t sAh = sbase + (uint32_t)st * STG2;
        uint32_t sAl = sAh + RGA;
        uint32_t sBh = sAh + 2 * RGA;
        uint32_t sBl = sBh + RGBB;
#pragma unroll
        for (int ks = 0; ks < 2; ks++) {
            uint32_t ahf[4][4], alf[4][4];
#pragma unroll
            for (int ti = 0; ti < 4; ti++) {
                int r = wm * 64 + ti * 16 + (lane & 15);
                int cc = 2 * ks + (lane >> 4);
                uint32_t off = r * 64 + ((cc ^ ((r >> 1) & 3)) << 4);
                ldsm4(ahf[ti][0], ahf[ti][1], ahf[ti][2], ahf[ti][3], sAh + off);
                ldsm4(alf[ti][0], alf[ti][1], alf[ti][2], alf[ti][3], sAl + off);
            }
#pragma unroll
            for (int tj = 0; tj < 4; tj++) {
                int r = wn * 64 + tj * 16 + (lane & 15);
                int cc = 2 * ks + (lane >> 4);
                uint32_t off = r * 64 + ((cc ^ ((r >> 1) & 3)) << 4);
                uint32_t b0, b1, b2, b3, c0, c1, c2, c3;
                ldsm4(b0, b1, b2, b3, sBh + off);
                ldsm4(c0, c1, c2, c3, sBl + off);
#pragma unroll
                for (int ti = 0; ti < 4; ti++) {
                    mma16816(acc[ti][2 * tj],     ahf[ti], b0, b2);
                    mma16816(acc[ti][2 * tj + 1], ahf[ti], b1, b3);
                    mma16816(acc[ti][2 * tj],     alf[ti], b0, b2);
                    mma16816(acc[ti][2 * tj + 1], alf[ti], b1, b3);
                    mma16816(acc[ti][2 * tj],     ahf[ti], c0, c2);
                    mma16816(acc[ti][2 * tj + 1], ahf[ti], c1, c3);
                }
            }
        }
        if (++st == 3) st = 0;
    }

    const int col0 = wn * 64;
    const int row0 = blockIdx.y * BM + wm * 64;
#pragma unroll
    for (int ti = 0; ti < 4; ti++) {
#pragma unroll
        for (int tj = 0; tj < 8; tj++) {
            int cl = col0 + tj * 8 + 2 * (lane & 3);
            int colg = blockIdx.x * BN2 + cl;
            float b0 = sh_bias[cl], b1 = sh_bias[cl + 1];
#pragma unroll
            for (int hh = 0; hh < 2; hh++) {
                int row = row0 + ti * 16 + (lane >> 2) + hh * 8;
                float v0 = acc[ti][tj][2 * hh + 0] + b0;
                float v1 = acc[ti][tj][2 * hh + 1] + b1;
                if (relu) { v0 = fmaxf(v0, 0.f); v1 = fmaxf(v1, 0.f); }
                size_t o = (size_t)row * N + colg;
                if (Cf) *(float2*)(Cf + o) = make_float2(v0, v1);
                if (Ch) {
                    __nv_bfloat16 h0, l0, h1, l1;
                    split_hl(v0, h0, l0);
                    split_hl(v1, h1, l1);
                    __nv_bfloat162 hv; hv.x = h0; hv.y = h1;
                    __nv_bfloat162 lv; lv.x = l0; lv.y = l1;
                    *(__nv_bfloat162*)(Ch + o) = hv;
                    *(__nv_bfloat162*)(Cl + o) = lv;
                }
            }
        }
    }
}

// ---------------- scores: S = Q K^T / 8 (fused hi/lo, K=64 -> 2 chunks) ----------------
#define RGB 8192
#define STGB (4 * RGB)

__global__ __launch_bounds__(256, 2) void scores_mma(
    const __nv_bfloat16* __restrict__ qh, const __nv_bfloat16* __restrict__ ql,
    float* __restrict__ sc)
{
    extern __shared__ __align__(128) uint8_t dsm[];
    const int tid = threadIdx.x;
    const uint32_t sbase = smem_u32(dsm);
    const int wid = tid >> 5, lane = tid & 31;
    const int wm = wid >> 1, wn = wid & 1;
    const int bh = blockIdx.z, b = bh >> 4, h = bh & 15;
    const int LDQ = 3 * En;

    const __nv_bfloat16* Qhb = qh + (size_t)b * Tn * LDQ + h * Dn + (size_t)blockIdx.y * 128 * LDQ;
    const __nv_bfloat16* Qlb = ql + (size_t)b * Tn * LDQ + h * Dn + (size_t)blockIdx.y * 128 * LDQ;
    const __nv_bfloat16* Khb = qh + (size_t)b * Tn * LDQ + En + h * Dn + (size_t)blockIdx.x * 128 * LDQ;
    const __nv_bfloat16* Klb = ql + (size_t)b * Tn * LDQ + En + h * Dn + (size_t)blockIdx.x * 128 * LDQ;

    auto load_chunk = [&](int c, int stg) {
        int kc = c * BK;
        uint32_t sg = sbase + (uint32_t)stg * STGB;
#pragma unroll
        for (int j = 0; j < 2; j++) {
            int idx = tid + j * 256;
            int r = idx >> 2, cc = idx & 3;
            uint32_t off = r * 64 + ((cc ^ ((r >> 1) & 3)) << 4);
            size_t go = (size_t)r * LDQ + kc + cc * 8;
            cpasync16(sg + off,           Qhb + go);
            cpasync16(sg + RGB + off,     Qlb + go);
            cpasync16(sg + 2 * RGB + off, Khb + go);
            cpasync16(sg + 3 * RGB + off, Klb + go);
        }
        cp_commit();
    };

    float acc[2][8][4] = {};
    load_chunk(0, 0);
    load_chunk(1, 1);

    for (int c = 0; c < 2; c++) {
        if (c == 0) cp_wait<1>(); else cp_wait<0>();
        __syncthreads();
        uint32_t sAh = sbase + (uint32_t)c * STGB;
        uint32_t sAl = sAh + RGB;
        uint32_t sBh = sAh + 2 * RGB;
        uint32_t sBl = sAh + 3 * RGB;
#pragma unroll
        for (int ks = 0; ks < 2; ks++) {
            uint32_t ah[2][4], al[2][4];
#pragma unroll
            for (int ti = 0; ti < 2; ti++) {
                int r = wm * 32 + ti * 16 + (lane & 15);
                int cc = 2 * ks + (lane >> 4);
                uint32_t off = r * 64 + ((cc ^ ((r >> 1) & 3)) << 4);
                ldsm4(ah[ti][0], ah[ti][1], ah[ti][2], ah[ti][3], sAh + off);
                ldsm4(al[ti][0], al[ti][1], al[ti][2], al[ti][3], sAl + off);
            }
#pragma unroll
            for (int tj = 0; tj < 4; tj++) {
                int r = wn * 64 + tj * 16 + (lane & 15);
                int cc = 2 * ks + (lane >> 4);
                uint32_t off = r * 64 + ((cc ^ ((r >> 1) & 3)) << 4);
                uint32_t b0, b1, b2, b3, c0, c1, c2, c3;
                ldsm4(b0, b1, b2, b3, sBh + off);
                ldsm4(c0, c1, c2, c3, sBl + off);
                mma16816(acc[0][2 * tj],     ah[0], b0, b2);
                mma16816(acc[0][2 * tj + 1], ah[0], b1, b3);
                mma16816(acc[1][2 * tj],     ah[1], b0, b2);
                mma16816(acc[1][2 * tj + 1], ah[1], b1, b3);
                mma16816(acc[0][2 * tj],     al[0], b0, b2);
                mma16816(acc[0][2 * tj + 1], al[0], b1, b3);
                mma16816(acc[1][2 * tj],     al[1], b0, b2);
                mma16816(acc[1][2 * tj + 1], al[1], b1, b3);
                mma16816(acc[0][2 * tj],     ah[0], c0, c2);
                mma16816(acc[0][2 * tj + 1], ah[0], c1, c3);
                mma16816(acc[1][2 * tj],     ah[1], c0, c2);
                mma16816(acc[1][2 * tj + 1], ah[1], c1, c3);
            }
        }
    }

    float* outb = sc + (size_t)bh * Tn * Tn + blockIdx.x * 128;
    const int col0 = wn * 64;
    const int row0 = blockIdx.y * 128 + wm * 32;
#pragma unroll
    for (int ti = 0; ti < 2; ti++) {
#pragma unroll
        for (int tj = 0; tj < 8; tj++) {
            int cl = col0 + tj * 8 + 2 * (lane & 3);
#pragma unroll
            for (int hh = 0; hh < 2; hh++) {
                int row = row0 + ti * 16 + (lane >> 2) + hh * 8;
                *(float2*)(outb + (size_t)row * Tn + cl) =
                    make_float2(acc[ti][tj][2 * hh] * 0.125f, acc[ti][tj][2 * hh + 1] * 0.125f);
            }
        }
    }
}

// ---------------- softmax * gaussian * renorm -> bf16 hi/lo probs ----------------
__global__ __launch_bounds__(256) void softmax_gauss(
    const float* __restrict__ sc,
    __nv_bfloat16* __restrict__ wh, __nv_bfloat16* __restrict__ wl)
{
    const int q = blockIdx.x & (Tn - 1);
    const float* row = sc + (size_t)blockIdx.x * Tn;
    const int tid = threadIdx.x;
    float s0 = row[tid], s1 = row[tid + 256];
    float m = blockMax(fmaxf(s0, s1));
    float p0 = __expf(s0 - m), p1 = __expf(s1 - m);
    float d0 = (float)(q - tid), d1 = (float)(q - (tid + 256));
    float g0 = __expf(-d0 * d0 * (1.0f / 32768.0f));
    float g1 = __expf(-d1 * d1 * (1.0f / 32768.0f));
    float2 zg = blockSum2(p0 + p1, p0 * g0 + p1 * g1);
    float inv = 1.0f / (zg.y + 1e-5f * zg.x);
    float w0 = p0 * g0 * inv, w1 = p1 * g1 * inv;
    size_t base = (size_t)blockIdx.x * Tn;
    __nv_bfloat16 h0, l0, h1, l1;
    split_hl(w0, h0, l0);
    split_hl(w1, h1, l1);
    wh[base + tid] = h0;       wl[base + tid] = l0;
    wh[base + tid + 256] = h1; wl[base + tid + 256] = l1;
}

// ---------------- attn output: O = W V (fused hi/lo, 16 chunks) ----------------
__global__ __launch_bounds__(256, 2) void attno_mma(
    const __nv_bfloat16* __restrict__ wh, const __nv_bfloat16* __restrict__ wl,
    const __nv_bfloat16* __restrict__ vh, const __nv_bfloat16* __restrict__ vl,
    __nv_bfloat16* __restrict__ oh, __nv_bfloat16* __restrict__ ol)
{
    extern __shared__ __align__(128) uint8_t dsm[];
    const int tid = threadIdx.x;
    const uint32_t sbase = smem_u32(dsm);
    const uint32_t bOff = 49152;
    const int wid = tid >> 5, lane = tid & 31;
    const int wm = wid >> 1, wn = wid & 1;
    const int bh = blockIdx.y, b = bh >> 4, h = bh & 15;
    const int LDQ = 3 * En;

    const __nv_bfloat16* Wh = wh + (size_t)bh * Tn * Tn + (size_t)blockIdx.x * 128 * Tn;
    const __nv_bfloat16* Wl = wl + (size_t)bh * Tn * Tn + (size_t)blockIdx.x * 128 * Tn;
    const __nv_bfloat16* Vhb = vh + (size_t)b * Tn * LDQ + 2 * En + h * Dn;
    const __nv_bfloat16* Vlb = vl + (size_t)b * Tn * LDQ + 2 * En + h * Dn;

    const int vr = tid >> 3;
    const int vc = (tid & 7) * 8;

    auto loadA = [&](int c, int stg) {
        int kc = c * BK;
        uint32_t sg = sbase + (uint32_t)stg * 16384;
#pragma unroll
        for (int j = 0; j < 2; j++) {
            int idx = tid + j * 256;
            int r = idx >> 2, cc = idx & 3;
            uint32_t off = r * 64 + ((cc ^ ((r >> 1) & 3)) << 4);
            size_t go = (size_t)r * Tn + kc + cc * 8;
            cpasync16(sg + off,        Wh + go);
            cpasync16(sg + 8192 + off, Wl + go);
        }
        cp_commit();
    };

    const int C = 16;
    uint4 vrh = *(const uint4*)(Vhb + (size_t)vr * LDQ + vc);
    uint4 vrl = *(const uint4*)(Vlb + (size_t)vr * LDQ + vc);
    loadA(0, 0); loadA(1, 1);

    float acc[2][4][4] = {};
    int st = 0;
    for (int c = 0; c < C; c++) {
        {
            uint32_t wh4[4] = {vrh.x, vrh.y, vrh.z, vrh.w};
            uint32_t wl4[4] = {vrl.x, vrl.y, vrl.z, vrl.w};
            uint32_t bb = bOff + (uint32_t)(c & 1) * 8192;
#pragma unroll
            for (int i = 0; i < 8; i++) {
                uint16_t hv = (uint16_t)(wh4[i >> 1] >> ((i & 1) * 16));
                uint16_t lv = (uint16_t)(wl4[i >> 1] >> ((i & 1) * 16));
                int d = vc + i;
                int fd = ((d >> 1) & 3) ^ ((d >> 3) & 3);
                uint32_t off = d * 64 + (((vr >> 3) ^ fd) << 4) + (vr & 7) * 2;
                *(uint16_t*)(dsm + bb + off) = hv;
                *(uint16_t*)(dsm + bb + 4096 + off) = lv;
            }
        }
        if (c + 1 < C) {
            int kc = (c + 1) * BK;
            vrh = *(const uint4*)(Vhb + (size_t)(kc + vr) * LDQ + vc);
            vrl = *(const uint4*)(Vlb + (size_t)(kc + vr) * LDQ + vc);
        }
        if (c + 1 < C) cp_wait<1>(); else cp_wait<0>();
        __syncthreads();
        if (c + 2 < C) {
            int ns = st + 2; if (ns >= 3) ns -= 3;
            loadA(c + 2, ns);
        }

        uint32_t sAh = sbase + (uint32_t)st * 16384;
        uint32_t sAl = sAh + 8192;
        uint32_t sBh = sbase + bOff + (uint32_t)(c & 1) * 8192;
        uint32_t sBl = sBh + 4096;
#pragma unroll
        for (int ks = 0; ks < 2; ks++) {
            uint32_t ah[2][4], al[2][4];
#pragma unroll
            for (int ti = 0; ti < 2; ti++) {
                int r = wm * 32 + ti * 16 + (lane & 15);
                int cc = 2 * ks + (lane >> 4);
                uint32_t off = r * 64 + ((cc ^ ((r >> 1) & 3)) << 4);
                ldsm4(ah[ti][0], ah[ti][1], ah[ti][2], ah[ti][3], sAh + off);
                ldsm4(al[ti][0], al[ti][1], al[ti][2], al[ti][3], sAl + off);
            }
#pragma unroll
            for (int tj = 0; tj < 2; tj++) {
                int r = wn * 32 + tj * 16 + (lane & 15);
                int cc = 2 * ks + (lane >> 4);
                int fd = ((r >> 1) & 3) ^ ((r >> 3) & 3);
                uint32_t off = r * 64 + ((cc ^ fd) << 4);
                uint32_t b0, b1, b2, b3, c0, c1, c2, c3;
                ldsm4(b0, b1, b2, b3, sBh + off);
                ldsm4(c0, c1, c2, c3, sBl + off);
                mma16816(acc[0][2 * tj],     ah[0], b0, b2);
                mma16816(acc[0][2 * tj + 1], ah[0], b1, b3);
                mma16816(acc[1][2 * tj],     ah[1], b0, b2);
                mma16816(acc[1][2 * tj + 1], ah[1], b1, b3);
                mma16816(acc[0][2 * tj],     al[0], b0, b2);
                mma16816(acc[0][2 * tj + 1], al[0], b1, b3);
                mma16816(acc[1][2 * tj],     al[1], b0, b2);
                mma16816(acc[1][2 * tj + 1], al[1], b1, b3);
                mma16816(acc[0][2 * tj],     ah[0], c0, c2);
                mma16816(acc[0][2 * tj + 1], ah[0], c1, c3);
                mma16816(acc[1][2 * tj],     ah[1], c0, c2);
                mma16816(acc[1][2 * tj + 1], ah[1], c1, c3);
            }
        }
        if (++st == 3) st = 0;
    }

#pragma unroll
    for (int ti = 0; ti < 2; ti++) {
#pragma unroll
        for (int tj = 0; tj < 4; tj++) {
            int dl = wn * 32 + tj * 8 + 2 * (lane & 3);
            int colg = h * Dn + dl;
#pragma unroll
            for (int hh = 0; hh < 2; hh++) {
                int row = blockIdx.x * 128 + wm * 32 + ti * 16 + (lane >> 2) + hh * 8;
                float v0 = acc[ti][tj][2 * hh + 0];
                float v1 = acc[ti][tj][2 * hh + 1];
                __nv_bfloat16 h0, l0, h1, l1;
                split_hl(v0, h0, l0);
                split_hl(v1, h1, l1);
                __nv_bfloat162 hv; hv.x = h0; hv.y = h1;
                __nv_bfloat162 lv; lv.x = l0; lv.y = l1;
                size_t o = (size_t)b * Tn * En + (size_t)row * En + colg;
                *(__nv_bfloat162*)(oh + o) = hv;
                *(__nv_bfloat162*)(ol + o) = lv;
            }
        }
    }
}

// ---------------- residual + LN ----------------
__global__ __launch_bounds__(256) void add_ln(
    float* __restrict__ x, const float* __restrict__ r,
    const float* __restrict__ g, const float* __restrict__ bt,
    __nv_bfloat16* __restrict__ xh, __nv_bfloat16* __restrict__ xl)
{
    const size_t base = (size_t)blockIdx.x * En;
    const int tid = threadIdx.x;
    float v[4];
#pragma unroll
    for (int i = 0; i < 4; i++) { int c = tid + i * 256; v[i] = x[base + c] + r[base + c]; }
    float mu = blockSum(v[0] + v[1] + v[2] + v[3]) * (1.0f / En);
    float var = 0.f;
#pragma unroll
    for (int i = 0; i < 4; i++) { float d = v[i] - mu; var += d * d; }
    var = blockSum(var) * (1.0f / En);
    float rs = rsqrtf(var + 1e-5f);
#pragma unroll
    for (int i = 0; i < 4; i++) {
        int c = tid + i * 256;
        float o = (v[i] - mu) * rs * g[c] + bt[c];
        x[base + c] = o;
        split_hl(o, xh[base + c], xl[base + c]);
    }
}

__global__ __launch_bounds__(256) void head_kernel(
    const float* __restrict__ x, const float* __restrict__ hw,
    const float* __restrict__ hb, float* __restrict__ out)
{
    const int b = blockIdx.x;
    const int tid = threadIdx.x;
    const float* row = x + (size_t)b * Tn * En + (size_t)(Tn - 1) * En;
    float s = 0.f;
    for (int c = tid; c < En; c += 256) s += row[c] * hw[c];
    s = blockSum(s);
    if (tid == 0) out[b] = s + hb[0];
}

// ---------------- launch ----------------
extern "C" void kernel_launch(void* const* d_in, const int* in_sizes, int n_in,
                              void* d_out, int out_size)
{
    const float* src    = (const float*)d_in[0];
    const float* in_w   = (const float*)d_in[1];
    const float* in_b   = (const float*)d_in[2];
    const float* outp_w = (const float*)d_in[3];
    const float* outp_b = (const float*)d_in[4];
    const float* ff1_w  = (const float*)d_in[5];
    const float* ff1_b  = (const float*)d_in[6];
    const float* ff2_w  = (const float*)d_in[7];
    const float* ff2_b  = (const float*)d_in[8];
    const float* ln1_g  = (const float*)d_in[9];
    const float* ln1_b  = (const float*)d_in[10];
    const float* ln2_g  = (const float*)d_in[11];
    const float* ln2_b  = (const float*)d_in[12];
    const float* head_w = (const float*)d_in[13];
    const float* head_b = (const float*)d_in[14];
    float* out = (float*)d_out;

    static bool init = false;
    static float *x, *sc, *proj;
    static __nv_bfloat16 *xh,*xl,*ah,*al,*fh,*fl,*qkvh,*qkvl,*wprh,*wprl,
                         *wih,*wil,*woh,*wol,*w1h,*w1l,*w2h,*w2l;
    if (!init) {
        cudaGetSymbolAddress((void**)&x, g_x);
        cudaGetSymbolAddress((void**)&sc, g_scores);
        cudaGetSymbolAddress((void**)&proj, g_proj);
        cudaGetSymbolAddress((void**)&xh, g_xh); cudaGetSymbolAddress((void**)&xl, g_xl);
        cudaGetSymbolAddress((void**)&ah, g_ah); cudaGetSymbolAddress((void**)&al, g_al);
        cudaGetSymbolAddress((void**)&fh, g_fh); cudaGetSymbolAddress((void**)&fl, g_fl);
        cudaGetSymbolAddress((void**)&qkvh, g_qkvh); cudaGetSymbolAddress((void**)&qkvl, g_qkvl);
        cudaGetSymbolAddress((void**)&wprh, g_wprh); cudaGetSymbolAddress((void**)&wprl, g_wprl);
        cudaGetSymbolAddress((void**)&wih, g_wih); cudaGetSymbolAddress((void**)&wil, g_wil);
        cudaGetSymbolAddress((void**)&woh, g_woh); cudaGetSymbolAddress((void**)&wol, g_wol);
        cudaGetSymbolAddress((void**)&w1h, g_w1h); cudaGetSymbolAddress((void**)&w1l, g_w1l);
        cudaGetSymbolAddress((void**)&w2h, g_w2h); cudaGetSymbolAddress((void**)&w2l, g_w2l);
        cudaFuncSetAttribute(gemm_mma, cudaFuncAttributeMaxDynamicSharedMemorySize, 3 * STG2);
        cudaFuncSetAttribute(scores_mma, cudaFuncAttributeMaxDynamicSharedMemorySize, 2 * STGB);
        cudaFuncSetAttribute(attno_mma, cudaFuncAttributeMaxDynamicSharedMemorySize, 65536);
        init = true;
    }

    // weight -> hi/lo bf16
    convert_hl4<<<Ln * 3 * En * En / 1024, 256>>>((const float4*)in_w,
        (__nv_bfloat162*)wih, (__nv_bfloat162*)wil);
    convert_hl4<<<Ln * En * En / 1024, 256>>>((const float4*)outp_w,
        (__nv_bfloat162*)woh, (__nv_bfloat162*)wol);
    convert_hl4<<<Ln * FFn * En / 1024, 256>>>((const float4*)ff1_w,
        (__nv_bfloat162*)w1h, (__nv_bfloat162*)w1l);
    convert_hl4<<<Ln * En * FFn / 1024, 256>>>((const float4*)ff2_w,
        (__nv_bfloat162*)w2h, (__nv_bfloat162*)w2l);

    pe_add_kernel<<<Bn * Tn * En / 256, 256>>>(src, x, xh, xl);

    for (int l = 0; l < Ln; l++) {
        size_t wo3 = (size_t)l * 3 * En * En, wo1 = (size_t)l * En * En;
        size_t wof = (size_t)l * FFn * En;
        // qkv (bf16 hi/lo out only)
        gemm_mma<<<dim3(3 * En / BN2, Bn * Tn / BM), 256, 3 * STG2>>>(
            xh, xl, wih + wo3, wil + wo3, in_b + (size_t)l * 3 * En,
            nullptr, qkvh, qkvl, En, 3 * En, 0);
        scores_mma<<<dim3(4, 4, Bn * Hn), 256, 2 * STGB>>>(qkvh, qkvl, sc);
        softmax_gauss<<<Bn * Hn * Tn, 256>>>(sc, wprh, wprl);
        attno_mma<<<dim3(4, Bn * Hn), 256, 65536>>>(wprh, wprl, qkvh, qkvl, ah, al);
        // out proj
        gemm_mma<<<dim3(En / BN2, Bn * Tn / BM), 256, 3 * STG2>>>(
            ah, al, woh + wo1, wol + wo1, outp_b + (size_t)l * En,
            proj, nullptr, nullptr, En, En, 0);
        add_ln<<<Bn * Tn, 256>>>(x, proj, ln1_g + (size_t)l * En, ln1_b + (size_t)l * En, xh, xl);
        // ff1 (relu, hl out)
        gemm_mma<<<dim3(FFn / BN2, Bn * Tn / BM), 256, 3 * STG2>>>(
            xh, xl, w1h + wof, w1l + wof, ff1_b + (size_t)l * FFn,
            nullptr, fh, fl, En, FFn, 1);
        // ff2
        gemm_mma<<<dim3(En / BN2, Bn * Tn / BM), 256, 3 * STG2>>>(
            fh, fl, w2h + wof, w2l + wof, ff2_b + (size_t)l * En,
            proj, nullptr, nullptr, FFn, En, 0);
        add_ln<<<Bn * Tn, 256>>>(x, proj, ln2_g + (size_t)l * En, ln2_b + (size_t)l * En, xh, xl);
    }

    head_kernel<<<Bn, 256>>>(x, head_w, head_b, out);
}

// round 9
// speedup vs baseline: 1.1510x; 1.1510x over previous
#include <cuda_runtime.h>
#include <cuda_bf16.h>
#include <math.h>
#include <stdint.h>

#define Bn  8
#define Tn  512
#define En  1024
#define Hn  16
#define Dn  64
#define Ln  4
#define FFn 4096

// fp32 scratch
__device__ float g_x[Bn * Tn * En];
__device__ float g_proj[Bn * Tn * En];
// bf16 hi/lo activation pairs
__device__ __nv_bfloat16 g_xh[Bn * Tn * En],  g_xl[Bn * Tn * En];
__device__ __nv_bfloat16 g_ah[Bn * Tn * En],  g_al[Bn * Tn * En];
__device__ __nv_bfloat16 g_fh[Bn * Tn * FFn], g_fl[Bn * Tn * FFn];
__device__ __nv_bfloat16 g_qkvh[Bn * Tn * 3 * En], g_qkvl[Bn * Tn * 3 * En];
// bf16 hi/lo weight pairs
__device__ __nv_bfloat16 g_wih[Ln * 3 * En * En], g_wil[Ln * 3 * En * En];
__device__ __nv_bfloat16 g_woh[Ln * En * En],     g_wol[Ln * En * En];
__device__ __nv_bfloat16 g_w1h[Ln * FFn * En],    g_w1l[Ln * FFn * En];
__device__ __nv_bfloat16 g_w2h[Ln * En * FFn],    g_w2l[Ln * En * FFn];

// ---------------- PTX helpers (sm_80+ only) ----------------
__device__ __forceinline__ uint32_t smem_u32(const void* p) {
    uint32_t a;
    asm("{ .reg .u64 t; cvta.to.shared.u64 t, %1; cvt.u32.u64 %0, t; }" : "=r"(a) : "l"(p));
    return a;
}
__device__ __forceinline__ void cpasync16(uint32_t dst, const void* src) {
    asm volatile("cp.async.cg.shared.global [%0], [%1], 16;" :: "r"(dst), "l"(src));
}
__device__ __forceinline__ void cp_commit() { asm volatile("cp.async.commit_group;" ::: "memory"); }
template <int N> __device__ __forceinline__ void cp_wait() {
    asm volatile("cp.async.wait_group %0;" :: "n"(N) : "memory");
}
__device__ __forceinline__ void ldsm4(uint32_t& r0, uint32_t& r1, uint32_t& r2,
                                      uint32_t& r3, uint32_t a) {
    asm volatile("ldmatrix.sync.aligned.m8n8.x4.shared.b16 {%0,%1,%2,%3}, [%4];"
                 : "=r"(r0), "=r"(r1), "=r"(r2), "=r"(r3) : "r"(a));
}
__device__ __forceinline__ void mma16816(float* d, const uint32_t* a, uint32_t b0, uint32_t b1) {
    asm volatile("mma.sync.aligned.m16n8k16.row.col.f32.bf16.bf16.f32 "
                 "{%0,%1,%2,%3}, {%4,%5,%6,%7}, {%8,%9}, {%0,%1,%2,%3};"
                 : "+f"(d[0]), "+f"(d[1]), "+f"(d[2]), "+f"(d[3])
                 : "r"(a[0]), "r"(a[1]), "r"(a[2]), "r"(a[3]), "r"(b0), "r"(b1));
}
__device__ __forceinline__ void split_hl(float v, __nv_bfloat16& h, __nv_bfloat16& l) {
    h = __float2bfloat16(v);
    l = __float2bfloat16(v - __bfloat162float(h));
}

// ---------------- reductions ----------------
__device__ __forceinline__ float warpSum(float v) {
#pragma unroll
    for (int o = 16; o; o >>= 1) v += __shfl_xor_sync(~0u, v, o);
    return v;
}
__device__ __forceinline__ float blockSum(float v) {
    __shared__ float sm[8];
    int lane = threadIdx.x & 31, wid = threadIdx.x >> 5;
    v = warpSum(v);
    __syncthreads();
    if (lane == 0) sm[wid] = v;
    __syncthreads();
    v = sm[lane & 7];
#pragma unroll
    for (int o = 4; o; o >>= 1) v += __shfl_xor_sync(~0u, v, o);
    return v;
}
__device__ __forceinline__ float2 blockSum2(float a, float b) {
    __shared__ float2 sm[8];
    int lane = threadIdx.x & 31, wid = threadIdx.x >> 5;
#pragma unroll
    for (int o = 16; o; o >>= 1) {
        a += __shfl_xor_sync(~0u, a, o);
        b += __shfl_xor_sync(~0u, b, o);
    }
    __syncthreads();
    if (lane == 0) sm[wid] = make_float2(a, b);
    __syncthreads();
    float2 v = sm[lane & 7];
#pragma unroll
    for (int o = 4; o; o >>= 1) {
        v.x += __shfl_xor_sync(~0u, v.x, o);
        v.y += __shfl_xor_sync(~0u, v.y, o);
    }
    return v;
}

// ---------------- small kernels ----------------
__global__ void convert_hl4(const float4* __restrict__ s,
                            __nv_bfloat162* __restrict__ h,
                            __nv_bfloat162* __restrict__ l) {
    int i = blockIdx.x * 256 + threadIdx.x;
    float4 v = s[i];
    __nv_bfloat16 h0,l0,h1,l1,h2,l2,h3,l3;
    split_hl(v.x, h0, l0); split_hl(v.y, h1, l1);
    split_hl(v.z, h2, l2); split_hl(v.w, h3, l3);
    __nv_bfloat162 a, b, c, d;
    a.x = h0; a.y = h1; b.x = h2; b.y = h3;
    c.x = l0; c.y = l1; d.x = l2; d.y = l3;
    h[2*i] = a; h[2*i+1] = b;
    l[2*i] = c; l[2*i+1] = d;
}

__global__ void pe_add_kernel(const float* __restrict__ src, float* __restrict__ x,
                              __nv_bfloat16* __restrict__ xh, __nv_bfloat16* __restrict__ xl) {
    int idx = blockIdx.x * 256 + threadIdx.x;
    int e = idx & (En - 1);
    int b = idx / (Tn * En);
    float dv = expf((float)(e & ~1) * (-9.210340371976184f / (float)En));
    float ang = (float)b * dv;
    float pe = (e & 1) ? cosf(ang) : sinf(ang);
    float v = src[idx] + pe;
    x[idx] = v;
    split_hl(v, xh[idx], xl[idx]);
}

// ---------------- fused hi/lo bf16 GEMM (R7 config: 128x128, 3-stage) ----------------
#define BM 128
#define BN 128
#define BK 32
#define RGB 8192                    // one 128x32 bf16 region
#define STGB (4 * RGB)              // 32 KB per stage

__global__ __launch_bounds__(256, 2) void gemm_mma(
    const __nv_bfloat16* __restrict__ Ah, const __nv_bfloat16* __restrict__ Al,
    const __nv_bfloat16* __restrict__ Bh, const __nv_bfloat16* __restrict__ Bl,
    const float* __restrict__ bias, float* __restrict__ Cf,
    __nv_bfloat16* __restrict__ Ch, __nv_bfloat16* __restrict__ Cl,
    int K, int N, int relu)
{
    extern __shared__ __align__(128) uint8_t dsm[];
    __shared__ float sh_bias[BN];

    const int tid = threadIdx.x;
    const uint32_t sbase = smem_u32(dsm);
    if (tid < BN) sh_bias[tid] = bias[blockIdx.x * BN + tid];

    const int wid = tid >> 5, lane = tid & 31;
    const int wm = wid >> 1, wn = wid & 1;

    const __nv_bfloat16* Abh = Ah + (size_t)blockIdx.y * BM * K;
    const __nv_bfloat16* Abl = Al + (size_t)blockIdx.y * BM * K;
    const __nv_bfloat16* Bbh = Bh + (size_t)blockIdx.x * BN * K;
    const __nv_bfloat16* Bbl = Bl + (size_t)blockIdx.x * BN * K;

    const int cps = K / BK;

    auto load_chunk = [&](int c, int st) {
        int kc = c * BK;
        uint32_t sg = sbase + (uint32_t)st * STGB;
#pragma unroll
        for (int j = 0; j < 2; j++) {
            int idx = tid + j * 256;
            int r = idx >> 2, cc = idx & 3;
            uint32_t off = r * 64 + ((cc ^ ((r >> 1) & 3)) << 4);
            size_t go = (size_t)r * K + kc + cc * 8;
            cpasync16(sg + off,            Abh + go);
            cpasync16(sg + RGB + off,      Abl + go);
            cpasync16(sg + 2 * RGB + off,  Bbh + go);
            cpasync16(sg + 3 * RGB + off,  Bbl + go);
        }
        cp_commit();
    };

    float acc[2][8][4] = {};
    load_chunk(0, 0);
    load_chunk(1, 1);

    int st = 0;
    for (int c = 0; c < cps; c++) {
        if (c + 1 < cps) cp_wait<1>(); else cp_wait<0>();
        __syncthreads();
        if (c + 2 < cps) {
            int ns = st + 2; if (ns >= 3) ns -= 3;
            load_chunk(c + 2, ns);
        }

        uint32_t sAh = sbase + (uint32_t)st * STGB;
        uint32_t sAl = sAh + RGB;
        uint32_t sBh = sAh + 2 * RGB;
        uint32_t sBl = sAh + 3 * RGB;
#pragma unroll
        for (int ks = 0; ks < 2; ks++) {
            uint32_t ah[2][4], al[2][4];
#pragma unroll
            for (int ti = 0; ti < 2; ti++) {
                int r = wm * 32 + ti * 16 + (lane & 15);
                int cc = 2 * ks + (lane >> 4);
                uint32_t off = r * 64 + ((cc ^ ((r >> 1) & 3)) << 4);
                ldsm4(ah[ti][0], ah[ti][1], ah[ti][2], ah[ti][3], sAh + off);
                ldsm4(al[ti][0], al[ti][1], al[ti][2], al[ti][3], sAl + off);
            }
#pragma unroll
            for (int tj = 0; tj < 4; tj++) {
                int r = wn * 64 + tj * 16 + (lane & 15);
                int cc = 2 * ks + (lane >> 4);
                uint32_t off = r * 64 + ((cc ^ ((r >> 1) & 3)) << 4);
                uint32_t b0, b1, b2, b3, c0, c1, c2, c3;
                ldsm4(b0, b1, b2, b3, sBh + off);
                ldsm4(c0, c1, c2, c3, sBl + off);
                mma16816(acc[0][2 * tj],     ah[0], b0, b2);
                mma16816(acc[0][2 * tj + 1], ah[0], b1, b3);
                mma16816(acc[1][2 * tj],     ah[1], b0, b2);
                mma16816(acc[1][2 * tj + 1], ah[1], b1, b3);
                mma16816(acc[0][2 * tj],     al[0], b0, b2);
                mma16816(acc[0][2 * tj + 1], al[0], b1, b3);
                mma16816(acc[1][2 * tj],     al[1], b0, b2);
                mma16816(acc[1][2 * tj + 1], al[1], b1, b3);
                mma16816(acc[0][2 * tj],     ah[0], c0, c2);
                mma16816(acc[0][2 * tj + 1], ah[0], c1, c3);
                mma16816(acc[1][2 * tj],     ah[1], c0, c2);
                mma16816(acc[1][2 * tj + 1], ah[1], c1, c3);
            }
        }
        if (++st == 3) st = 0;
    }

    const int col0 = wn * 64;
    const int row0 = blockIdx.y * BM + wm * 32;
#pragma unroll
    for (int ti = 0; ti < 2; ti++) {
#pragma unroll
        for (int tj = 0; tj < 8; tj++) {
            int cl = col0 + tj * 8 + 2 * (lane & 3);
            int colg = blockIdx.x * BN + cl;
            float b0 = sh_bias[cl], b1 = sh_bias[cl + 1];
#pragma unroll
            for (int hh = 0; hh < 2; hh++) {
                int row = row0 + ti * 16 + (lane >> 2) + hh * 8;
                float v0 = acc[ti][tj][2 * hh + 0] + b0;
                float v1 = acc[ti][tj][2 * hh + 1] + b1;
                if (relu) { v0 = fmaxf(v0, 0.f); v1 = fmaxf(v1, 0.f); }
                size_t o = (size_t)row * N + colg;
                if (Cf) *(float2*)(Cf + o) = make_float2(v0, v1);
                if (Ch) {
                    __nv_bfloat16 h0, l0, h1, l1;
                    split_hl(v0, h0, l0);
                    split_hl(v1, h1, l1);
                    __nv_bfloat162 hv; hv.x = h0; hv.y = h1;
                    __nv_bfloat162 lv; lv.x = l0; lv.y = l1;
                    *(__nv_bfloat162*)(Ch + o) = hv;
                    *(__nv_bfloat162*)(Cl + o) = lv;
                }
            }
        }
    }
}

// ---------------- fused attention: S=QK^T/8, softmax*gauss*renorm, O=WV ----------------
// grid (qtile=4, bh=128), 256 threads. No max-subtraction (|s| << 88).
// smem: Q 32K | K 32K | V 32K | P 64K | Z/G/inv 1.5K  = ~166 KB, 1 CTA/SM.
#define AF_SQ 0
#define AF_SK 32768
#define AF_SV 65536
#define AF_SP 98304
#define AF_SZ 163840
#define AF_SMEM (163840 + 1536)

__global__ __launch_bounds__(256, 1) void attn_fused(
    const __nv_bfloat16* __restrict__ qkvh, const __nv_bfloat16* __restrict__ qkvl,
    __nv_bfloat16* __restrict__ oh, __nv_bfloat16* __restrict__ ol)
{
    extern __shared__ __align__(128) uint8_t dsm[];
    const int tid = threadIdx.x;
    const uint32_t sbase = smem_u32(dsm);
    const int wid = tid >> 5, lane = tid & 31;
    const int wm = wid >> 1, wn = wid & 1;   // scores: q-band 32 x k-band 64 ; PV: q-band 32 x d-band 32
    const int bh = blockIdx.y, b = bh >> 4, h = bh & 15;
    const int q0 = blockIdx.x * 128;
    const int LDQ = 3 * En;

    float* sZ = (float*)(dsm + AF_SZ);
    float* sG = (float*)(dsm + AF_SZ + 512);
    float* sInv = (float*)(dsm + AF_SZ + 1024);

    const __nv_bfloat16* Qhb = qkvh + (size_t)b * Tn * LDQ + h * Dn + (size_t)q0 * LDQ;
    const __nv_bfloat16* Qlb = qkvl + (size_t)b * Tn * LDQ + h * Dn + (size_t)q0 * LDQ;
    const __nv_bfloat16* Khb = qkvh + (size_t)b * Tn * LDQ + En + h * Dn;
    const __nv_bfloat16* Klb = qkvl + (size_t)b * Tn * LDQ + En + h * Dn;
    const __nv_bfloat16* Vhb = qkvh + (size_t)b * Tn * LDQ + 2 * En + h * Dn;
    const __nv_bfloat16* Vlb = qkvl + (size_t)b * Tn * LDQ + 2 * En + h * Dn;

    // load 128 rows x 128B (2 chunks of 64B) hi+lo into dst / dst+16384
    auto loadQK = [&](const __nv_bfloat16* Gh, const __nv_bfloat16* Gl,
                      uint32_t dst, int rowOff) {
#pragma unroll
        for (int j = 0; j < 4; j++) {
            int idx = tid + j * 256;         // 0..1023
            int r = idx >> 3, gg = idx & 7;
            int chunk = gg >> 2, grp = gg & 3;
            uint32_t off = (uint32_t)chunk * 8192 + r * 64 + ((grp ^ ((r >> 1) & 3)) << 4);
            size_t go = (size_t)(rowOff + r) * LDQ + gg * 8;
            cpasync16(dst + off, Gh + go);
            cpasync16(dst + 16384 + off, Gl + go);
        }
        cp_commit();
    };

    auto loadV = [&](int kt) {
#pragma unroll
        for (int p = 0; p < 4; p++) {
            int kk = tid >> 3;               // 0..31
            int d0 = (tid & 7) * 8;
            size_t go = (size_t)(kt * 128 + p * 32 + kk) * LDQ + d0;
            uint4 hv = *(const uint4*)(Vhb + go);
            uint4 lv = *(const uint4*)(Vlb + go);
            uint32_t h4[4] = {hv.x, hv.y, hv.z, hv.w};
            uint32_t l4[4] = {lv.x, lv.y, lv.z, lv.w};
#pragma unroll
            for (int i = 0; i < 8; i++) {
                uint16_t hb16 = (uint16_t)(h4[i >> 1] >> ((i & 1) * 16));
                uint16_t lb16 = (uint16_t)(l4[i >> 1] >> ((i & 1) * 16));
                int d = d0 + i;
                int fd = ((d >> 1) & 3) ^ ((d >> 3) & 3);
                uint32_t off = (uint32_t)p * 4096 + d * 64 + (((kk >> 3) ^ fd) << 4) + (kk & 7) * 2;
                *(uint16_t*)(dsm + AF_SV + off) = hb16;
                *(uint16_t*)(dsm + AF_SV + 16384 + off) = lb16;
            }
        }
    };

    loadQK(Qhb, Qlb, sbase + AF_SQ, 0);
    if (tid < 128) { sZ[tid] = 0.f; sG[tid] = 0.f; }

    float accO[2][4][4] = {};
    float zacc[4] = {}, gacc[4] = {};

    for (int kt = 0; kt < 4; kt++) {
        __syncthreads();  // prior PV/scores consumed K,V,P (and sZ init visible)
        loadQK(Khb, Klb, sbase + AF_SK, kt * 128);
        loadV(kt);
        cp_wait<0>();
        __syncthreads();

        // ---- scores: S = Q K^T (acc2), K=64 in 2 chunks ----
        float acc2[2][8][4] = {};
#pragma unroll
        for (int c = 0; c < 2; c++) {
            uint32_t sAh = sbase + AF_SQ + (uint32_t)c * 8192, sAl = sAh + 16384;
            uint32_t sBh = sbase + AF_SK + (uint32_t)c * 8192, sBl = sBh + 16384;
#pragma unroll
            for (int ks = 0; ks < 2; ks++) {
                uint32_t ah[2][4], al[2][4];
#pragma unroll
                for (int ti = 0; ti < 2; ti++) {
                    int r = wm * 32 + ti * 16 + (lane & 15);
                    int cc = 2 * ks + (lane >> 4);
                    uint32_t off = r * 64 + ((cc ^ ((r >> 1) & 3)) << 4);
                    ldsm4(ah[ti][0], ah[ti][1], ah[ti][2], ah[ti][3], sAh + off);
                    ldsm4(al[ti][0], al[ti][1], al[ti][2], al[ti][3], sAl + off);
                }
#pragma unroll
                for (int tj = 0; tj < 4; tj++) {
                    int r = wn * 64 + tj * 16 + (lane & 15);
                    int cc = 2 * ks + (lane >> 4);
                    uint32_t off = r * 64 + ((cc ^ ((r >> 1) & 3)) << 4);
                    uint32_t b0, b1, b2, b3, c0, c1, c2, c3;
                    ldsm4(b0, b1, b2, b3, sBh + off);
                    ldsm4(c0, c1, c2, c3, sBl + off);
                    mma16816(acc2[0][2 * tj],     ah[0], b0, b2);
                    mma16816(acc2[0][2 * tj + 1], ah[0], b1, b3);
                    mma16816(acc2[1][2 * tj],     ah[1], b0, b2);
                    mma16816(acc2[1][2 * tj + 1], ah[1], b1, b3);
                    mma16816(acc2[0][2 * tj],     al[0], b0, b2);
                    mma16816(acc2[0][2 * tj + 1], al[0], b1, b3);
                    mma16816(acc2[1][2 * tj],     al[1], b0, b2);
                    mma16816(acc2[1][2 * tj + 1], al[1], b1, b3);
                    mma16816(acc2[0][2 * tj],     ah[0], c0, c2);
                    mma16816(acc2[0][2 * tj + 1], ah[0], c1, c3);
                    mma16816(acc2[1][2 * tj],     ah[1], c0, c2);
                    mma16816(acc2[1][2 * tj + 1], ah[1], c1, c3);
                }
            }
        }

        // ---- p = exp(s/8), g = gaussian, accumulate Z,G, store p*g hi/lo to sP ----
#pragma unroll
        for (int ti = 0; ti < 2; ti++) {
#pragma unroll
            for (int hh = 0; hh < 2; hh++) {
                int rloc = wm * 32 + ti * 16 + (lane >> 2) + hh * 8;
                float qg = (float)(q0 + rloc);
                float zs = 0.f, gs = 0.f;
#pragma unroll
                for (int tj = 0; tj < 8; tj++) {
                    int kcl = wn * 64 + tj * 8 + 2 * (lane & 3);
                    float kg = (float)(kt * 128 + kcl);
                    float s0 = acc2[ti][tj][2 * hh + 0] * 0.125f;
                    float s1 = acc2[ti][tj][2 * hh + 1] * 0.125f;
                    float p0 = __expf(s0), p1 = __expf(s1);
                    float d0 = qg - kg, d1 = qg - (kg + 1.0f);
                    float g0 = __expf(-d0 * d0 * (1.0f / 32768.0f));
                    float g1 = __expf(-d1 * d1 * (1.0f / 32768.0f));
                    float pg0 = p0 * g0, pg1 = p1 * g1;
                    zs += p0 + p1;
                    gs += pg0 + pg1;
                    __nv_bfloat16 h0, l0, h1, l1;
                    split_hl(pg0, h0, l0);
                    split_hl(pg1, h1, l1);
                    __nv_bfloat162 hv; hv.x = h0; hv.y = h1;
                    __nv_bfloat162 lv; lv.x = l0; lv.y = l1;
                    int chunk = kcl >> 5;
                    int c32 = kcl & 31;
                    uint32_t off = (uint32_t)chunk * 8192 + rloc * 64
                                 + (((c32 >> 3) ^ ((rloc >> 1) & 3)) << 4) + (c32 & 7) * 2;
                    *(__nv_bfloat162*)(dsm + AF_SP + off) = hv;
                    *(__nv_bfloat162*)(dsm + AF_SP + 32768 + off) = lv;
                }
                zacc[ti * 2 + hh] += zs;
                gacc[ti * 2 + hh] += gs;
            }
        }
        __syncthreads();  // P,V visible

        // ---- PV: accO += P @ V (4 chunks of 32 k) ----
#pragma unroll
        for (int ch = 0; ch < 4; ch++) {
            uint32_t sAh = sbase + AF_SP + (uint32_t)ch * 8192, sAl = sAh + 32768;
            uint32_t sBh = sbase + AF_SV + (uint32_t)ch * 4096, sBl = sBh + 16384;
#pragma unroll
            for (int ks = 0; ks < 2; ks++) {
                uint32_t ah[2][4], al[2][4];
#pragma unroll
                for (int ti = 0; ti < 2; ti++) {
                    int r = wm * 32 + ti * 16 + (lane & 15);
                    int cc = 2 * ks + (lane >> 4);
                    uint32_t off = r * 64 + ((cc ^ ((r >> 1) & 3)) << 4);
                    ldsm4(ah[ti][0], ah[ti][1], ah[ti][2], ah[ti][3], sAh + off);
                    ldsm4(al[ti][0], al[ti][1], al[ti][2], al[ti][3], sAl + off);
                }
#pragma unroll
                for (int tj = 0; tj < 2; tj++) {
                    int r = wn * 32 + tj * 16 + (lane & 15);
                    int cc = 2 * ks + (lane >> 4);
                    int fd = ((r >> 1) & 3) ^ ((r >> 3) & 3);
                    uint32_t off = r * 64 + ((cc ^ fd) << 4);
                    uint32_t b0, b1, b2, b3, c0, c1, c2, c3;
                    ldsm4(b0, b1, b2, b3, sBh + off);
                    ldsm4(c0, c1, c2, c3, sBl + off);
                    mma16816(accO[0][2 * tj],     ah[0], b0, b2);
                    mma16816(accO[0][2 * tj + 1], ah[0], b1, b3);
                    mma16816(accO[1][2 * tj],     ah[1], b0, b2);
                    mma16816(accO[1][2 * tj + 1], ah[1], b1, b3);
                    mma16816(accO[0][2 * tj],     al[0], b0, b2);
                    mma16816(accO[0][2 * tj + 1], al[0], b1, b3);
                    mma16816(accO[1][2 * tj],     al[1], b0, b2);
                    mma16816(accO[1][2 * tj + 1], al[1], b1, b3);
                    mma16816(accO[0][2 * tj],     ah[0], c0, c2);
                    mma16816(accO[0][2 * tj + 1], ah[0], c1, c3);
                    mma16816(accO[1][2 * tj],     ah[1], c0, c2);
                    mma16816(accO[1][2 * tj + 1], ah[1], c1, c3);
                }
            }
        }
    }

    // ---- reduce Z,G per row; normalize; write O ----
#pragma unroll
    for (int s = 0; s < 4; s++) {
        zacc[s] += __shfl_xor_sync(~0u, zacc[s], 1);
        zacc[s] += __shfl_xor_sync(~0u, zacc[s], 2);
        gacc[s] += __shfl_xor_sync(~0u, gacc[s], 1);
        gacc[s] += __shfl_xor_sync(~0u, gacc[s], 2);
    }
    if ((lane & 3) == 0) {
#pragma unroll
        for (int ti = 0; ti < 2; ti++)
#pragma unroll
            for (int hh = 0; hh < 2; hh++) {
                int rloc = wm * 32 + ti * 16 + (lane >> 2) + hh * 8;
                atomicAdd(&sZ[rloc], zacc[ti * 2 + hh]);
                atomicAdd(&sG[rloc], gacc[ti * 2 + hh]);
            }
    }
    __syncthreads();
    if (tid < 128) sInv[tid] = 1.0f / (sG[tid] + 1e-5f * sZ[tid]);
    __syncthreads();

#pragma unroll
    for (int ti = 0; ti < 2; ti++) {
#pragma unroll
        for (int tj = 0; tj < 4; tj++) {
            int dl = wn * 32 + tj * 8 + 2 * (lane & 3);
            int colg = h * Dn + dl;
#pragma unroll
            for (int hh = 0; hh < 2; hh++) {
                int rloc = wm * 32 + ti * 16 + (lane >> 2) + hh * 8;
                float inv = sInv[rloc];
                float v0 = accO[ti][tj][2 * hh + 0] * inv;
                float v1 = accO[ti][tj][2 * hh + 1] * inv;
                __nv_bfloat16 h0, l0, h1, l1;
                split_hl(v0, h0, l0);
                split_hl(v1, h1, l1);
                __nv_bfloat162 hv; hv.x = h0; hv.y = h1;
                __nv_bfloat162 lv; lv.x = l0; lv.y = l1;
                size_t o = (size_t)b * Tn * En + (size_t)(q0 + rloc) * En + colg;
                *(__nv_bfloat162*)(oh + o) = hv;
                *(__nv_bfloat162*)(ol + o) = lv;
            }
        }
    }
}

// ---------------- residual + LN (single-pass mean/var) ----------------
__global__ __launch_bounds__(256) void add_ln(
    float* __restrict__ x, const float* __restrict__ r,
    const float* __restrict__ g, const float* __restrict__ bt,
    __nv_bfloat16* __restrict__ xh, __nv_bfloat16* __restrict__ xl)
{
    const size_t base = (size_t)blockIdx.x * En;
    const int tid = threadIdx.x;
    float v[4];
    float s = 0.f, sq = 0.f;
#pragma unroll
    for (int i = 0; i < 4; i++) {
        int c = tid + i * 256;
        v[i] = x[base + c] + r[base + c];
        s += v[i];
        sq += v[i] * v[i];
    }
    float2 t = blockSum2(s, sq);
    float mu = t.x * (1.0f / En);
    float var = fmaxf(t.y * (1.0f / En) - mu * mu, 0.f);
    float rs = rsqrtf(var + 1e-5f);
#pragma unroll
    for (int i = 0; i < 4; i++) {
        int c = tid + i * 256;
        float o = (v[i] - mu) * rs * g[c] + bt[c];
        x[base + c] = o;
        split_hl(o, xh[base + c], xl[base + c]);
    }
}

__global__ __launch_bounds__(256) void head_kernel(
    const float* __restrict__ x, const float* __restrict__ hw,
    const float* __restrict__ hb, float* __restrict__ out)
{
    const int b = blockIdx.x;
    const int tid = threadIdx.x;
    const float* row = x + (size_t)b * Tn * En + (size_t)(Tn - 1) * En;
    float s = 0.f;
    for (int c = tid; c < En; c += 256) s += row[c] * hw[c];
    s = blockSum(s);
    if (tid == 0) out[b] = s + hb[0];
}

// ---------------- launch ----------------
extern "C" void kernel_launch(void* const* d_in, const int* in_sizes, int n_in,
                              void* d_out, int out_size)
{
    const float* src    = (const float*)d_in[0];
    const float* in_w   = (const float*)d_in[1];
    const float* in_b   = (const float*)d_in[2];
    const float* outp_w = (const float*)d_in[3];
    const float* outp_b = (const float*)d_in[4];
    const float* ff1_w  = (const float*)d_in[5];
    const float* ff1_b  = (const float*)d_in[6];
    const float* ff2_w  = (const float*)d_in[7];
    const float* ff2_b  = (const float*)d_in[8];
    const float* ln1_g  = (const float*)d_in[9];
    const float* ln1_b  = (const float*)d_in[10];
    const float* ln2_g  = (const float*)d_in[11];
    const float* ln2_b  = (const float*)d_in[12];
    const float* head_w = (const float*)d_in[13];
    const float* head_b = (const float*)d_in[14];
    float* out = (float*)d_out;

    static bool init = false;
    static float *x, *proj;
    static __nv_bfloat16 *xh,*xl,*ah,*al,*fh,*fl,*qkvh,*qkvl,
                         *wih,*wil,*woh,*wol,*w1h,*w1l,*w2h,*w2l;
    if (!init) {
        cudaGetSymbolAddress((void**)&x, g_x);
        cudaGetSymbolAddress((void**)&proj, g_proj);
        cudaGetSymbolAddress((void**)&xh, g_xh); cudaGetSymbolAddress((void**)&xl, g_xl);
        cudaGetSymbolAddress((void**)&ah, g_ah); cudaGetSymbolAddress((void**)&al, g_al);
        cudaGetSymbolAddress((void**)&fh, g_fh); cudaGetSymbolAddress((void**)&fl, g_fl);
        cudaGetSymbolAddress((void**)&qkvh, g_qkvh); cudaGetSymbolAddress((void**)&qkvl, g_qkvl);
        cudaGetSymbolAddress((void**)&wih, g_wih); cudaGetSymbolAddress((void**)&wil, g_wil);
        cudaGetSymbolAddress((void**)&woh, g_woh); cudaGetSymbolAddress((void**)&wol, g_wol);
        cudaGetSymbolAddress((void**)&w1h, g_w1h); cudaGetSymbolAddress((void**)&w1l, g_w1l);
        cudaGetSymbolAddress((void**)&w2h, g_w2h); cudaGetSymbolAddress((void**)&w2l, g_w2l);
        cudaFuncSetAttribute(gemm_mma, cudaFuncAttributeMaxDynamicSharedMemorySize, 3 * STGB);
        cudaFuncSetAttribute(attn_fused, cudaFuncAttributeMaxDynamicSharedMemorySize, AF_SMEM);
        init = true;
    }

    // weight -> hi/lo bf16
    convert_hl4<<<Ln * 3 * En * En / 1024, 256>>>((const float4*)in_w,
        (__nv_bfloat162*)wih, (__nv_bfloat162*)wil);
    convert_hl4<<<Ln * En * En / 1024, 256>>>((const float4*)outp_w,
        (__nv_bfloat162*)woh, (__nv_bfloat162*)wol);
    convert_hl4<<<Ln * FFn * En / 1024, 256>>>((const float4*)ff1_w,
        (__nv_bfloat162*)w1h, (__nv_bfloat162*)w1l);
    convert_hl4<<<Ln * En * FFn / 1024, 256>>>((const float4*)ff2_w,
        (__nv_bfloat162*)w2h, (__nv_bfloat162*)w2l);

    pe_add_kernel<<<Bn * Tn * En / 256, 256>>>(src, x, xh, xl);

    for (int l = 0; l < Ln; l++) {
        size_t wo3 = (size_t)l * 3 * En * En, wo1 = (size_t)l * En * En;
        size_t wof = (size_t)l * FFn * En;
        // qkv (bf16 hi/lo out only)
        gemm_mma<<<dim3(3 * En / BN, Bn * Tn / BM), 256, 3 * STGB>>>(
            xh, xl, wih + wo3, wil + wo3, in_b + (size_t)l * 3 * En,
            nullptr, qkvh, qkvl, En, 3 * En, 0);
        // fused attention (scores + softmax*gauss + PV)
        attn_fused<<<dim3(4, Bn * Hn), 256, AF_SMEM>>>(qkvh, qkvl, ah, al);
        // out proj
        gemm_mma<<<dim3(En / BN, Bn * Tn / BM), 256, 3 * STGB>>>(
            ah, al, woh + wo1, wol + wo1, outp_b + (size_t)l * En,
            proj, nullptr, nullptr, En, En, 0);
        add_ln<<<Bn * Tn, 256>>>(x, proj, ln1_g + (size_t)l * En, ln1_b + (size_t)l * En, xh, xl);
        // ff1 (relu, hl out)
        gemm_mma<<<dim3(FFn / BN, Bn * Tn / BM), 256, 3 * STGB>>>(
            xh, xl, w1h + wof, w1l + wof, ff1_b + (size_t)l * FFn,
            nullptr, fh, fl, En, FFn, 1);
        // ff2
        gemm_mma<<<dim3(En / BN, Bn * Tn / BM), 256, 3 * STGB>>>(
            fh, fl, w2h + wof, w2l + wof, ff2_b + (size_t)l * En,
            proj, nullptr, nullptr, FFn, En, 0);
        add_ln<<<Bn * Tn, 256>>>(x, proj, ln2_g + (size_t)l * En, ln2_b + (size_t)l * En, xh, xl);
    }

    head_kernel<<<Bn, 256>>>(x, head_w, head_b, out);
}

// round 10
// speedup vs baseline: 1.5244x; 1.3245x over previous
#include <cuda_runtime.h>
#include <cuda_fp16.h>
#include <math.h>
#include <stdint.h>

#define Bn  8
#define Tn  512
#define En  1024
#define Hn  16
#define Dn  64
#define Ln  4
#define FFn 4096

// fp32 scratch
__device__ float g_x[Bn * Tn * En];
__device__ float g_proj[Bn * Tn * En];
// fp16 hi/lo activation pairs
__device__ __half g_xh[Bn * Tn * En],  g_xl[Bn * Tn * En];
__device__ __half g_ah[Bn * Tn * En],  g_al[Bn * Tn * En];
__device__ __half g_fh[Bn * Tn * FFn], g_fl[Bn * Tn * FFn];
__device__ __half g_qkvh[Bn * Tn * 3 * En], g_qkvl[Bn * Tn * 3 * En];
// fp16 weight (hi only — B-side quantization, 2-term scheme)
__device__ __half g_wih[Ln * 3 * En * En];
__device__ __half g_woh[Ln * En * En];
__device__ __half g_w1h[Ln * FFn * En];
__device__ __half g_w2h[Ln * En * FFn];

// ---------------- PTX helpers (sm_80+ only) ----------------
__device__ __forceinline__ uint32_t smem_u32(const void* p) {
    uint32_t a;
    asm("{ .reg .u64 t; cvta.to.shared.u64 t, %1; cvt.u32.u64 %0, t; }" : "=r"(a) : "l"(p));
    return a;
}
__device__ __forceinline__ void cpasync16(uint32_t dst, const void* src) {
    asm volatile("cp.async.cg.shared.global [%0], [%1], 16;" :: "r"(dst), "l"(src));
}
__device__ __forceinline__ void cp_commit() { asm volatile("cp.async.commit_group;" ::: "memory"); }
template <int N> __device__ __forceinline__ void cp_wait() {
    asm volatile("cp.async.wait_group %0;" :: "n"(N) : "memory");
}
__device__ __forceinline__ void ldsm4(uint32_t& r0, uint32_t& r1, uint32_t& r2,
                                      uint32_t& r3, uint32_t a) {
    asm volatile("ldmatrix.sync.aligned.m8n8.x4.shared.b16 {%0,%1,%2,%3}, [%4];"
                 : "=r"(r0), "=r"(r1), "=r"(r2), "=r"(r3) : "r"(a));
}
__device__ __forceinline__ void mma16816(float* d, const uint32_t* a, uint32_t b0, uint32_t b1) {
    asm volatile("mma.sync.aligned.m16n8k16.row.col.f32.f16.f16.f32 "
                 "{%0,%1,%2,%3}, {%4,%5,%6,%7}, {%8,%9}, {%0,%1,%2,%3};"
                 : "+f"(d[0]), "+f"(d[1]), "+f"(d[2]), "+f"(d[3])
                 : "r"(a[0]), "r"(a[1]), "r"(a[2]), "r"(a[3]), "r"(b0), "r"(b1));
}
__device__ __forceinline__ void split_hl(float v, __half& h, __half& l) {
    h = __float2half_rn(v);
    l = __float2half_rn(v - __half2float(h));
}

// ---------------- reductions ----------------
__device__ __forceinline__ float warpSum(float v) {
#pragma unroll
    for (int o = 16; o; o >>= 1) v += __shfl_xor_sync(~0u, v, o);
    return v;
}
__device__ __forceinline__ float blockSum(float v) {
    __shared__ float sm[8];
    int lane = threadIdx.x & 31, wid = threadIdx.x >> 5;
    v = warpSum(v);
    __syncthreads();
    if (lane == 0) sm[wid] = v;
    __syncthreads();
    v = sm[lane & 7];
#pragma unroll
    for (int o = 4; o; o >>= 1) v += __shfl_xor_sync(~0u, v, o);
    return v;
}
__device__ __forceinline__ float2 blockSum2(float a, float b) {
    __shared__ float2 sm[8];
    int lane = threadIdx.x & 31, wid = threadIdx.x >> 5;
#pragma unroll
    for (int o = 16; o; o >>= 1) {
        a += __shfl_xor_sync(~0u, a, o);
        b += __shfl_xor_sync(~0u, b, o);
    }
    __syncthreads();
    if (lane == 0) sm[wid] = make_float2(a, b);
    __syncthreads();
    float2 v = sm[lane & 7];
#pragma unroll
    for (int o = 4; o; o >>= 1) {
        v.x += __shfl_xor_sync(~0u, v.x, o);
        v.y += __shfl_xor_sync(~0u, v.y, o);
    }
    return v;
}

// ---------------- small kernels ----------------
// weights: hi-only fp16 conversion
__global__ void convert_h4(const float4* __restrict__ s, __half2* __restrict__ h) {
    int i = blockIdx.x * 256 + threadIdx.x;
    float4 v = s[i];
    h[2 * i]     = __floats2half2_rn(v.x, v.y);
    h[2 * i + 1] = __floats2half2_rn(v.z, v.w);
}

__global__ void pe_add_kernel(const float* __restrict__ src, float* __restrict__ x,
                              __half* __restrict__ xh, __half* __restrict__ xl) {
    int idx = blockIdx.x * 256 + threadIdx.x;
    int e = idx & (En - 1);
    int b = idx / (Tn * En);
    float dv = expf((float)(e & ~1) * (-9.210340371976184f / (float)En));
    float ang = (float)b * dv;
    float pe = (e & 1) ? cosf(ang) : sinf(ang);
    float v = src[idx] + pe;
    x[idx] = v;
    split_hl(v, xh[idx], xl[idx]);
}

// ---------------- fp16 2-term GEMM: C = (Ah+Al) @ Bh^T + bias ----------------
// error = A.Bl ~ 2^-12 rel. CTA 128x128, BK=32, 3-stage, 24 KB/stage, 2 CTA/SM.
#define BM 128
#define BN 128
#define BK 32
#define RGB 8192                    // one 128x32 fp16 region
#define STGB (3 * RGB)              // 24 KB per stage: Ah | Al | Bh

__global__ __launch_bounds__(256, 2) void gemm_mma(
    const __half* __restrict__ Ah, const __half* __restrict__ Al,
    const __half* __restrict__ Bh,
    const float* __restrict__ bias, float* __restrict__ Cf,
    __half* __restrict__ Ch, __half* __restrict__ Cl,
    int K, int N, int relu)
{
    extern __shared__ __align__(128) uint8_t dsm[];
    __shared__ float sh_bias[BN];

    const int tid = threadIdx.x;
    const uint32_t sbase = smem_u32(dsm);
    if (tid < BN) sh_bias[tid] = bias[blockIdx.x * BN + tid];

    const int wid = tid >> 5, lane = tid & 31;
    const int wm = wid >> 1, wn = wid & 1;

    const __half* Abh = Ah + (size_t)blockIdx.y * BM * K;
    const __half* Abl = Al + (size_t)blockIdx.y * BM * K;
    const __half* Bbh = Bh + (size_t)blockIdx.x * BN * K;

    const int cps = K / BK;

    auto load_chunk = [&](int c, int st) {
        int kc = c * BK;
        uint32_t sg = sbase + (uint32_t)st * STGB;
#pragma unroll
        for (int j = 0; j < 2; j++) {
            int idx = tid + j * 256;
            int r = idx >> 2, cc = idx & 3;
            uint32_t off = r * 64 + ((cc ^ ((r >> 1) & 3)) << 4);
            size_t go = (size_t)r * K + kc + cc * 8;
            cpasync16(sg + off,           Abh + go);
            cpasync16(sg + RGB + off,     Abl + go);
            cpasync16(sg + 2 * RGB + off, Bbh + go);
        }
        cp_commit();
    };

    float acc[2][8][4] = {};
    load_chunk(0, 0);
    load_chunk(1, 1);

    int st = 0;
    for (int c = 0; c < cps; c++) {
        if (c + 1 < cps) cp_wait<1>(); else cp_wait<0>();
        __syncthreads();
        if (c + 2 < cps) {
            int ns = st + 2; if (ns >= 3) ns -= 3;
            load_chunk(c + 2, ns);
        }

        uint32_t sAh = sbase + (uint32_t)st * STGB;
        uint32_t sAl = sAh + RGB;
        uint32_t sBh = sAh + 2 * RGB;
#pragma unroll
        for (int ks = 0; ks < 2; ks++) {
            uint32_t ah[2][4], al[2][4];
#pragma unroll
            for (int ti = 0; ti < 2; ti++) {
                int r = wm * 32 + ti * 16 + (lane & 15);
                int cc = 2 * ks + (lane >> 4);
                uint32_t off = r * 64 + ((cc ^ ((r >> 1) & 3)) << 4);
                ldsm4(ah[ti][0], ah[ti][1], ah[ti][2], ah[ti][3], sAh + off);
                ldsm4(al[ti][0], al[ti][1], al[ti][2], al[ti][3], sAl + off);
            }
#pragma unroll
            for (int tj = 0; tj < 4; tj++) {
                int r = wn * 64 + tj * 16 + (lane & 15);
                int cc = 2 * ks + (lane >> 4);
                uint32_t off = r * 64 + ((cc ^ ((r >> 1) & 3)) << 4);
                uint32_t b0, b1, b2, b3;
                ldsm4(b0, b1, b2, b3, sBh + off);
                mma16816(acc[0][2 * tj],     ah[0], b0, b2);
                mma16816(acc[0][2 * tj + 1], ah[0], b1, b3);
                mma16816(acc[1][2 * tj],     ah[1], b0, b2);
                mma16816(acc[1][2 * tj + 1], ah[1], b1, b3);
                mma16816(acc[0][2 * tj],     al[0], b0, b2);
                mma16816(acc[0][2 * tj + 1], al[0], b1, b3);
                mma16816(acc[1][2 * tj],     al[1], b0, b2);
                mma16816(acc[1][2 * tj + 1], al[1], b1, b3);
            }
        }
        if (++st == 3) st = 0;
    }

    const int col0 = wn * 64;
    const int row0 = blockIdx.y * BM + wm * 32;
#pragma unroll
    for (int ti = 0; ti < 2; ti++) {
#pragma unroll
        for (int tj = 0; tj < 8; tj++) {
            int cl = col0 + tj * 8 + 2 * (lane & 3);
            int colg = blockIdx.x * BN + cl;
            float b0 = sh_bias[cl], b1 = sh_bias[cl + 1];
#pragma unroll
            for (int hh = 0; hh < 2; hh++) {
                int row = row0 + ti * 16 + (lane >> 2) + hh * 8;
                float v0 = acc[ti][tj][2 * hh + 0] + b0;
                float v1 = acc[ti][tj][2 * hh + 1] + b1;
                if (relu) { v0 = fmaxf(v0, 0.f); v1 = fmaxf(v1, 0.f); }
                size_t o = (size_t)row * N + colg;
                if (Cf) *(float2*)(Cf + o) = make_float2(v0, v1);
                if (Ch) {
                    __half h0, l0, h1, l1;
                    split_hl(v0, h0, l0);
                    split_hl(v1, h1, l1);
                    __half2 hv; hv.x = h0; hv.y = h1;
                    __half2 lv; lv.x = l0; lv.y = l1;
                    *(__half2*)(Ch + o) = hv;
                    *(__half2*)(Cl + o) = lv;
                }
            }
        }
    }
}

// ---------------- fused attention (fp16, 3-term; structure from R9) ----------------
#define AF_SQ 0
#define AF_SK 32768
#define AF_SV 65536
#define AF_SP 98304
#define AF_SZ 163840
#define AF_SMEM (163840 + 1536)

__global__ __launch_bounds__(256, 1) void attn_fused(
    const __half* __restrict__ qkvh, const __half* __restrict__ qkvl,
    __half* __restrict__ oh, __half* __restrict__ ol)
{
    extern __shared__ __align__(128) uint8_t dsm[];
    const int tid = threadIdx.x;
    const uint32_t sbase = smem_u32(dsm);
    const int wid = tid >> 5, lane = tid & 31;
    const int wm = wid >> 1, wn = wid & 1;
    const int bh = blockIdx.y, b = bh >> 4, h = bh & 15;
    const int q0 = blockIdx.x * 128;
    const int LDQ = 3 * En;

    float* sZ = (float*)(dsm + AF_SZ);
    float* sG = (float*)(dsm + AF_SZ + 512);
    float* sInv = (float*)(dsm + AF_SZ + 1024);

    const __half* Qhb = qkvh + (size_t)b * Tn * LDQ + h * Dn + (size_t)q0 * LDQ;
    const __half* Qlb = qkvl + (size_t)b * Tn * LDQ + h * Dn + (size_t)q0 * LDQ;
    const __half* Khb = qkvh + (size_t)b * Tn * LDQ + En + h * Dn;
    const __half* Klb = qkvl + (size_t)b * Tn * LDQ + En + h * Dn;
    const __half* Vhb = qkvh + (size_t)b * Tn * LDQ + 2 * En + h * Dn;
    const __half* Vlb = qkvl + (size_t)b * Tn * LDQ + 2 * En + h * Dn;

    auto loadQK = [&](const __half* Gh, const __half* Gl, uint32_t dst, int rowOff) {
#pragma unroll
        for (int j = 0; j < 4; j++) {
            int idx = tid + j * 256;
            int r = idx >> 3, gg = idx & 7;
            int chunk = gg >> 2, grp = gg & 3;
            uint32_t off = (uint32_t)chunk * 8192 + r * 64 + ((grp ^ ((r >> 1) & 3)) << 4);
            size_t go = (size_t)(rowOff + r) * LDQ + gg * 8;
            cpasync16(dst + off, Gh + go);
            cpasync16(dst + 16384 + off, Gl + go);
        }
        cp_commit();
    };

    auto loadV = [&](int kt) {
#pragma unroll
        for (int p = 0; p < 4; p++) {
            int kk = tid >> 3;
            int d0 = (tid & 7) * 8;
            size_t go = (size_t)(kt * 128 + p * 32 + kk) * LDQ + d0;
            uint4 hv = *(const uint4*)(Vhb + go);
            uint4 lv = *(const uint4*)(Vlb + go);
            uint32_t h4[4] = {hv.x, hv.y, hv.z, hv.w};
            uint32_t l4[4] = {lv.x, lv.y, lv.z, lv.w};
#pragma unroll
            for (int i = 0; i < 8; i++) {
                uint16_t hb16 = (uint16_t)(h4[i >> 1] >> ((i & 1) * 16));
                uint16_t lb16 = (uint16_t)(l4[i >> 1] >> ((i & 1) * 16));
                int d = d0 + i;
                int fd = ((d >> 1) & 3) ^ ((d >> 3) & 3);
                uint32_t off = (uint32_t)p * 4096 + d * 64 + (((kk >> 3) ^ fd) << 4) + (kk & 7) * 2;
                *(uint16_t*)(dsm + AF_SV + off) = hb16;
                *(uint16_t*)(dsm + AF_SV + 16384 + off) = lb16;
            }
        }
    };

    loadQK(Qhb, Qlb, sbase + AF_SQ, 0);
    if (tid < 128) { sZ[tid] = 0.f; sG[tid] = 0.f; }

    float accO[2][4][4] = {};
    float zacc[4] = {}, gacc[4] = {};

    for (int kt = 0; kt < 4; kt++) {
        __syncthreads();
        loadQK(Khb, Klb, sbase + AF_SK, kt * 128);
        loadV(kt);
        cp_wait<0>();
        __syncthreads();

        float acc2[2][8][4] = {};
#pragma unroll
        for (int c = 0; c < 2; c++) {
            uint32_t sAh = sbase + AF_SQ + (uint32_t)c * 8192, sAl = sAh + 16384;
            uint32_t sBh = sbase + AF_SK + (uint32_t)c * 8192, sBl = sBh + 16384;
#pragma unroll
            for (int ks = 0; ks < 2; ks++) {
                uint32_t ah[2][4], al[2][4];
#pragma unroll
                for (int ti = 0; ti < 2; ti++) {
                    int r = wm * 32 + ti * 16 + (lane & 15);
                    int cc = 2 * ks + (lane >> 4);
                    uint32_t off = r * 64 + ((cc ^ ((r >> 1) & 3)) << 4);
                    ldsm4(ah[ti][0], ah[ti][1], ah[ti][2], ah[ti][3], sAh + off);
                    ldsm4(al[ti][0], al[ti][1], al[ti][2], al[ti][3], sAl + off);
                }
#pragma unroll
                for (int tj = 0; tj < 4; tj++) {
                    int r = wn * 64 + tj * 16 + (lane & 15);
                    int cc = 2 * ks + (lane >> 4);
                    uint32_t off = r * 64 + ((cc ^ ((r >> 1) & 3)) << 4);
                    uint32_t b0, b1, b2, b3, c0, c1, c2, c3;
                    ldsm4(b0, b1, b2, b3, sBh + off);
                    ldsm4(c0, c1, c2, c3, sBl + off);
                    mma16816(acc2[0][2 * tj],     ah[0], b0, b2);
                    mma16816(acc2[0][2 * tj + 1], ah[0], b1, b3);
                    mma16816(acc2[1][2 * tj],     ah[1], b0, b2);
                    mma16816(acc2[1][2 * tj + 1], ah[1], b1, b3);
                    mma16816(acc2[0][2 * tj],     al[0], b0, b2);
                    mma16816(acc2[0][2 * tj + 1], al[0], b1, b3);
                    mma16816(acc2[1][2 * tj],     al[1], b0, b2);
                    mma16816(acc2[1][2 * tj + 1], al[1], b1, b3);
                    mma16816(acc2[0][2 * tj],     ah[0], c0, c2);
                    mma16816(acc2[0][2 * tj + 1], ah[0], c1, c3);
                    mma16816(acc2[1][2 * tj],     ah[1], c0, c2);
                    mma16816(acc2[1][2 * tj + 1], ah[1], c1, c3);
                }
            }
        }

#pragma unroll
        for (int ti = 0; ti < 2; ti++) {
#pragma unroll
            for (int hh = 0; hh < 2; hh++) {
                int rloc = wm * 32 + ti * 16 + (lane >> 2) + hh * 8;
                float qg = (float)(q0 + rloc);
                float zs = 0.f, gs = 0.f;
#pragma unroll
                for (int tj = 0; tj < 8; tj++) {
                    int kcl = wn * 64 + tj * 8 + 2 * (lane & 3);
                    float kg = (float)(kt * 128 + kcl);
                    float s0 = acc2[ti][tj][2 * hh + 0] * 0.125f;
                    float s1 = acc2[ti][tj][2 * hh + 1] * 0.125f;
                    float p0 = __expf(s0), p1 = __expf(s1);
                    float d0 = qg - kg, d1 = qg - (kg + 1.0f);
                    float g0 = __expf(-d0 * d0 * (1.0f / 32768.0f));
                    float g1 = __expf(-d1 * d1 * (1.0f / 32768.0f));
                    float pg0 = p0 * g0, pg1 = p1 * g1;
                    zs += p0 + p1;
                    gs += pg0 + pg1;
                    __half h0, l0, h1, l1;
                    split_hl(pg0, h0, l0);
                    split_hl(pg1, h1, l1);
                    __half2 hv; hv.x = h0; hv.y = h1;
                    __half2 lv; lv.x = l0; lv.y = l1;
                    int chunk = kcl >> 5;
                    int c32 = kcl & 31;
                    uint32_t off = (uint32_t)chunk * 8192 + rloc * 64
                                 + (((c32 >> 3) ^ ((rloc >> 1) & 3)) << 4) + (c32 & 7) * 2;
                    *(__half2*)(dsm + AF_SP + off) = hv;
                    *(__half2*)(dsm + AF_SP + 32768 + off) = lv;
                }
                zacc[ti * 2 + hh] += zs;
                gacc[ti * 2 + hh] += gs;
            }
        }
        __syncthreads();

#pragma unroll
        for (int ch = 0; ch < 4; ch++) {
            uint32_t sAh = sbase + AF_SP + (uint32_t)ch * 8192, sAl = sAh + 32768;
            uint32_t sBh = sbase + AF_SV + (uint32_t)ch * 4096, sBl = sBh + 16384;
#pragma unroll
            for (int ks = 0; ks < 2; ks++) {
                uint32_t ah[2][4], al[2][4];
#pragma unroll
                for (int ti = 0; ti < 2; ti++) {
                    int r = wm * 32 + ti * 16 + (lane & 15);
                    int cc = 2 * ks + (lane >> 4);
                    uint32_t off = r * 64 + ((cc ^ ((r >> 1) & 3)) << 4);
                    ldsm4(ah[ti][0], ah[ti][1], ah[ti][2], ah[ti][3], sAh + off);
                    ldsm4(al[ti][0], al[ti][1], al[ti][2], al[ti][3], sAl + off);
                }
#pragma unroll
                for (int tj = 0; tj < 2; tj++) {
                    int r = wn * 32 + tj * 16 + (lane & 15);
                    int cc = 2 * ks + (lane >> 4);
                    int fd = ((r >> 1) & 3) ^ ((r >> 3) & 3);
                    uint32_t off = r * 64 + ((cc ^ fd) << 4);
                    uint32_t b0, b1, b2, b3, c0, c1, c2, c3;
                    ldsm4(b0, b1, b2, b3, sBh + off);
                    ldsm4(c0, c1, c2, c3, sBl + off);
                    mma16816(accO[0][2 * tj],     ah[0], b0, b2);
                    mma16816(accO[0][2 * tj + 1], ah[0], b1, b3);
                    mma16816(accO[1][2 * tj],     ah[1], b0, b2);
                    mma16816(accO[1][2 * tj + 1], ah[1], b1, b3);
                    mma16816(accO[0][2 * tj],     al[0], b0, b2);
                    mma16816(accO[0][2 * tj + 1], al[0], b1, b3);
                    mma16816(accO[1][2 * tj],     al[1], b0, b2);
                    mma16816(accO[1][2 * tj + 1], al[1], b1, b3);
                    mma16816(accO[0][2 * tj],     ah[0], c0, c2);
                    mma16816(accO[0][2 * tj + 1], ah[0], c1, c3);
                    mma16816(accO[1][2 * tj],     ah[1], c0, c2);
                    mma16816(accO[1][2 * tj + 1], ah[1], c1, c3);
                }
            }
        }
    }

#pragma unroll
    for (int s = 0; s < 4; s++) {
        zacc[s] += __shfl_xor_sync(~0u, zacc[s], 1);
        zacc[s] += __shfl_xor_sync(~0u, zacc[s], 2);
        gacc[s] += __shfl_xor_sync(~0u, gacc[s], 1);
        gacc[s] += __shfl_xor_sync(~0u, gacc[s], 2);
    }
    if ((lane & 3) == 0) {
#pragma unroll
        for (int ti = 0; ti < 2; ti++)
#pragma unroll
            for (int hh = 0; hh < 2; hh++) {
                int rloc = wm * 32 + ti * 16 + (lane >> 2) + hh * 8;
                atomicAdd(&sZ[rloc], zacc[ti * 2 + hh]);
                atomicAdd(&sG[rloc], gacc[ti * 2 + hh]);
            }
    }
    __syncthreads();
    if (tid < 128) sInv[tid] = 1.0f / (sG[tid] + 1e-5f * sZ[tid]);
    __syncthreads();

#pragma unroll
    for (int ti = 0; ti < 2; ti++) {
#pragma unroll
        for (int tj = 0; tj < 4; tj++) {
            int dl = wn * 32 + tj * 8 + 2 * (lane & 3);
            int colg = h * Dn + dl;
#pragma unroll
            for (int hh = 0; hh < 2; hh++) {
                int rloc = wm * 32 + ti * 16 + (lane >> 2) + hh * 8;
                float inv = sInv[rloc];
                float v0 = accO[ti][tj][2 * hh + 0] * inv;
                float v1 = accO[ti][tj][2 * hh + 1] * inv;
                __half h0, l0, h1, l1;
                split_hl(v0, h0, l0);
                split_hl(v1, h1, l1);
                __half2 hv; hv.x = h0; hv.y = h1;
                __half2 lv; lv.x = l0; lv.y = l1;
                size_t o = (size_t)b * Tn * En + (size_t)(q0 + rloc) * En + colg;
                *(__half2*)(oh + o) = hv;
                *(__half2*)(ol + o) = lv;
            }
        }
    }
}

// ---------------- residual + LN ----------------
__global__ __launch_bounds__(256) void add_ln(
    float* __restrict__ x, const float* __restrict__ r,
    const float* __restrict__ g, const float* __restrict__ bt,
    __half* __restrict__ xh, __half* __restrict__ xl)
{
    const size_t base = (size_t)blockIdx.x * En;
    const int tid = threadIdx.x;
    float v[4];
    float s = 0.f, sq = 0.f;
#pragma unroll
    for (int i = 0; i < 4; i++) {
        int c = tid + i * 256;
        v[i] = x[base + c] + r[base + c];
        s += v[i];
        sq += v[i] * v[i];
    }
    float2 t = blockSum2(s, sq);
    float mu = t.x * (1.0f / En);
    float var = fmaxf(t.y * (1.0f / En) - mu * mu, 0.f);
    float rs = rsqrtf(var + 1e-5f);
#pragma unroll
    for (int i = 0; i < 4; i++) {
        int c = tid + i * 256;
        float o = (v[i] - mu) * rs * g[c] + bt[c];
        x[base + c] = o;
        split_hl(o, xh[base + c], xl[base + c]);
    }
}

__global__ __launch_bounds__(256) void head_kernel(
    const float* __restrict__ x, const float* __restrict__ hw,
    const float* __restrict__ hb, float* __restrict__ out)
{
    const int b = blockIdx.x;
    const int tid = threadIdx.x;
    const float* row = x + (size_t)b * Tn * En + (size_t)(Tn - 1) * En;
    float s = 0.f;
    for (int c = tid; c < En; c += 256) s += row[c] * hw[c];
    s = blockSum(s);
    if (tid == 0) out[b] = s + hb[0];
}

// ---------------- launch ----------------
extern "C" void kernel_launch(void* const* d_in, const int* in_sizes, int n_in,
                              void* d_out, int out_size)
{
    const float* src    = (const float*)d_in[0];
    const float* in_w   = (const float*)d_in[1];
    const float* in_b   = (const float*)d_in[2];
    const float* outp_w = (const float*)d_in[3];
    const float* outp_b = (const float*)d_in[4];
    const float* ff1_w  = (const float*)d_in[5];
    const float* ff1_b  = (const float*)d_in[6];
    const float* ff2_w  = (const float*)d_in[7];
    const float* ff2_b  = (const float*)d_in[8];
    const float* ln1_g  = (const float*)d_in[9];
    const float* ln1_b  = (const float*)d_in[10];
    const float* ln2_g  = (const float*)d_in[11];
    const float* ln2_b  = (const float*)d_in[12];
    const float* head_w = (const float*)d_in[13];
    const float* head_b = (const float*)d_in[14];
    float* out = (float*)d_out;

    static bool init = false;
    static float *x, *proj;
    static __half *xh,*xl,*ah,*al,*fh,*fl,*qkvh,*qkvl,*wih,*woh,*w1h,*w2h;
    if (!init) {
        cudaGetSymbolAddress((void**)&x, g_x);
        cudaGetSymbolAddress((void**)&proj, g_proj);
        cudaGetSymbolAddress((void**)&xh, g_xh); cudaGetSymbolAddress((void**)&xl, g_xl);
        cudaGetSymbolAddress((void**)&ah, g_ah); cudaGetSymbolAddress((void**)&al, g_al);
        cudaGetSymbolAddress((void**)&fh, g_fh); cudaGetSymbolAddress((void**)&fl, g_fl);
        cudaGetSymbolAddress((void**)&qkvh, g_qkvh); cudaGetSymbolAddress((void**)&qkvl, g_qkvl);
        cudaGetSymbolAddress((void**)&wih, g_wih);
        cudaGetSymbolAddress((void**)&woh, g_woh);
        cudaGetSymbolAddress((void**)&w1h, g_w1h);
        cudaGetSymbolAddress((void**)&w2h, g_w2h);
        cudaFuncSetAttribute(gemm_mma, cudaFuncAttributeMaxDynamicSharedMemorySize, 3 * STGB);
        cudaFuncSetAttribute(attn_fused, cudaFuncAttributeMaxDynamicSharedMemorySize, AF_SMEM);
        init = true;
    }

    // weights -> fp16 hi
    convert_h4<<<Ln * 3 * En * En / 1024, 256>>>((const float4*)in_w, (__half2*)wih);
    convert_h4<<<Ln * En * En / 1024, 256>>>((const float4*)outp_w, (__half2*)woh);
    convert_h4<<<Ln * FFn * En / 1024, 256>>>((const float4*)ff1_w, (__half2*)w1h);
    convert_h4<<<Ln * En * FFn / 1024, 256>>>((const float4*)ff2_w, (__half2*)w2h);

    pe_add_kernel<<<Bn * Tn * En / 256, 256>>>(src, x, xh, xl);

    for (int l = 0; l < Ln; l++) {
        size_t wo3 = (size_t)l * 3 * En * En, wo1 = (size_t)l * En * En;
        size_t wof = (size_t)l * FFn * En;
        // qkv (fp16 hi/lo out only)
        gemm_mma<<<dim3(3 * En / BN, Bn * Tn / BM), 256, 3 * STGB>>>(
            xh, xl, wih + wo3, in_b + (size_t)l * 3 * En,
            nullptr, qkvh, qkvl, En, 3 * En, 0);
        // fused attention
        attn_fused<<<dim3(4, Bn * Hn), 256, AF_SMEM>>>(qkvh, qkvl, ah, al);
        // out proj
        gemm_mma<<<dim3(En / BN, Bn * Tn / BM), 256, 3 * STGB>>>(
            ah, al, woh + wo1, outp_b + (size_t)l * En,
            proj, nullptr, nullptr, En, En, 0);
        add_ln<<<Bn * Tn, 256>>>(x, proj, ln1_g + (size_t)l * En, ln1_b + (size_t)l * En, xh, xl);
        // ff1 (relu, hl out)
        gemm_mma<<<dim3(FFn / BN, Bn * Tn / BM), 256, 3 * STGB>>>(
            xh, xl, w1h + wof, ff1_b + (size_t)l * FFn,
            nullptr, fh, fl, En, FFn, 1);
        // ff2
        gemm_mma<<<dim3(En / BN, Bn * Tn / BM), 256, 3 * STGB>>>(
            fh, fl, w2h + wof, ff2_b + (size_t)l * En,
            proj, nullptr, nullptr, FFn, En, 0);
        add_ln<<<Bn * Tn, 256>>>(x, proj, ln2_g + (size_t)l * En, ln2_b + (size_t)l * En, xh, xl);
    }

    head_kernel<<<Bn, 256>>>(x, head_w, head_b, out);
}

// round 11
// speedup vs baseline: 1.5748x; 1.0331x over previous
#include <cuda_runtime.h>
#include <cuda_fp16.h>
#include <math.h>
#include <stdint.h>

#define Bn  8
#define Tn  512
#define En  1024
#define Hn  16
#define Dn  64
#define Ln  4
#define FFn 4096

// fp32 scratch
__device__ float g_x[Bn * Tn * En];
__device__ float g_proj[Bn * Tn * En];
// fp16 hi/lo activation pairs
__device__ __half g_xh[Bn * Tn * En],  g_xl[Bn * Tn * En];
__device__ __half g_ah[Bn * Tn * En],  g_al[Bn * Tn * En];
__device__ __half g_fh[Bn * Tn * FFn], g_fl[Bn * Tn * FFn];
__device__ __half g_qkvh[Bn * Tn * 3 * En], g_qkvl[Bn * Tn * 3 * En];
// fp16 weight (hi only — B-side quantization, 2-term scheme)
__device__ __half g_wih[Ln * 3 * En * En];
__device__ __half g_woh[Ln * En * En];
__device__ __half g_w1h[Ln * FFn * En];
__device__ __half g_w2h[Ln * En * FFn];

// ---------------- PTX helpers (sm_80+ only) ----------------
__device__ __forceinline__ uint32_t smem_u32(const void* p) {
    uint32_t a;
    asm("{ .reg .u64 t; cvta.to.shared.u64 t, %1; cvt.u32.u64 %0, t; }" : "=r"(a) : "l"(p));
    return a;
}
__device__ __forceinline__ void cpasync16(uint32_t dst, const void* src) {
    asm volatile("cp.async.cg.shared.global [%0], [%1], 16;" :: "r"(dst), "l"(src));
}
__device__ __forceinline__ void cp_commit() { asm volatile("cp.async.commit_group;" ::: "memory"); }
template <int N> __device__ __forceinline__ void cp_wait() {
    asm volatile("cp.async.wait_group %0;" :: "n"(N) : "memory");
}
__device__ __forceinline__ void ldsm4(uint32_t& r0, uint32_t& r1, uint32_t& r2,
                                      uint32_t& r3, uint32_t a) {
    asm volatile("ldmatrix.sync.aligned.m8n8.x4.shared.b16 {%0,%1,%2,%3}, [%4];"
                 : "=r"(r0), "=r"(r1), "=r"(r2), "=r"(r3) : "r"(a));
}
__device__ __forceinline__ void mma16816(float* d, const uint32_t* a, uint32_t b0, uint32_t b1) {
    asm volatile("mma.sync.aligned.m16n8k16.row.col.f32.f16.f16.f32 "
                 "{%0,%1,%2,%3}, {%4,%5,%6,%7}, {%8,%9}, {%0,%1,%2,%3};"
                 : "+f"(d[0]), "+f"(d[1]), "+f"(d[2]), "+f"(d[3])
                 : "r"(a[0]), "r"(a[1]), "r"(a[2]), "r"(a[3]), "r"(b0), "r"(b1));
}
__device__ __forceinline__ void split_hl(float v, __half& h, __half& l) {
    h = __float2half_rn(v);
    l = __float2half_rn(v - __half2float(h));
}

// ---------------- reductions ----------------
__device__ __forceinline__ float warpSum(float v) {
#pragma unroll
    for (int o = 16; o; o >>= 1) v += __shfl_xor_sync(~0u, v, o);
    return v;
}
__device__ __forceinline__ float blockSum(float v) {
    __shared__ float sm[8];
    int lane = threadIdx.x & 31, wid = threadIdx.x >> 5;
    v = warpSum(v);
    __syncthreads();
    if (lane == 0) sm[wid] = v;
    __syncthreads();
    v = sm[lane & 7];
#pragma unroll
    for (int o = 4; o; o >>= 1) v += __shfl_xor_sync(~0u, v, o);
    return v;
}
__device__ __forceinline__ float2 blockSum2(float a, float b) {
    __shared__ float2 sm[8];
    int lane = threadIdx.x & 31, wid = threadIdx.x >> 5;
#pragma unroll
    for (int o = 16; o; o >>= 1) {
        a += __shfl_xor_sync(~0u, a, o);
        b += __shfl_xor_sync(~0u, b, o);
    }
    __syncthreads();
    if (lane == 0) sm[wid] = make_float2(a, b);
    __syncthreads();
    float2 v = sm[lane & 7];
#pragma unroll
    for (int o = 4; o; o >>= 1) {
        v.x += __shfl_xor_sync(~0u, v.x, o);
        v.y += __shfl_xor_sync(~0u, v.y, o);
    }
    return v;
}

// ---------------- small kernels ----------------
__global__ void convert_h4(const float4* __restrict__ s, __half2* __restrict__ h) {
    int i = blockIdx.x * 256 + threadIdx.x;
    float4 v = s[i];
    h[2 * i]     = __floats2half2_rn(v.x, v.y);
    h[2 * i + 1] = __floats2half2_rn(v.z, v.w);
}

__global__ void pe_add_kernel(const float* __restrict__ src, float* __restrict__ x,
                              __half* __restrict__ xh, __half* __restrict__ xl) {
    int idx = blockIdx.x * 256 + threadIdx.x;
    int e = idx & (En - 1);
    int b = idx / (Tn * En);
    float dv = expf((float)(e & ~1) * (-9.210340371976184f / (float)En));
    float ang = (float)b * dv;
    float pe = (e & 1) ? cosf(ang) : sinf(ang);
    float v = src[idx] + pe;
    x[idx] = v;
    split_hl(v, xh[idx], xl[idx]);
}

// ---------------- fp16 2-term GEMM: C = (Ah+Al) @ Bh^T + bias ----------------
// CTA 128x128, BK=32, 4-stage cp.async (96 KB), 2 CTA/SM.
#define BM 128
#define BN 128
#define BK 32
#define RGB 8192                    // one 128x32 fp16 region
#define STGB (3 * RGB)              // 24 KB per stage: Ah | Al | Bh

__global__ __launch_bounds__(256, 2) void gemm_mma(
    const __half* __restrict__ Ah, const __half* __restrict__ Al,
    const __half* __restrict__ Bh,
    const float* __restrict__ bias, float* __restrict__ Cf,
    __half* __restrict__ Ch, __half* __restrict__ Cl,
    int K, int N, int relu)
{
    extern __shared__ __align__(128) uint8_t dsm[];
    __shared__ float sh_bias[BN];

    const int tid = threadIdx.x;
    const uint32_t sbase = smem_u32(dsm);
    if (tid < BN) sh_bias[tid] = bias[blockIdx.x * BN + tid];

    const int wid = tid >> 5, lane = tid & 31;
    const int wm = wid >> 1, wn = wid & 1;

    const __half* Abh = Ah + (size_t)blockIdx.y * BM * K;
    const __half* Abl = Al + (size_t)blockIdx.y * BM * K;
    const __half* Bbh = Bh + (size_t)blockIdx.x * BN * K;

    const int cps = K / BK;

    auto load_chunk = [&](int c, int st) {
        int kc = c * BK;
        uint32_t sg = sbase + (uint32_t)st * STGB;
#pragma unroll
        for (int j = 0; j < 2; j++) {
            int idx = tid + j * 256;
            int r = idx >> 2, cc = idx & 3;
            uint32_t off = r * 64 + ((cc ^ ((r >> 1) & 3)) << 4);
            size_t go = (size_t)r * K + kc + cc * 8;
            cpasync16(sg + off,           Abh + go);
            cpasync16(sg + RGB + off,     Abl + go);
            cpasync16(sg + 2 * RGB + off, Bbh + go);
        }
        cp_commit();
    };

    float acc[2][8][4] = {};
    load_chunk(0, 0);
    load_chunk(1, 1);
    load_chunk(2, 2);

    int st = 0;
    for (int c = 0; c < cps; c++) {
        int rem = cps - 1 - c;
        if (rem >= 2)      cp_wait<2>();
        else if (rem == 1) cp_wait<1>();
        else               cp_wait<0>();
        __syncthreads();
        if (c + 3 < cps) {
            int ns = st + 3; if (ns >= 4) ns -= 4;
            load_chunk(c + 3, ns);
        }

        uint32_t sAh = sbase + (uint32_t)st * STGB;
        uint32_t sAl = sAh + RGB;
        uint32_t sBh = sAh + 2 * RGB;
#pragma unroll
        for (int ks = 0; ks < 2; ks++) {
            uint32_t ah[2][4], al[2][4];
#pragma unroll
            for (int ti = 0; ti < 2; ti++) {
                int r = wm * 32 + ti * 16 + (lane & 15);
                int cc = 2 * ks + (lane >> 4);
                uint32_t off = r * 64 + ((cc ^ ((r >> 1) & 3)) << 4);
                ldsm4(ah[ti][0], ah[ti][1], ah[ti][2], ah[ti][3], sAh + off);
                ldsm4(al[ti][0], al[ti][1], al[ti][2], al[ti][3], sAl + off);
            }
#pragma unroll
            for (int tj = 0; tj < 4; tj++) {
                int r = wn * 64 + tj * 16 + (lane & 15);
                int cc = 2 * ks + (lane >> 4);
                uint32_t off = r * 64 + ((cc ^ ((r >> 1) & 3)) << 4);
                uint32_t b0, b1, b2, b3;
                ldsm4(b0, b1, b2, b3, sBh + off);
                mma16816(acc[0][2 * tj],     ah[0], b0, b2);
                mma16816(acc[0][2 * tj + 1], ah[0], b1, b3);
                mma16816(acc[1][2 * tj],     ah[1], b0, b2);
                mma16816(acc[1][2 * tj + 1], ah[1], b1, b3);
                mma16816(acc[0][2 * tj],     al[0], b0, b2);
                mma16816(acc[0][2 * tj + 1], al[0], b1, b3);
                mma16816(acc[1][2 * tj],     al[1], b0, b2);
                mma16816(acc[1][2 * tj + 1], al[1], b1, b3);
            }
        }
        if (++st == 4) st = 0;
    }

    const int col0 = wn * 64;
    const int row0 = blockIdx.y * BM + wm * 32;
#pragma unroll
    for (int ti = 0; ti < 2; ti++) {
#pragma unroll
        for (int tj = 0; tj < 8; tj++) {
            int cl = col0 + tj * 8 + 2 * (lane & 3);
            int colg = blockIdx.x * BN + cl;
            float b0 = sh_bias[cl], b1 = sh_bias[cl + 1];
#pragma unroll
            for (int hh = 0; hh < 2; hh++) {
                int row = row0 + ti * 16 + (lane >> 2) + hh * 8;
                float v0 = acc[ti][tj][2 * hh + 0] + b0;
                float v1 = acc[ti][tj][2 * hh + 1] + b1;
                if (relu) { v0 = fmaxf(v0, 0.f); v1 = fmaxf(v1, 0.f); }
                size_t o = (size_t)row * N + colg;
                if (Cf) *(float2*)(Cf + o) = make_float2(v0, v1);
                if (Ch) {
                    __half h0, l0, h1, l1;
                    split_hl(v0, h0, l0);
                    split_hl(v1, h1, l1);
                    __half2 hv; hv.x = h0; hv.y = h1;
                    __half2 lv; lv.x = l0; lv.y = l1;
                    *(__half2*)(Ch + o) = hv;
                    *(__half2*)(Cl + o) = lv;
                }
            }
        }
    }
}

// ---------------- fused attention v2: q-tile 64, 2 CTA/SM ----------------
// grid (qtile=8, bh=128). Warps 2x4: scores 32q x 32k, PV 32q x 16d.
// Q/K 2-term, V 2-term, P hi-only.
// smem: Qh/Ql 16K | Kh/Kl 32K | Vh/Vl 32K | Ph 16K | stats 768B  = ~96.8 KB
#define QT 64
#define AF_SQ 0
#define AF_SK 16384
#define AF_SV 49152
#define AF_SP 81920
#define AF_SZ 98304
#define AF_SMEM (98304 + 768)

__global__ __launch_bounds__(256, 2) void attn_fused(
    const __half* __restrict__ qkvh, const __half* __restrict__ qkvl,
    __half* __restrict__ oh, __half* __restrict__ ol)
{
    extern __shared__ __align__(128) uint8_t dsm[];
    const int tid = threadIdx.x;
    const uint32_t sbase = smem_u32(dsm);
    const int wid = tid >> 5, lane = tid & 31;
    const int wm = wid >> 2, wn = wid & 3;
    const int bh = blockIdx.y, b = bh >> 4, h = bh & 15;
    const int q0 = blockIdx.x * QT;
    const int LDQ = 3 * En;

    float* sZ = (float*)(dsm + AF_SZ);
    float* sG = (float*)(dsm + AF_SZ + 256);
    float* sInv = (float*)(dsm + AF_SZ + 512);

    const __half* Qhb = qkvh + (size_t)b * Tn * LDQ + h * Dn + (size_t)q0 * LDQ;
    const __half* Qlb = qkvl + (size_t)b * Tn * LDQ + h * Dn + (size_t)q0 * LDQ;
    const __half* Khb = qkvh + (size_t)b * Tn * LDQ + En + h * Dn;
    const __half* Klb = qkvl + (size_t)b * Tn * LDQ + En + h * Dn;
    const __half* Vhb = qkvh + (size_t)b * Tn * LDQ + 2 * En + h * Dn;
    const __half* Vlb = qkvl + (size_t)b * Tn * LDQ + 2 * En + h * Dn;

    // Q: 64 rows x 128B, 2 chunks of 64B; hi at AF_SQ, lo at +8192
    auto loadQ = [&]() {
#pragma unroll
        for (int j = 0; j < 2; j++) {
            int idx = tid + j * 256;            // 0..511
            int r = idx >> 3, gg = idx & 7;
            int chunk = gg >> 2, grp = gg & 3;
            uint32_t off = (uint32_t)chunk * 4096 + r * 64 + ((grp ^ ((r >> 1) & 3)) << 4);
            size_t go = (size_t)r * LDQ + gg * 8;
            cpasync16(sbase + AF_SQ + off, Qhb + go);
            cpasync16(sbase + AF_SQ + 8192 + off, Qlb + go);
        }
        cp_commit();
    };

    // K: 128 rows x 128B, 2 chunks; hi at AF_SK, lo at +16384
    auto loadK = [&](int kt) {
#pragma unroll
        for (int j = 0; j < 4; j++) {
            int idx = tid + j * 256;            // 0..1023
            int r = idx >> 3, gg = idx & 7;
            int chunk = gg >> 2, grp = gg & 3;
            uint32_t off = (uint32_t)chunk * 8192 + r * 64 + ((grp ^ ((r >> 1) & 3)) << 4);
            size_t go = (size_t)(kt * 128 + r) * LDQ + gg * 8;
            cpasync16(sbase + AF_SK + off, Khb + go);
            cpasync16(sbase + AF_SK + 16384 + off, Klb + go);
        }
        cp_commit();
    };

    // V transposed [d][k], 4 chunks of 32k; hi at AF_SV, lo at +16384
    auto loadV = [&](int kt) {
#pragma unroll
        for (int p = 0; p < 4; p++) {
            int kk = tid >> 3;
            int d0 = (tid & 7) * 8;
            size_t go = (size_t)(kt * 128 + p * 32 + kk) * LDQ + d0;
            uint4 hv = *(const uint4*)(Vhb + go);
            uint4 lv = *(const uint4*)(Vlb + go);
            uint32_t h4[4] = {hv.x, hv.y, hv.z, hv.w};
            uint32_t l4[4] = {lv.x, lv.y, lv.z, lv.w};
#pragma unroll
            for (int i = 0; i < 8; i++) {
                uint16_t hb16 = (uint16_t)(h4[i >> 1] >> ((i & 1) * 16));
                uint16_t lb16 = (uint16_t)(l4[i >> 1] >> ((i & 1) * 16));
                int d = d0 + i;
                int fd = ((d >> 1) & 3) ^ ((d >> 3) & 3);
                uint32_t off = (uint32_t)p * 4096 + d * 64 + (((kk >> 3) ^ fd) << 4) + (kk & 7) * 2;
                *(uint16_t*)(dsm + AF_SV + off) = hb16;
                *(uint16_t*)(dsm + AF_SV + 16384 + off) = lb16;
            }
        }
    };

    loadQ();
    if (tid < QT) { sZ[tid] = 0.f; sG[tid] = 0.f; }

    float accO[2][2][4] = {};
    float zacc[4] = {}, gacc[4] = {};

    for (int kt = 0; kt < 4; kt++) {
        __syncthreads();
        loadK(kt);
        loadV(kt);
        cp_wait<0>();
        __syncthreads();

        // ---- scores: S = Q K^T (64q x 128k), K-contraction 64 in 2 chunks ----
        float acc2[2][4][4] = {};
#pragma unroll
        for (int c = 0; c < 2; c++) {
            uint32_t sAh = sbase + AF_SQ + (uint32_t)c * 4096, sAl = sAh + 8192;
            uint32_t sBh = sbase + AF_SK + (uint32_t)c * 8192, sBl = sBh + 16384;
#pragma unroll
            for (int ks = 0; ks < 2; ks++) {
                uint32_t ah[2][4], al[2][4];
#pragma unroll
                for (int ti = 0; ti < 2; ti++) {
                    int r = wm * 32 + ti * 16 + (lane & 15);
                    int cc = 2 * ks + (lane >> 4);
                    uint32_t off = r * 64 + ((cc ^ ((r >> 1) & 3)) << 4);
                    ldsm4(ah[ti][0], ah[ti][1], ah[ti][2], ah[ti][3], sAh + off);
                    ldsm4(al[ti][0], al[ti][1], al[ti][2], al[ti][3], sAl + off);
                }
#pragma unroll
                for (int tjj = 0; tjj < 2; tjj++) {
                    int r = wn * 32 + tjj * 16 + (lane & 15);
                    int cc = 2 * ks + (lane >> 4);
                    uint32_t off = r * 64 + ((cc ^ ((r >> 1) & 3)) << 4);
                    uint32_t b0, b1, b2, b3, c0, c1, c2, c3;
                    ldsm4(b0, b1, b2, b3, sBh + off);
                    ldsm4(c0, c1, c2, c3, sBl + off);
#pragma unroll
                    for (int ti = 0; ti < 2; ti++) {
                        mma16816(acc2[ti][2 * tjj],     ah[ti], b0, b2);
                        mma16816(acc2[ti][2 * tjj + 1], ah[ti], b1, b3);
                        mma16816(acc2[ti][2 * tjj],     al[ti], b0, b2);
                        mma16816(acc2[ti][2 * tjj + 1], al[ti], b1, b3);
                        mma16816(acc2[ti][2 * tjj],     ah[ti], c0, c2);
                        mma16816(acc2[ti][2 * tjj + 1], ah[ti], c1, c3);
                    }
                }
            }
        }

        // ---- p*g, accumulate Z/G, store P hi to smem ----
#pragma unroll
        for (int ti = 0; ti < 2; ti++) {
#pragma unroll
            for (int hh = 0; hh < 2; hh++) {
                int rloc = wm * 32 + ti * 16 + (lane >> 2) + hh * 8;
                float qg = (float)(q0 + rloc);
                float zs = 0.f, gs = 0.f;
#pragma unroll
                for (int tj = 0; tj < 4; tj++) {
                    int kcl = wn * 32 + tj * 8 + 2 * (lane & 3);
                    float kg = (float)(kt * 128 + kcl);
                    float s0 = acc2[ti][tj][2 * hh + 0] * 0.125f;
                    float s1 = acc2[ti][tj][2 * hh + 1] * 0.125f;
                    float p0 = __expf(s0), p1 = __expf(s1);
                    float d0 = qg - kg, d1 = qg - (kg + 1.0f);
                    float g0 = __expf(-d0 * d0 * (1.0f / 32768.0f));
                    float g1 = __expf(-d1 * d1 * (1.0f / 32768.0f));
                    float pg0 = p0 * g0, pg1 = p1 * g1;
                    zs += p0 + p1;
                    gs += pg0 + pg1;
                    __half2 ph2 = __floats2half2_rn(pg0, pg1);
                    int chunk = kcl >> 5;
                    int c32 = kcl & 31;
                    uint32_t off = (uint32_t)chunk * 4096 + rloc * 64
                                 + (((c32 >> 3) ^ ((rloc >> 1) & 3)) << 4) + (c32 & 7) * 2;
                    *(__half2*)(dsm + AF_SP + off) = ph2;
                }
                zacc[ti * 2 + hh] += zs;
                gacc[ti * 2 + hh] += gs;
            }
        }
        __syncthreads();

        // ---- PV: accO += Ph @ (Vh+Vl) (4 chunks of 32 k) ----
#pragma unroll
        for (int ch = 0; ch < 4; ch++) {
            uint32_t sAh = sbase + AF_SP + (uint32_t)ch * 4096;
            uint32_t sBh = sbase + AF_SV + (uint32_t)ch * 4096, sBl = sBh + 16384;
#pragma unroll
            for (int ks = 0; ks < 2; ks++) {
                uint32_t ph[2][4];
#pragma unroll
                for (int ti = 0; ti < 2; ti++) {
                    int r = wm * 32 + ti * 16 + (lane & 15);
                    int cc = 2 * ks + (lane >> 4);
                    uint32_t off = r * 64 + ((cc ^ ((r >> 1) & 3)) << 4);
                    ldsm4(ph[ti][0], ph[ti][1], ph[ti][2], ph[ti][3], sAh + off);
                }
                int r = wn * 16 + (lane & 15);
                int cc = 2 * ks + (lane >> 4);
                int fd = ((r >> 1) & 3) ^ ((r >> 3) & 3);
                uint32_t off = r * 64 + ((cc ^ fd) << 4);
                uint32_t b0, b1, b2, b3, c0, c1, c2, c3;
                ldsm4(b0, b1, b2, b3, sBh + off);
                ldsm4(c0, c1, c2, c3, sBl + off);
#pragma unroll
                for (int ti = 0; ti < 2; ti++) {
                    mma16816(accO[ti][0], ph[ti], b0, b2);
                    mma16816(accO[ti][1], ph[ti], b1, b3);
                    mma16816(accO[ti][0], ph[ti], c0, c2);
                    mma16816(accO[ti][1], ph[ti], c1, c3);
                }
            }
        }
    }

    // ---- reduce Z/G per row; normalize; write O ----
#pragma unroll
    for (int s = 0; s < 4; s++) {
        zacc[s] += __shfl_xor_sync(~0u, zacc[s], 1);
        zacc[s] += __shfl_xor_sync(~0u, zacc[s], 2);
        gacc[s] += __shfl_xor_sync(~0u, gacc[s], 1);
        gacc[s] += __shfl_xor_sync(~0u, gacc[s], 2);
    }
    if ((lane & 3) == 0) {
#pragma unroll
        for (int ti = 0; ti < 2; ti++)
#pragma unroll
            for (int hh = 0; hh < 2; hh++) {
                int rloc = wm * 32 + ti * 16 + (lane >> 2) + hh * 8;
                atomicAdd(&sZ[rloc], zacc[ti * 2 + hh]);
                atomicAdd(&sG[rloc], gacc[ti * 2 + hh]);
            }
    }
    __syncthreads();
    if (tid < QT) sInv[tid] = 1.0f / (sG[tid] + 1e-5f * sZ[tid]);
    __syncthreads();

#pragma unroll
    for (int ti = 0; ti < 2; ti++) {
#pragma unroll
        for (int tj = 0; tj < 2; tj++) {
            int dl = wn * 16 + tj * 8 + 2 * (lane & 3);
            int colg = h * Dn + dl;
#pragma unroll
            for (int hh = 0; hh < 2; hh++) {
                int rloc = wm * 32 + ti * 16 + (lane >> 2) + hh * 8;
                float inv = sInv[rloc];
                float v0 = accO[ti][tj][2 * hh + 0] * inv;
                float v1 = accO[ti][tj][2 * hh + 1] * inv;
                __half h0, l0, h1, l1;
                split_hl(v0, h0, l0);
                split_hl(v1, h1, l1);
                __half2 hv; hv.x = h0; hv.y = h1;
                __half2 lv; lv.x = l0; lv.y = l1;
                size_t o = (size_t)b * Tn * En + (size_t)(q0 + rloc) * En + colg;
                *(__half2*)(oh + o) = hv;
                *(__half2*)(ol + o) = lv;
            }
        }
    }
}

// ---------------- residual + LN ----------------
__global__ __launch_bounds__(256) void add_ln(
    float* __restrict__ x, const float* __restrict__ r,
    const float* __restrict__ g, const float* __restrict__ bt,
    __half* __restrict__ xh, __half* __restrict__ xl)
{
    const size_t base = (size_t)blockIdx.x * En;
    const int tid = threadIdx.x;
    float v[4];
    float s = 0.f, sq = 0.f;
#pragma unroll
    for (int i = 0; i < 4; i++) {
        int c = tid + i * 256;
        v[i] = x[base + c] + r[base + c];
        s += v[i];
        sq += v[i] * v[i];
    }
    float2 t = blockSum2(s, sq);
    float mu = t.x * (1.0f / En);
    float var = fmaxf(t.y * (1.0f / En) - mu * mu, 0.f);
    float rs = rsqrtf(var + 1e-5f);
#pragma unroll
    for (int i = 0; i < 4; i++) {
        int c = tid + i * 256;
        float o = (v[i] - mu) * rs * g[c] + bt[c];
        x[base + c] = o;
        split_hl(o, xh[base + c], xl[base + c]);
    }
}

__global__ __launch_bounds__(256) void head_kernel(
    const float* __restrict__ x, const float* __restrict__ hw,
    const float* __restrict__ hb, float* __restrict__ out)
{
    const int b = blockIdx.x;
    const int tid = threadIdx.x;
    const float* row = x + (size_t)b * Tn * En + (size_t)(Tn - 1) * En;
    float s = 0.f;
    for (int c = tid; c < En; c += 256) s += row[c] * hw[c];
    s = blockSum(s);
    if (tid == 0) out[b] = s + hb[0];
}

// ---------------- launch ----------------
extern "C" void kernel_launch(void* const* d_in, const int* in_sizes, int n_in,
                              void* d_out, int out_size)
{
    const float* src    = (const float*)d_in[0];
    const float* in_w   = (const float*)d_in[1];
    const float* in_b   = (const float*)d_in[2];
    const float* outp_w = (const float*)d_in[3];
    const float* outp_b = (const float*)d_in[4];
    const float* ff1_w  = (const float*)d_in[5];
    const float* ff1_b  = (const float*)d_in[6];
    const float* ff2_w  = (const float*)d_in[7];
    const float* ff2_b  = (const float*)d_in[8];
    const float* ln1_g  = (const float*)d_in[9];
    const float* ln1_b  = (const float*)d_in[10];
    const float* ln2_g  = (const float*)d_in[11];
    const float* ln2_b  = (const float*)d_in[12];
    const float* head_w = (const float*)d_in[13];
    const float* head_b = (const float*)d_in[14];
    float* out = (float*)d_out;

    static bool init = false;
    static float *x, *proj;
    static __half *xh,*xl,*ah,*al,*fh,*fl,*qkvh,*qkvl,*wih,*woh,*w1h,*w2h;
    if (!init) {
        cudaGetSymbolAddress((void**)&x, g_x);
        cudaGetSymbolAddress((void**)&proj, g_proj);
        cudaGetSymbolAddress((void**)&xh, g_xh); cudaGetSymbolAddress((void**)&xl, g_xl);
        cudaGetSymbolAddress((void**)&ah, g_ah); cudaGetSymbolAddress((void**)&al, g_al);
        cudaGetSymbolAddress((void**)&fh, g_fh); cudaGetSymbolAddress((void**)&fl, g_fl);
        cudaGetSymbolAddress((void**)&qkvh, g_qkvh); cudaGetSymbolAddress((void**)&qkvl, g_qkvl);
        cudaGetSymbolAddress((void**)&wih, g_wih);
        cudaGetSymbolAddress((void**)&woh, g_woh);
        cudaGetSymbolAddress((void**)&w1h, g_w1h);
        cudaGetSymbolAddress((void**)&w2h, g_w2h);
        cudaFuncSetAttribute(gemm_mma, cudaFuncAttributeMaxDynamicSharedMemorySize, 4 * STGB);
        cudaFuncSetAttribute(attn_fused, cudaFuncAttributeMaxDynamicSharedMemorySize, AF_SMEM);
        init = true;
    }

    // weights -> fp16 hi
    convert_h4<<<Ln * 3 * En * En / 1024, 256>>>((const float4*)in_w, (__half2*)wih);
    convert_h4<<<Ln * En * En / 1024, 256>>>((const float4*)outp_w, (__half2*)woh);
    convert_h4<<<Ln * FFn * En / 1024, 256>>>((const float4*)ff1_w, (__half2*)w1h);
    convert_h4<<<Ln * En * FFn / 1024, 256>>>((const float4*)ff2_w, (__half2*)w2h);

    pe_add_kernel<<<Bn * Tn * En / 256, 256>>>(src, x, xh, xl);

    for (int l = 0; l < Ln; l++) {
        size_t wo3 = (size_t)l * 3 * En * En, wo1 = (size_t)l * En * En;
        size_t wof = (size_t)l * FFn * En;
        // qkv (fp16 hi/lo out only)
        gemm_mma<<<dim3(3 * En / BN, Bn * Tn / BM), 256, 4 * STGB>>>(
            xh, xl, wih + wo3, in_b + (size_t)l * 3 * En,
            nullptr, qkvh, qkvl, En, 3 * En, 0);
        // fused attention (q-tile 64, 2 CTA/SM)
        attn_fused<<<dim3(Tn / QT, Bn * Hn), 256, AF_SMEM>>>(qkvh, qkvl, ah, al);
        // out proj
        gemm_mma<<<dim3(En / BN, Bn * Tn / BM), 256, 4 * STGB>>>(
            ah, al, woh + wo1, outp_b + (size_t)l * En,
            proj, nullptr, nullptr, En, En, 0);
        add_ln<<<Bn * Tn, 256>>>(x, proj, ln1_g + (size_t)l * En, ln1_b + (size_t)l * En, xh, xl);
        // ff1 (relu, hl out)
        gemm_mma<<<dim3(FFn / BN, Bn * Tn / BM), 256, 4 * STGB>>>(
            xh, xl, w1h + wof, ff1_b + (size_t)l * FFn,
            nullptr, fh, fl, En, FFn, 1);
        // ff2
        gemm_mma<<<dim3(En / BN, Bn * Tn / BM), 256, 4 * STGB>>>(
            fh, fl, w2h + wof, ff2_b + (size_t)l * En,
            proj, nullptr, nullptr, FFn, En, 0);
        add_ln<<<Bn * Tn, 256>>>(x, proj, ln2_g + (size_t)l * En, ln2_b + (size_t)l * En, xh, xl);
    }

    head_kernel<<<Bn, 256>>>(x, head_w, head_b, out);
}

// round 13
// speedup vs baseline: 1.7951x; 1.1399x over previous
#include <cuda_runtime.h>
#include <cuda_fp16.h>
#include <math.h>
#include <stdint.h>

#define Bn  8
#define Tn  512
#define En  1024
#define Hn  16
#define Dn  64
#define Ln  4
#define FFn 4096

// fp32 scratch
__device__ float g_x[Bn * Tn * En];
__device__ float g_proj[Bn * Tn * En];
// fp16 hi/lo activation pairs
__device__ __half g_xh[Bn * Tn * En],  g_xl[Bn * Tn * En];
__device__ __half g_ah[Bn * Tn * En],  g_al[Bn * Tn * En];
__device__ __half g_fh[Bn * Tn * FFn];
__device__ __half g_qkvh[Bn * Tn * 3 * En], g_qkvl[Bn * Tn * 3 * En];
// fp16 weight (hi only — B-side quantization)
__device__ __half g_wih[Ln * 3 * En * En];
__device__ __half g_woh[Ln * En * En];
__device__ __half g_w1h[Ln * FFn * En];
__device__ __half g_w2h[Ln * En * FFn];

// ---------------- PTX helpers (sm_80+ only) ----------------
__device__ __forceinline__ uint32_t smem_u32(const void* p) {
    uint32_t a;
    asm("{ .reg .u64 t; cvta.to.shared.u64 t, %1; cvt.u32.u64 %0, t; }" : "=r"(a) : "l"(p));
    return a;
}
__device__ __forceinline__ void cpasync16(uint32_t dst, const void* src) {
    asm volatile("cp.async.cg.shared.global [%0], [%1], 16;" :: "r"(dst), "l"(src));
}
__device__ __forceinline__ void cp_commit() { asm volatile("cp.async.commit_group;" ::: "memory"); }
template <int N> __device__ __forceinline__ void cp_wait() {
    asm volatile("cp.async.wait_group %0;" :: "n"(N) : "memory");
}
__device__ __forceinline__ void ldsm4(uint32_t& r0, uint32_t& r1, uint32_t& r2,
                                      uint32_t& r3, uint32_t a) {
    asm volatile("ldmatrix.sync.aligned.m8n8.x4.shared.b16 {%0,%1,%2,%3}, [%4];"
                 : "=r"(r0), "=r"(r1), "=r"(r2), "=r"(r3) : "r"(a));
}
__device__ __forceinline__ void mma16816(float* d, const uint32_t* a, uint32_t b0, uint32_t b1) {
    asm volatile("mma.sync.aligned.m16n8k16.row.col.f32.f16.f16.f32 "
                 "{%0,%1,%2,%3}, {%4,%5,%6,%7}, {%8,%9}, {%0,%1,%2,%3};"
                 : "+f"(d[0]), "+f"(d[1]), "+f"(d[2]), "+f"(d[3])
                 : "r"(a[0]), "r"(a[1]), "r"(a[2]), "r"(a[3]), "r"(b0), "r"(b1));
}
__device__ __forceinline__ void split_hl(float v, __half& h, __half& l) {
    h = __float2half_rn(v);
    l = __float2half_rn(v - __half2float(h));
}

// ---------------- reductions ----------------
__device__ __forceinline__ float warpSum(float v) {
#pragma unroll
    for (int o = 16; o; o >>= 1) v += __shfl_xor_sync(~0u, v, o);
    return v;
}
__device__ __forceinline__ float blockSum(float v) {
    __shared__ float sm[8];
    int lane = threadIdx.x & 31, wid = threadIdx.x >> 5;
    v = warpSum(v);
    __syncthreads();
    if (lane == 0) sm[wid] = v;
    __syncthreads();
    v = sm[lane & 7];
#pragma unroll
    for (int o = 4; o; o >>= 1) v += __shfl_xor_sync(~0u, v, o);
    return v;
}
__device__ __forceinline__ float2 blockSum2(float a, float b) {
    __shared__ float2 sm[8];
    int lane = threadIdx.x & 31, wid = threadIdx.x >> 5;
#pragma unroll
    for (int o = 16; o; o >>= 1) {
        a += __shfl_xor_sync(~0u, a, o);
        b += __shfl_xor_sync(~0u, b, o);
    }
    __syncthreads();
    if (lane == 0) sm[wid] = make_float2(a, b);
    __syncthreads();
    float2 v = sm[lane & 7];
#pragma unroll
    for (int o = 4; o; o >>= 1) {
        v.x += __shfl_xor_sync(~0u, v.x, o);
        v.y += __shfl_xor_sync(~0u, v.y, o);
    }
    return v;
}

// ---------------- small kernels ----------------
__global__ void convert_h4(const float4* __restrict__ s, __half2* __restrict__ h) {
    int i = blockIdx.x * 256 + threadIdx.x;
    float4 v = s[i];
    h[2 * i]     = __floats2half2_rn(v.x, v.y);
    h[2 * i + 1] = __floats2half2_rn(v.z, v.w);
}

__global__ void pe_add_kernel(const float* __restrict__ src, float* __restrict__ x,
                              __half* __restrict__ xh, __half* __restrict__ xl) {
    int idx = blockIdx.x * 256 + threadIdx.x;
    int e = idx & (En - 1);
    int b = idx / (Tn * En);
    float dv = expf((float)(e & ~1) * (-9.210340371976184f / (float)En));
    float ang = (float)b * dv;
    float pe = (e & 1) ? cosf(ang) : sinf(ang);
    float v = src[idx] + pe;
    x[idx] = v;
    split_hl(v, xh[idx], xl[idx]);
}

// ---------------- fp16 GEMM: C = (Ah[+Al]) @ Bh^T + bias ----------------
// TWOA: 2-term A (hi+lo). CTA 128x128, BK=32, 4-stage cp.async, 2 CTA/SM.
#define BM 128
#define BN 128
#define BK 32
#define RGB 8192                    // one 128x32 fp16 region
#define STGB (3 * RGB)              // stage stride (regions: Ah | Al | Bh)

template <bool TWOA>
__global__ __launch_bounds__(256, 2) void gemm_mma(
    const __half* __restrict__ Ah, const __half* __restrict__ Al,
    const __half* __restrict__ Bh,
    const float* __restrict__ bias, float* __restrict__ Cf,
    __half* __restrict__ Ch, __half* __restrict__ Cl,
    int K, int N, int relu)
{
    extern __shared__ __align__(128) uint8_t dsm[];
    __shared__ float sh_bias[BN];

    const int tid = threadIdx.x;
    const uint32_t sbase = smem_u32(dsm);
    if (tid < BN) sh_bias[tid] = bias[blockIdx.x * BN + tid];

    const int wid = tid >> 5, lane = tid & 31;
    const int wm = wid >> 1, wn = wid & 1;

    const __half* Abh = Ah + (size_t)blockIdx.y * BM * K;
    const __half* Abl = TWOA ? Al + (size_t)blockIdx.y * BM * K : nullptr;
    const __half* Bbh = Bh + (size_t)blockIdx.x * BN * K;

    const int cps = K / BK;

    auto load_chunk = [&](int c, int st) {
        int kc = c * BK;
        uint32_t sg = sbase + (uint32_t)st * STGB;
#pragma unroll
        for (int j = 0; j < 2; j++) {
            int idx = tid + j * 256;
            int r = idx >> 2, cc = idx & 3;
            uint32_t off = r * 64 + ((cc ^ ((r >> 1) & 3)) << 4);
            size_t go = (size_t)r * K + kc + cc * 8;
            cpasync16(sg + off, Abh + go);
            if (TWOA) cpasync16(sg + RGB + off, Abl + go);
            cpasync16(sg + 2 * RGB + off, Bbh + go);
        }
        cp_commit();
    };

    float acc[2][8][4] = {};
    load_chunk(0, 0);
    load_chunk(1, 1);
    load_chunk(2, 2);

    int st = 0;
    for (int c = 0; c < cps; c++) {
        int rem = cps - 1 - c;
        if (rem >= 2)      cp_wait<2>();
        else if (rem == 1) cp_wait<1>();
        else               cp_wait<0>();
        __syncthreads();
        if (c + 3 < cps) {
            int ns = st + 3; if (ns >= 4) ns -= 4;
            load_chunk(c + 3, ns);
        }

        uint32_t sAh = sbase + (uint32_t)st * STGB;
        uint32_t sAl = sAh + RGB;
        uint32_t sBh = sAh + 2 * RGB;
#pragma unroll
        for (int ks = 0; ks < 2; ks++) {
            uint32_t ah[2][4], al[2][4];
#pragma unroll
            for (int ti = 0; ti < 2; ti++) {
                int r = wm * 32 + ti * 16 + (lane & 15);
                int cc = 2 * ks + (lane >> 4);
                uint32_t off = r * 64 + ((cc ^ ((r >> 1) & 3)) << 4);
                ldsm4(ah[ti][0], ah[ti][1], ah[ti][2], ah[ti][3], sAh + off);
                if (TWOA) ldsm4(al[ti][0], al[ti][1], al[ti][2], al[ti][3], sAl + off);
            }
#pragma unroll
            for (int tj = 0; tj < 4; tj++) {
                int r = wn * 64 + tj * 16 + (lane & 15);
                int cc = 2 * ks + (lane >> 4);
                uint32_t off = r * 64 + ((cc ^ ((r >> 1) & 3)) << 4);
                uint32_t b0, b1, b2, b3;
                ldsm4(b0, b1, b2, b3, sBh + off);
                mma16816(acc[0][2 * tj],     ah[0], b0, b2);
                mma16816(acc[0][2 * tj + 1], ah[0], b1, b3);
                mma16816(acc[1][2 * tj],     ah[1], b0, b2);
                mma16816(acc[1][2 * tj + 1], ah[1], b1, b3);
                if (TWOA) {
                    mma16816(acc[0][2 * tj],     al[0], b0, b2);
                    mma16816(acc[0][2 * tj + 1], al[0], b1, b3);
                    mma16816(acc[1][2 * tj],     al[1], b0, b2);
                    mma16816(acc[1][2 * tj + 1], al[1], b1, b3);
                }
            }
        }
        if (++st == 4) st = 0;
    }

    const int col0 = wn * 64;
    const int row0 = blockIdx.y * BM + wm * 32;
#pragma unroll
    for (int ti = 0; ti < 2; ti++) {
#pragma unroll
        for (int tj = 0; tj < 8; tj++) {
            int cl = col0 + tj * 8 + 2 * (lane & 3);
            int colg = blockIdx.x * BN + cl;
            float b0 = sh_bias[cl], b1 = sh_bias[cl + 1];
#pragma unroll
            for (int hh = 0; hh < 2; hh++) {
                int row = row0 + ti * 16 + (lane >> 2) + hh * 8;
                float v0 = acc[ti][tj][2 * hh + 0] + b0;
                float v1 = acc[ti][tj][2 * hh + 1] + b1;
                if (relu) { v0 = fmaxf(v0, 0.f); v1 = fmaxf(v1, 0.f); }
                size_t o = (size_t)row * N + colg;
                if (Cf) *(float2*)(Cf + o) = make_float2(v0, v1);
                if (Ch) {
                    if (Cl) {
                        __half h0, l0, h1, l1;
                        split_hl(v0, h0, l0);
                        split_hl(v1, h1, l1);
                        __half2 hv; hv.x = h0; hv.y = h1;
                        __half2 lv; lv.x = l0; lv.y = l1;
                        *(__half2*)(Ch + o) = hv;
                        *(__half2*)(Cl + o) = lv;
                    } else {
                        *(__half2*)(Ch + o) = __floats2half2_rn(v0, v1);
                    }
                }
            }
        }
    }
}

// ---------------- fused attention v2: q-tile 64, 2 CTA/SM ----------------
#define QT 64
#define AF_SQ 0
#define AF_SK 16384
#define AF_SV 49152
#define AF_SP 81920
#define AF_SZ 98304
#define AF_SMEM (98304 + 768)

__global__ __launch_bounds__(256, 2) void attn_fused(
    const __half* __restrict__ qkvh, const __half* __restrict__ qkvl,
    __half* __restrict__ oh, __half* __restrict__ ol)
{
    extern __shared__ __align__(128) uint8_t dsm[];
    const int tid = threadIdx.x;
    const uint32_t sbase = smem_u32(dsm);
    const int wid = tid >> 5, lane = tid & 31;
    const int wm = wid >> 2, wn = wid & 3;
    const int bh = blockIdx.y, b = bh >> 4, h = bh & 15;
    const int q0 = blockIdx.x * QT;
    const int LDQ = 3 * En;

    float* sZ = (float*)(dsm + AF_SZ);
    float* sG = (float*)(dsm + AF_SZ + 256);
    float* sInv = (float*)(dsm + AF_SZ + 512);

    const __half* Qhb = qkvh + (size_t)b * Tn * LDQ + h * Dn + (size_t)q0 * LDQ;
    const __half* Qlb = qkvl + (size_t)b * Tn * LDQ + h * Dn + (size_t)q0 * LDQ;
    const __half* Khb = qkvh + (size_t)b * Tn * LDQ + En + h * Dn;
    const __half* Klb = qkvl + (size_t)b * Tn * LDQ + En + h * Dn;
    const __half* Vhb = qkvh + (size_t)b * Tn * LDQ + 2 * En + h * Dn;
    const __half* Vlb = qkvl + (size_t)b * Tn * LDQ + 2 * En + h * Dn;

    auto loadQ = [&]() {
#pragma unroll
        for (int j = 0; j < 2; j++) {
            int idx = tid + j * 256;
            int r = idx >> 3, gg = idx & 7;
            int chunk = gg >> 2, grp = gg & 3;
            uint32_t off = (uint32_t)chunk * 4096 + r * 64 + ((grp ^ ((r >> 1) & 3)) << 4);
            size_t go = (size_t)r * LDQ + gg * 8;
            cpasync16(sbase + AF_SQ + off, Qhb + go);
            cpasync16(sbase + AF_SQ + 8192 + off, Qlb + go);
        }
        cp_commit();
    };

    auto loadK = [&](int kt) {
#pragma unroll
        for (int j = 0; j < 4; j++) {
            int idx = tid + j * 256;
            int r = idx >> 3, gg = idx & 7;
            int chunk = gg >> 2, grp = gg & 3;
            uint32_t off = (uint32_t)chunk * 8192 + r * 64 + ((grp ^ ((r >> 1) & 3)) << 4);
            size_t go = (size_t)(kt * 128 + r) * LDQ + gg * 8;
            cpasync16(sbase + AF_SK + off, Khb + go);
            cpasync16(sbase + AF_SK + 16384 + off, Klb + go);
        }
        cp_commit();
    };

    auto loadV = [&](int kt) {
#pragma unroll
        for (int p = 0; p < 4; p++) {
            int kk = tid >> 3;
            int d0 = (tid & 7) * 8;
            size_t go = (size_t)(kt * 128 + p * 32 + kk) * LDQ + d0;
            uint4 hv = *(const uint4*)(Vhb + go);
            uint4 lv = *(const uint4*)(Vlb + go);
            uint32_t h4[4] = {hv.x, hv.y, hv.z, hv.w};
            uint32_t l4[4] = {lv.x, lv.y, lv.z, lv.w};
#pragma unroll
            for (int i = 0; i < 8; i++) {
                uint16_t hb16 = (uint16_t)(h4[i >> 1] >> ((i & 1) * 16));
                uint16_t lb16 = (uint16_t)(l4[i >> 1] >> ((i & 1) * 16));
                int d = d0 + i;
                int fd = ((d >> 1) & 3) ^ ((d >> 3) & 3);
                uint32_t off = (uint32_t)p * 4096 + d * 64 + (((kk >> 3) ^ fd) << 4) + (kk & 7) * 2;
                *(uint16_t*)(dsm + AF_SV + off) = hb16;
                *(uint16_t*)(dsm + AF_SV + 16384 + off) = lb16;
            }
        }
    };

    loadQ();
    if (tid < QT) { sZ[tid] = 0.f; sG[tid] = 0.f; }

    float accO[2][2][4] = {};
    float zacc[4] = {}, gacc[4] = {};

    for (int kt = 0; kt < 4; kt++) {
        __syncthreads();
        loadK(kt);
        loadV(kt);
        cp_wait<0>();
        __syncthreads();

        float acc2[2][4][4] = {};
#pragma unroll
        for (int c = 0; c < 2; c++) {
            uint32_t sAh = sbase + AF_SQ + (uint32_t)c * 4096, sAl = sAh + 8192;
            uint32_t sBh = sbase + AF_SK + (uint32_t)c * 8192, sBl = sBh + 16384;
#pragma unroll
            for (int ks = 0; ks < 2; ks++) {
                uint32_t ah[2][4], al[2][4];
#pragma unroll
                for (int ti = 0; ti < 2; ti++) {
                    int r = wm * 32 + ti * 16 + (lane & 15);
                    int cc = 2 * ks + (lane >> 4);
                    uint32_t off = r * 64 + ((cc ^ ((r >> 1) & 3)) << 4);
                    ldsm4(ah[ti][0], ah[ti][1], ah[ti][2], ah[ti][3], sAh + off);
                    ldsm4(al[ti][0], al[ti][1], al[ti][2], al[ti][3], sAl + off);
                }
#pragma unroll
                for (int tjj = 0; tjj < 2; tjj++) {
                    int r = wn * 32 + tjj * 16 + (lane & 15);
                    int cc = 2 * ks + (lane >> 4);
                    uint32_t off = r * 64 + ((cc ^ ((r >> 1) & 3)) << 4);
                    uint32_t b0, b1, b2, b3, c0, c1, c2, c3;
                    ldsm4(b0, b1, b2, b3, sBh + off);
                    ldsm4(c0, c1, c2, c3, sBl + off);
#pragma unroll
                    for (int ti = 0; ti < 2; ti++) {
                        mma16816(acc2[ti][2 * tjj],     ah[ti], b0, b2);
                        mma16816(acc2[ti][2 * tjj + 1], ah[ti], b1, b3);
                        mma16816(acc2[ti][2 * tjj],     al[ti], b0, b2);
                        mma16816(acc2[ti][2 * tjj + 1], al[ti], b1, b3);
                        mma16816(acc2[ti][2 * tjj],     ah[ti], c0, c2);
                        mma16816(acc2[ti][2 * tjj + 1], ah[ti], c1, c3);
                    }
                }
            }
        }

#pragma unroll
        for (int ti = 0; ti < 2; ti++) {
#pragma unroll
            for (int hh = 0; hh < 2; hh++) {
                int rloc = wm * 32 + ti * 16 + (lane >> 2) + hh * 8;
                float qg = (float)(q0 + rloc);
                float zs = 0.f, gs = 0.f;
#pragma unroll
                for (int tj = 0; tj < 4; tj++) {
                    int kcl = wn * 32 + tj * 8 + 2 * (lane & 3);
                    float kg = (float)(kt * 128 + kcl);
                    float s0 = acc2[ti][tj][2 * hh + 0] * 0.125f;
                    float s1 = acc2[ti][tj][2 * hh + 1] * 0.125f;
                    float p0 = __expf(s0), p1 = __expf(s1);
                    float d0 = qg - kg, d1 = qg - (kg + 1.0f);
                    float g0 = __expf(-d0 * d0 * (1.0f / 32768.0f));
                    float g1 = __expf(-d1 * d1 * (1.0f / 32768.0f));
                    float pg0 = p0 * g0, pg1 = p1 * g1;
                    zs += p0 + p1;
                    gs += pg0 + pg1;
                    __half2 ph2 = __floats2half2_rn(pg0, pg1);
                    int chunk = kcl >> 5;
                    int c32 = kcl & 31;
                    uint32_t off = (uint32_t)chunk * 4096 + rloc * 64
                                 + (((c32 >> 3) ^ ((rloc >> 1) & 3)) << 4) + (c32 & 7) * 2;
                    *(__half2*)(dsm + AF_SP + off) = ph2;
                }
                zacc[ti * 2 + hh] += zs;
                gacc[ti * 2 + hh] += gs;
            }
        }
        __syncthreads();

#pragma unroll
        for (int ch = 0; ch < 4; ch++) {
            uint32_t sAh = sbase + AF_SP + (uint32_t)ch * 4096;
            uint32_t sBh = sbase + AF_SV + (uint32_t)ch * 4096, sBl = sBh + 16384;
#pragma unroll
            for (int ks = 0; ks < 2; ks++) {
                uint32_t ph[2][4];
#pragma unroll
                for (int ti = 0; ti < 2; ti++) {
                    int r = wm * 32 + ti * 16 + (lane & 15);
                    int cc = 2 * ks + (lane >> 4);
                    uint32_t off = r * 64 + ((cc ^ ((r >> 1) & 3)) << 4);
                    ldsm4(ph[ti][0], ph[ti][1], ph[ti][2], ph[ti][3], sAh + off);
                }
                int r = wn * 16 + (lane & 15);
                int cc = 2 * ks + (lane >> 4);
                int fd = ((r >> 1) & 3) ^ ((r >> 3) & 3);
                uint32_t off = r * 64 + ((cc ^ fd) << 4);
                uint32_t b0, b1, b2, b3, c0, c1, c2, c3;
                ldsm4(b0, b1, b2, b3, sBh + off);
                ldsm4(c0, c1, c2, c3, sBl + off);
#pragma unroll
                for (int ti = 0; ti < 2; ti++) {
                    mma16816(accO[ti][0], ph[ti], b0, b2);
                    mma16816(accO[ti][1], ph[ti], b1, b3);
                    mma16816(accO[ti][0], ph[ti], c0, c2);
                    mma16816(accO[ti][1], ph[ti], c1, c3);
                }
            }
        }
    }

#pragma unroll
    for (int s = 0; s < 4; s++) {
        zacc[s] += __shfl_xor_sync(~0u, zacc[s], 1);
        zacc[s] += __shfl_xor_sync(~0u, zacc[s], 2);
        gacc[s] += __shfl_xor_sync(~0u, gacc[s], 1);
        gacc[s] += __shfl_xor_sync(~0u, gacc[s], 2);
    }
    if ((lane & 3) == 0) {
#pragma unroll
        for (int ti = 0; ti < 2; ti++)
#pragma unroll
            for (int hh = 0; hh < 2; hh++) {
                int rloc = wm * 32 + ti * 16 + (lane >> 2) + hh * 8;
                atomicAdd(&sZ[rloc], zacc[ti * 2 + hh]);
                atomicAdd(&sG[rloc], gacc[ti * 2 + hh]);
            }
    }
    __syncthreads();
    if (tid < QT) sInv[tid] = 1.0f / (sG[tid] + 1e-5f * sZ[tid]);
    __syncthreads();

#pragma unroll
    for (int ti = 0; ti < 2; ti++) {
#pragma unroll
        for (int tj = 0; tj < 2; tj++) {
            int dl = wn * 16 + tj * 8 + 2 * (lane & 3);
            int colg = h * Dn + dl;
#pragma unroll
            for (int hh = 0; hh < 2; hh++) {
                int rloc = wm * 32 + ti * 16 + (lane >> 2) + hh * 8;
                float inv = sInv[rloc];
                float v0 = accO[ti][tj][2 * hh + 0] * inv;
                float v1 = accO[ti][tj][2 * hh + 1] * inv;
                __half h0, l0, h1, l1;
                split_hl(v0, h0, l0);
                split_hl(v1, h1, l1);
                __half2 hv; hv.x = h0; hv.y = h1;
                __half2 lv; lv.x = l0; lv.y = l1;
                size_t o = (size_t)b * Tn * En + (size_t)(q0 + rloc) * En + colg;
                *(__half2*)(oh + o) = hv;
                *(__half2*)(ol + o) = lv;
            }
        }
    }
}

// ---------------- residual + LN ----------------
__global__ __launch_bounds__(256) void add_ln(
    float* __restrict__ x, const float* __restrict__ r,
    const float* __restrict__ g, const float* __restrict__ bt,
    __half* __restrict__ xh, __half* __restrict__ xl)
{
    const size_t base = (size_t)blockIdx.x * En;
    const int tid = threadIdx.x;
    float v[4];
    float s = 0.f, sq = 0.f;
#pragma unroll
    for (int i = 0; i < 4; i++) {
        int c = tid + i * 256;
        v[i] = x[base + c] + r[base + c];
        s += v[i];
        sq += v[i] * v[i];
    }
    float2 t = blockSum2(s, sq);
    float mu = t.x * (1.0f / En);
    float var = fmaxf(t.y * (1.0f / En) - mu * mu, 0.f);
    float rs = rsqrtf(var + 1e-5f);
#pragma unroll
    for (int i = 0; i < 4; i++) {
        int c = tid + i * 256;
        float o = (v[i] - mu) * rs * g[c] + bt[c];
        x[base + c] = o;
        split_hl(o, xh[base + c], xl[base + c]);
    }
}

__global__ __launch_bounds__(256) void head_kernel(
    const float* __restrict__ x, const float* __restrict__ hw,
    const float* __restrict__ hb, float* __restrict__ out)
{
    const int b = blockIdx.x;
    const int tid = threadIdx.x;
    const float* row = x + (size_t)b * Tn * En + (size_t)(Tn - 1) * En;
    float s = 0.f;
    for (int c = tid; c < En; c += 256) s += row[c] * hw[c];
    s = blockSum(s);
    if (tid == 0) out[b] = s + hb[0];
}

// ---------------- launch ----------------
extern "C" void kernel_launch(void* const* d_in, const int* in_sizes, int n_in,
                              void* d_out, int out_size)
{
    const float* src    = (const float*)d_in[0];
    const float* in_w   = (const float*)d_in[1];
    const float* in_b   = (const float*)d_in[2];
    const float* outp_w = (const float*)d_in[3];
    const float* outp_b = (const float*)d_in[4];
    const float* ff1_w  = (const float*)d_in[5];
    const float* ff1_b  = (const float*)d_in[6];
    const float* ff2_w  = (const float*)d_in[7];
    const float* ff2_b  = (const float*)d_in[8];
    const float* ln1_g  = (const float*)d_in[9];
    const float* ln1_b  = (const float*)d_in[10];
    const float* ln2_g  = (const float*)d_in[11];
    const float* ln2_b  = (const float*)d_in[12];
    const float* head_w = (const float*)d_in[13];
    const float* head_b = (const float*)d_in[14];
    float* out = (float*)d_out;

    static bool init = false;
    static float *x, *proj;
    static __half *xh,*xl,*ah,*al,*fh,*qkvh,*qkvl,*wih,*woh,*w1h,*w2h;
    if (!init) {
        cudaGetSymbolAddress((void**)&x, g_x);
        cudaGetSymbolAddress((void**)&proj, g_proj);
        cudaGetSymbolAddress((void**)&xh, g_xh); cudaGetSymbolAddress((void**)&xl, g_xl);
        cudaGetSymbolAddress((void**)&ah, g_ah); cudaGetSymbolAddress((void**)&al, g_al);
        cudaGetSymbolAddress((void**)&fh, g_fh);
        cudaGetSymbolAddress((void**)&qkvh, g_qkvh); cudaGetSymbolAddress((void**)&qkvl, g_qkvl);
        cudaGetSymbolAddress((void**)&wih, g_wih);
        cudaGetSymbolAddress((void**)&woh, g_woh);
        cudaGetSymbolAddress((void**)&w1h, g_w1h);
        cudaGetSymbolAddress((void**)&w2h, g_w2h);
        cudaFuncSetAttribute(gemm_mma<true>, cudaFuncAttributeMaxDynamicSharedMemorySize, 4 * STGB);
        cudaFuncSetAttribute(gemm_mma<false>, cudaFuncAttributeMaxDynamicSharedMemorySize, 4 * STGB);
        cudaFuncSetAttribute(attn_fused, cudaFuncAttributeMaxDynamicSharedMemorySize, AF_SMEM);
        init = true;
    }

    // weights -> fp16 hi
    convert_h4<<<Ln * 3 * En * En / 1024, 256>>>((const float4*)in_w, (__half2*)wih);
    convert_h4<<<Ln * En * En / 1024, 256>>>((const float4*)outp_w, (__half2*)woh);
    convert_h4<<<Ln * FFn * En / 1024, 256>>>((const float4*)ff1_w, (__half2*)w1h);
    convert_h4<<<Ln * En * FFn / 1024, 256>>>((const float4*)ff2_w, (__half2*)w2h);

    pe_add_kernel<<<Bn * Tn * En / 256, 256>>>(src, x, xh, xl);

    for (int l = 0; l < Ln; l++) {
        size_t wo3 = (size_t)l * 3 * En * En, wo1 = (size_t)l * En * En;
        size_t wof = (size_t)l * FFn * En;
        // qkv (2-term A, fp16 hi/lo out)
        gemm_mma<true><<<dim3(3 * En / BN, Bn * Tn / BM), 256, 4 * STGB>>>(
            xh, xl, wih + wo3, in_b + (size_t)l * 3 * En,
            nullptr, qkvh, qkvl, En, 3 * En, 0);
        // fused attention
        attn_fused<<<dim3(Tn / QT, Bn * Hn), 256, AF_SMEM>>>(qkvh, qkvl, ah, al);
        // out proj (2-term A)
        gemm_mma<true><<<dim3(En / BN, Bn * Tn / BM), 256, 4 * STGB>>>(
            ah, al, woh + wo1, outp_b + (size_t)l * En,
            proj, nullptr, nullptr, En, En, 0);
        add_ln<<<Bn * Tn, 256>>>(x, proj, ln1_g + (size_t)l * En, ln1_b + (size_t)l * En, xh, xl);
        // ff1 (2-term A, relu, hi-only out)
        gemm_mma<true><<<dim3(FFn / BN, Bn * Tn / BM), 256, 4 * STGB>>>(
            xh, xl, w1h + wof, ff1_b + (size_t)l * FFn,
            nullptr, fh, nullptr, En, FFn, 1);
        // ff2 (1-term A: hi only)
        gemm_mma<false><<<dim3(En / BN, Bn * Tn / BM), 256, 4 * STGB>>>(
            fh, nullptr, w2h + wof, ff2_b + (size_t)l * En,
            proj, nullptr, nullptr, FFn, En, 0);
        add_ln<<<Bn * Tn, 256>>>(x, proj, ln2_g + (size_t)l * En, ln2_b + (size_t)l * En, xh, xl);
    }

    head_kernel<<<Bn, 256>>>(x, head_w, head_b, out);
}

// round 14
// speedup vs baseline: 2.0915x; 1.1651x over previous
#include <cuda_runtime.h>
#include <cuda_fp16.h>
#include <math.h>
#include <stdint.h>

#define Bn  8
#define Tn  512
#define En  1024
#define Hn  16
#define Dn  64
#define Ln  4
#define FFn 4096

// fp32 scratch
__device__ float g_x[Bn * Tn * En];
__device__ float g_proj[Bn * Tn * En];
// fp16 activations
__device__ __half g_xh[Bn * Tn * En],  g_xl[Bn * Tn * En];
__device__ __half g_ah[Bn * Tn * En];
__device__ __half g_fh[Bn * Tn * FFn];
__device__ __half g_qkvh[Bn * Tn * 3 * En], g_qkvl[Bn * Tn * 3 * En];
// fp16 weight (hi only)
__device__ __half g_wih[Ln * 3 * En * En];
__device__ __half g_woh[Ln * En * En];
__device__ __half g_w1h[Ln * FFn * En];
__device__ __half g_w2h[Ln * En * FFn];

// ---------------- PTX helpers (sm_80+ only) ----------------
__device__ __forceinline__ uint32_t smem_u32(const void* p) {
    uint32_t a;
    asm("{ .reg .u64 t; cvta.to.shared.u64 t, %1; cvt.u32.u64 %0, t; }" : "=r"(a) : "l"(p));
    return a;
}
__device__ __forceinline__ void cpasync16(uint32_t dst, const void* src) {
    asm volatile("cp.async.cg.shared.global [%0], [%1], 16;" :: "r"(dst), "l"(src));
}
__device__ __forceinline__ void cp_commit() { asm volatile("cp.async.commit_group;" ::: "memory"); }
template <int N> __device__ __forceinline__ void cp_wait() {
    asm volatile("cp.async.wait_group %0;" :: "n"(N) : "memory");
}
__device__ __forceinline__ void ldsm4(uint32_t& r0, uint32_t& r1, uint32_t& r2,
                                      uint32_t& r3, uint32_t a) {
    asm volatile("ldmatrix.sync.aligned.m8n8.x4.shared.b16 {%0,%1,%2,%3}, [%4];"
                 : "=r"(r0), "=r"(r1), "=r"(r2), "=r"(r3) : "r"(a));
}
__device__ __forceinline__ void mma16816(float* d, const uint32_t* a, uint32_t b0, uint32_t b1) {
    asm volatile("mma.sync.aligned.m16n8k16.row.col.f32.f16.f16.f32 "
                 "{%0,%1,%2,%3}, {%4,%5,%6,%7}, {%8,%9}, {%0,%1,%2,%3};"
                 : "+f"(d[0]), "+f"(d[1]), "+f"(d[2]), "+f"(d[3])
                 : "r"(a[0]), "r"(a[1]), "r"(a[2]), "r"(a[3]), "r"(b0), "r"(b1));
}
__device__ __forceinline__ void split_hl(float v, __half& h, __half& l) {
    h = __float2half_rn(v);
    l = __float2half_rn(v - __half2float(h));
}

// ---------------- reductions ----------------
__device__ __forceinline__ float warpSum(float v) {
#pragma unroll
    for (int o = 16; o; o >>= 1) v += __shfl_xor_sync(~0u, v, o);
    return v;
}
__device__ __forceinline__ float blockSum(float v) {
    __shared__ float sm[8];
    int lane = threadIdx.x & 31, wid = threadIdx.x >> 5;
    v = warpSum(v);
    __syncthreads();
    if (lane == 0) sm[wid] = v;
    __syncthreads();
    v = sm[lane & 7];
#pragma unroll
    for (int o = 4; o; o >>= 1) v += __shfl_xor_sync(~0u, v, o);
    return v;
}
__device__ __forceinline__ float2 blockSum2(float a, float b) {
    __shared__ float2 sm[8];
    int lane = threadIdx.x & 31, wid = threadIdx.x >> 5;
#pragma unroll
    for (int o = 16; o; o >>= 1) {
        a += __shfl_xor_sync(~0u, a, o);
        b += __shfl_xor_sync(~0u, b, o);
    }
    __syncthreads();
    if (lane == 0) sm[wid] = make_float2(a, b);
    __syncthreads();
    float2 v = sm[lane & 7];
#pragma unroll
    for (int o = 4; o; o >>= 1) {
        v.x += __shfl_xor_sync(~0u, v.x, o);
        v.y += __shfl_xor_sync(~0u, v.y, o);
    }
    return v;
}

// ---------------- small kernels ----------------
__global__ void convert_h4(const float4* __restrict__ s, __half2* __restrict__ h) {
    int i = blockIdx.x * 256 + threadIdx.x;
    float4 v = s[i];
    h[2 * i]     = __floats2half2_rn(v.x, v.y);
    h[2 * i + 1] = __floats2half2_rn(v.z, v.w);
}

__global__ void pe_add_kernel(const float* __restrict__ src, float* __restrict__ x,
                              __half* __restrict__ xh, __half* __restrict__ xl) {
    int idx = blockIdx.x * 256 + threadIdx.x;
    int e = idx & (En - 1);
    int b = idx / (Tn * En);
    float dv = expf((float)(e & ~1) * (-9.210340371976184f / (float)En));
    float ang = (float)b * dv;
    float pe = (e & 1) ? cosf(ang) : sinf(ang);
    float v = src[idx] + pe;
    x[idx] = v;
    split_hl(v, xh[idx], xl[idx]);
}

// ---------------- fp16 GEMM: C = (Ah[+Al]) @ Bh^T + bias ----------------
#define BM 128
#define BN 128
#define BK 32
#define RGB 8192
#define STGB (3 * RGB)

template <bool TWOA>
__global__ __launch_bounds__(256, 2) void gemm_mma(
    const __half* __restrict__ Ah, const __half* __restrict__ Al,
    const __half* __restrict__ Bh,
    const float* __restrict__ bias, float* __restrict__ Cf,
    __half* __restrict__ Ch, __half* __restrict__ Cl,
    int K, int N, int relu)
{
    extern __shared__ __align__(128) uint8_t dsm[];
    __shared__ float sh_bias[BN];

    const int tid = threadIdx.x;
    const uint32_t sbase = smem_u32(dsm);
    if (tid < BN) sh_bias[tid] = bias[blockIdx.x * BN + tid];

    const int wid = tid >> 5, lane = tid & 31;
    const int wm = wid >> 1, wn = wid & 1;

    const __half* Abh = Ah + (size_t)blockIdx.y * BM * K;
    const __half* Abl = TWOA ? Al + (size_t)blockIdx.y * BM * K : nullptr;
    const __half* Bbh = Bh + (size_t)blockIdx.x * BN * K;

    const int cps = K / BK;

    auto load_chunk = [&](int c, int st) {
        int kc = c * BK;
        uint32_t sg = sbase + (uint32_t)st * STGB;
#pragma unroll
        for (int j = 0; j < 2; j++) {
            int idx = tid + j * 256;
            int r = idx >> 2, cc = idx & 3;
            uint32_t off = r * 64 + ((cc ^ ((r >> 1) & 3)) << 4);
            size_t go = (size_t)r * K + kc + cc * 8;
            cpasync16(sg + off, Abh + go);
            if (TWOA) cpasync16(sg + RGB + off, Abl + go);
            cpasync16(sg + 2 * RGB + off, Bbh + go);
        }
        cp_commit();
    };

    float acc[2][8][4] = {};
    load_chunk(0, 0);
    load_chunk(1, 1);
    load_chunk(2, 2);

    int st = 0;
    for (int c = 0; c < cps; c++) {
        int rem = cps - 1 - c;
        if (rem >= 2)      cp_wait<2>();
        else if (rem == 1) cp_wait<1>();
        else               cp_wait<0>();
        __syncthreads();
        if (c + 3 < cps) {
            int ns = st + 3; if (ns >= 4) ns -= 4;
            load_chunk(c + 3, ns);
        }

        uint32_t sAh = sbase + (uint32_t)st * STGB;
        uint32_t sAl = sAh + RGB;
        uint32_t sBh = sAh + 2 * RGB;
#pragma unroll
        for (int ks = 0; ks < 2; ks++) {
            uint32_t ah[2][4], al[2][4];
#pragma unroll
            for (int ti = 0; ti < 2; ti++) {
                int r = wm * 32 + ti * 16 + (lane & 15);
                int cc = 2 * ks + (lane >> 4);
                uint32_t off = r * 64 + ((cc ^ ((r >> 1) & 3)) << 4);
                ldsm4(ah[ti][0], ah[ti][1], ah[ti][2], ah[ti][3], sAh + off);
                if (TWOA) ldsm4(al[ti][0], al[ti][1], al[ti][2], al[ti][3], sAl + off);
            }
#pragma unroll
            for (int tj = 0; tj < 4; tj++) {
                int r = wn * 64 + tj * 16 + (lane & 15);
                int cc = 2 * ks + (lane >> 4);
                uint32_t off = r * 64 + ((cc ^ ((r >> 1) & 3)) << 4);
                uint32_t b0, b1, b2, b3;
                ldsm4(b0, b1, b2, b3, sBh + off);
                mma16816(acc[0][2 * tj],     ah[0], b0, b2);
                mma16816(acc[0][2 * tj + 1], ah[0], b1, b3);
                mma16816(acc[1][2 * tj],     ah[1], b0, b2);
                mma16816(acc[1][2 * tj + 1], ah[1], b1, b3);
                if (TWOA) {
                    mma16816(acc[0][2 * tj],     al[0], b0, b2);
                    mma16816(acc[0][2 * tj + 1], al[0], b1, b3);
                    mma16816(acc[1][2 * tj],     al[1], b0, b2);
                    mma16816(acc[1][2 * tj + 1], al[1], b1, b3);
                }
            }
        }
        if (++st == 4) st = 0;
    }

    const int col0 = wn * 64;
    const int row0 = blockIdx.y * BM + wm * 32;
#pragma unroll
    for (int ti = 0; ti < 2; ti++) {
#pragma unroll
        for (int tj = 0; tj < 8; tj++) {
            int cl = col0 + tj * 8 + 2 * (lane & 3);
            int colg = blockIdx.x * BN + cl;
            float b0 = sh_bias[cl], b1 = sh_bias[cl + 1];
#pragma unroll
            for (int hh = 0; hh < 2; hh++) {
                int row = row0 + ti * 16 + (lane >> 2) + hh * 8;
                float v0 = acc[ti][tj][2 * hh + 0] + b0;
                float v1 = acc[ti][tj][2 * hh + 1] + b1;
                if (relu) { v0 = fmaxf(v0, 0.f); v1 = fmaxf(v1, 0.f); }
                size_t o = (size_t)row * N + colg;
                if (Cf) *(float2*)(Cf + o) = make_float2(v0, v1);
                if (Ch) {
                    if (Cl) {
                        __half h0, l0, h1, l1;
                        split_hl(v0, h0, l0);
                        split_hl(v1, h1, l1);
                        __half2 hv; hv.x = h0; hv.y = h1;
                        __half2 lv; lv.x = l0; lv.y = l1;
                        *(__half2*)(Ch + o) = hv;
                        *(__half2*)(Cl + o) = lv;
                    } else {
                        *(__half2*)(Ch + o) = __floats2half2_rn(v0, v1);
                    }
                }
            }
        }
    }
}

// ---------------- fused attention v2: q-tile 64, 2 CTA/SM, hi-only O ----------------
#define QT 64
#define AF_SQ 0
#define AF_SK 16384
#define AF_SV 49152
#define AF_SP 81920
#define AF_SZ 98304
#define AF_SMEM (98304 + 768)

__global__ __launch_bounds__(256, 2) void attn_fused(
    const __half* __restrict__ qkvh, const __half* __restrict__ qkvl,
    __half* __restrict__ oh)
{
    extern __shared__ __align__(128) uint8_t dsm[];
    const int tid = threadIdx.x;
    const uint32_t sbase = smem_u32(dsm);
    const int wid = tid >> 5, lane = tid & 31;
    const int wm = wid >> 2, wn = wid & 3;
    const int bh = blockIdx.y, b = bh >> 4, h = bh & 15;
    const int q0 = blockIdx.x * QT;
    const int LDQ = 3 * En;

    float* sZ = (float*)(dsm + AF_SZ);
    float* sG = (float*)(dsm + AF_SZ + 256);
    float* sInv = (float*)(dsm + AF_SZ + 512);

    const __half* Qhb = qkvh + (size_t)b * Tn * LDQ + h * Dn + (size_t)q0 * LDQ;
    const __half* Qlb = qkvl + (size_t)b * Tn * LDQ + h * Dn + (size_t)q0 * LDQ;
    const __half* Khb = qkvh + (size_t)b * Tn * LDQ + En + h * Dn;
    const __half* Klb = qkvl + (size_t)b * Tn * LDQ + En + h * Dn;
    const __half* Vhb = qkvh + (size_t)b * Tn * LDQ + 2 * En + h * Dn;
    const __half* Vlb = qkvl + (size_t)b * Tn * LDQ + 2 * En + h * Dn;

    auto loadQ = [&]() {
#pragma unroll
        for (int j = 0; j < 2; j++) {
            int idx = tid + j * 256;
            int r = idx >> 3, gg = idx & 7;
            int chunk = gg >> 2, grp = gg & 3;
            uint32_t off = (uint32_t)chunk * 4096 + r * 64 + ((grp ^ ((r >> 1) & 3)) << 4);
            size_t go = (size_t)r * LDQ + gg * 8;
            cpasync16(sbase + AF_SQ + off, Qhb + go);
            cpasync16(sbase + AF_SQ + 8192 + off, Qlb + go);
        }
        cp_commit();
    };

    auto loadK = [&](int kt) {
#pragma unroll
        for (int j = 0; j < 4; j++) {
            int idx = tid + j * 256;
            int r = idx >> 3, gg = idx & 7;
            int chunk = gg >> 2, grp = gg & 3;
            uint32_t off = (uint32_t)chunk * 8192 + r * 64 + ((grp ^ ((r >> 1) & 3)) << 4);
            size_t go = (size_t)(kt * 128 + r) * LDQ + gg * 8;
            cpasync16(sbase + AF_SK + off, Khb + go);
            cpasync16(sbase + AF_SK + 16384 + off, Klb + go);
        }
        cp_commit();
    };

    auto loadV = [&](int kt) {
#pragma unroll
        for (int p = 0; p < 4; p++) {
            int kk = tid >> 3;
            int d0 = (tid & 7) * 8;
            size_t go = (size_t)(kt * 128 + p * 32 + kk) * LDQ + d0;
            uint4 hv = *(const uint4*)(Vhb + go);
            uint4 lv = *(const uint4*)(Vlb + go);
            uint32_t h4[4] = {hv.x, hv.y, hv.z, hv.w};
            uint32_t l4[4] = {lv.x, lv.y, lv.z, lv.w};
#pragma unroll
            for (int i = 0; i < 8; i++) {
                uint16_t hb16 = (uint16_t)(h4[i >> 1] >> ((i & 1) * 16));
                uint16_t lb16 = (uint16_t)(l4[i >> 1] >> ((i & 1) * 16));
                int d = d0 + i;
                int fd = ((d >> 1) & 3) ^ ((d >> 3) & 3);
                uint32_t off = (uint32_t)p * 4096 + d * 64 + (((kk >> 3) ^ fd) << 4) + (kk & 7) * 2;
                *(uint16_t*)(dsm + AF_SV + off) = hb16;
                *(uint16_t*)(dsm + AF_SV + 16384 + off) = lb16;
            }
        }
    };

    loadQ();
    if (tid < QT) { sZ[tid] = 0.f; sG[tid] = 0.f; }

    float accO[2][2][4] = {};
    float zacc[4] = {}, gacc[4] = {};

    for (int kt = 0; kt < 4; kt++) {
        __syncthreads();
        loadK(kt);
        loadV(kt);
        cp_wait<0>();
        __syncthreads();

        float acc2[2][4][4] = {};
#pragma unroll
        for (int c = 0; c < 2; c++) {
            uint32_t sAh = sbase + AF_SQ + (uint32_t)c * 4096, sAl = sAh + 8192;
            uint32_t sBh = sbase + AF_SK + (uint32_t)c * 8192, sBl = sBh + 16384;
#pragma unroll
            for (int ks = 0; ks < 2; ks++) {
                uint32_t ah[2][4], al[2][4];
#pragma unroll
                for (int ti = 0; ti < 2; ti++) {
                    int r = wm * 32 + ti * 16 + (lane & 15);
                    int cc = 2 * ks + (lane >> 4);
                    uint32_t off = r * 64 + ((cc ^ ((r >> 1) & 3)) << 4);
                    ldsm4(ah[ti][0], ah[ti][1], ah[ti][2], ah[ti][3], sAh + off);
                    ldsm4(al[ti][0], al[ti][1], al[ti][2], al[ti][3], sAl + off);
                }
#pragma unroll
                for (int tjj = 0; tjj < 2; tjj++) {
                    int r = wn * 32 + tjj * 16 + (lane & 15);
                    int cc = 2 * ks + (lane >> 4);
                    uint32_t off = r * 64 + ((cc ^ ((r >> 1) & 3)) << 4);
                    uint32_t b0, b1, b2, b3, c0, c1, c2, c3;
                    ldsm4(b0, b1, b2, b3, sBh + off);
                    ldsm4(c0, c1, c2, c3, sBl + off);
#pragma unroll
                    for (int ti = 0; ti < 2; ti++) {
                        mma16816(acc2[ti][2 * tjj],     ah[ti], b0, b2);
                        mma16816(acc2[ti][2 * tjj + 1], ah[ti], b1, b3);
                        mma16816(acc2[ti][2 * tjj],     al[ti], b0, b2);
                        mma16816(acc2[ti][2 * tjj + 1], al[ti], b1, b3);
                        mma16816(acc2[ti][2 * tjj],     ah[ti], c0, c2);
                        mma16816(acc2[ti][2 * tjj + 1], ah[ti], c1, c3);
                    }
                }
            }
        }

#pragma unroll
        for (int ti = 0; ti < 2; ti++) {
#pragma unroll
            for (int hh = 0; hh < 2; hh++) {
                int rloc = wm * 32 + ti * 16 + (lane >> 2) + hh * 8;
                float qg = (float)(q0 + rloc);
                float zs = 0.f, gs = 0.f;
#pragma unroll
                for (int tj = 0; tj < 4; tj++) {
                    int kcl = wn * 32 + tj * 8 + 2 * (lane & 3);
                    float kg = (float)(kt * 128 + kcl);
                    float s0 = acc2[ti][tj][2 * hh + 0] * 0.125f;
                    float s1 = acc2[ti][tj][2 * hh + 1] * 0.125f;
                    float p0 = __expf(s0), p1 = __expf(s1);
                    float d0 = qg - kg, d1 = qg - (kg + 1.0f);
                    float g0 = __expf(-d0 * d0 * (1.0f / 32768.0f));
                    float g1 = __expf(-d1 * d1 * (1.0f / 32768.0f));
                    float pg0 = p0 * g0, pg1 = p1 * g1;
                    zs += p0 + p1;
                    gs += pg0 + pg1;
                    __half2 ph2 = __floats2half2_rn(pg0, pg1);
                    int chunk = kcl >> 5;
                    int c32 = kcl & 31;
                    uint32_t off = (uint32_t)chunk * 4096 + rloc * 64
                                 + (((c32 >> 3) ^ ((rloc >> 1) & 3)) << 4) + (c32 & 7) * 2;
                    *(__half2*)(dsm + AF_SP + off) = ph2;
                }
                zacc[ti * 2 + hh] += zs;
                gacc[ti * 2 + hh] += gs;
            }
        }
        __syncthreads();

#pragma unroll
        for (int ch = 0; ch < 4; ch++) {
            uint32_t sAh = sbase + AF_SP + (uint32_t)ch * 4096;
            uint32_t sBh = sbase + AF_SV + (uint32_t)ch * 4096, sBl = sBh + 16384;
#pragma unroll
            for (int ks = 0; ks < 2; ks++) {
                uint32_t ph[2][4];
#pragma unroll
                for (int ti = 0; ti < 2; ti++) {
                    int r = wm * 32 + ti * 16 + (lane & 15);
                    int cc = 2 * ks + (lane >> 4);
                    uint32_t off = r * 64 + ((cc ^ ((r >> 1) & 3)) << 4);
                    ldsm4(ph[ti][0], ph[ti][1], ph[ti][2], ph[ti][3], sAh + off);
                }
                int r = wn * 16 + (lane & 15);
                int cc = 2 * ks + (lane >> 4);
                int fd = ((r >> 1) & 3) ^ ((r >> 3) & 3);
                uint32_t off = r * 64 + ((cc ^ fd) << 4);
                uint32_t b0, b1, b2, b3, c0, c1, c2, c3;
                ldsm4(b0, b1, b2, b3, sBh + off);
                ldsm4(c0, c1, c2, c3, sBl + off);
#pragma unroll
                for (int ti = 0; ti < 2; ti++) {
                    mma16816(accO[ti][0], ph[ti], b0, b2);
                    mma16816(accO[ti][1], ph[ti], b1, b3);
                    mma16816(accO[ti][0], ph[ti], c0, c2);
                    mma16816(accO[ti][1], ph[ti], c1, c3);
                }
            }
        }
    }

#pragma unroll
    for (int s = 0; s < 4; s++) {
        zacc[s] += __shfl_xor_sync(~0u, zacc[s], 1);
        zacc[s] += __shfl_xor_sync(~0u, zacc[s], 2);
        gacc[s] += __shfl_xor_sync(~0u, gacc[s], 1);
        gacc[s] += __shfl_xor_sync(~0u, gacc[s], 2);
    }
    if ((lane & 3) == 0) {
#pragma unroll
        for (int ti = 0; ti < 2; ti++)
#pragma unroll
            for (int hh = 0; hh < 2; hh++) {
                int rloc = wm * 32 + ti * 16 + (lane >> 2) + hh * 8;
                atomicAdd(&sZ[rloc], zacc[ti * 2 + hh]);
                atomicAdd(&sG[rloc], gacc[ti * 2 + hh]);
            }
    }
    __syncthreads();
    if (tid < QT) sInv[tid] = 1.0f / (sG[tid] + 1e-5f * sZ[tid]);
    __syncthreads();

#pragma unroll
    for (int ti = 0; ti < 2; ti++) {
#pragma unroll
        for (int tj = 0; tj < 2; tj++) {
            int dl = wn * 16 + tj * 8 + 2 * (lane & 3);
            int colg = h * Dn + dl;
#pragma unroll
            for (int hh = 0; hh < 2; hh++) {
                int rloc = wm * 32 + ti * 16 + (lane >> 2) + hh * 8;
                float inv = sInv[rloc];
                float v0 = accO[ti][tj][2 * hh + 0] * inv;
                float v1 = accO[ti][tj][2 * hh + 1] * inv;
                size_t o = (size_t)b * Tn * En + (size_t)(q0 + rloc) * En + colg;
                *(__half2*)(oh + o) = __floats2half2_rn(v0, v1);
            }
        }
    }
}

// ---------------- residual + LN ----------------
__global__ __launch_bounds__(256) void add_ln(
    float* __restrict__ x, const float* __restrict__ r,
    const float* __restrict__ g, const float* __restrict__ bt,
    __half* __restrict__ xh, __half* __restrict__ xl)
{
    const size_t base = (size_t)blockIdx.x * En;
    const int tid = threadIdx.x;
    float v[4];
    float s = 0.f, sq = 0.f;
#pragma unroll
    for (int i = 0; i < 4; i++) {
        int c = tid + i * 256;
        v[i] = x[base + c] + r[base + c];
        s += v[i];
        sq += v[i] * v[i];
    }
    float2 t = blockSum2(s, sq);
    float mu = t.x * (1.0f / En);
    float var = fmaxf(t.y * (1.0f / En) - mu * mu, 0.f);
    float rs = rsqrtf(var + 1e-5f);
#pragma unroll
    for (int i = 0; i < 4; i++) {
        int c = tid + i * 256;
        float o = (v[i] - mu) * rs * g[c] + bt[c];
        x[base + c] = o;
        if (xl) {
            split_hl(o, xh[base + c], xl[base + c]);
        } else {
            xh[base + c] = __float2half_rn(o);
        }
    }
}

__global__ __launch_bounds__(256) void head_kernel(
    const float* __restrict__ x, const float* __restrict__ hw,
    const float* __restrict__ hb, float* __restrict__ out)
{
    const int b = blockIdx.x;
    const int tid = threadIdx.x;
    const float* row = x + (size_t)b * Tn * En + (size_t)(Tn - 1) * En;
    float s = 0.f;
    for (int c = tid; c < En; c += 256) s += row[c] * hw[c];
    s = blockSum(s);
    if (tid == 0) out[b] = s + hb[0];
}

// ---------------- launch ----------------
extern "C" void kernel_launch(void* const* d_in, const int* in_sizes, int n_in,
                              void* d_out, int out_size)
{
    const float* src    = (const float*)d_in[0];
    const float* in_w   = (const float*)d_in[1];
    const float* in_b   = (const float*)d_in[2];
    const float* outp_w = (const float*)d_in[3];
    const float* outp_b = (const float*)d_in[4];
    const float* ff1_w  = (const float*)d_in[5];
    const float* ff1_b  = (const float*)d_in[6];
    const float* ff2_w  = (const float*)d_in[7];
    const float* ff2_b  = (const float*)d_in[8];
    const float* ln1_g  = (const float*)d_in[9];
    const float* ln1_b  = (const float*)d_in[10];
    const float* ln2_g  = (const float*)d_in[11];
    const float* ln2_b  = (const float*)d_in[12];
    const float* head_w = (const float*)d_in[13];
    const float* head_b = (const float*)d_in[14];
    float* out = (float*)d_out;

    static bool init = false;
    static float *x, *proj;
    static __half *xh,*xl,*ah,*fh,*qkvh,*qkvl,*wih,*woh,*w1h,*w2h;
    if (!init) {
        cudaGetSymbolAddress((void**)&x, g_x);
        cudaGetSymbolAddress((void**)&proj, g_proj);
        cudaGetSymbolAddress((void**)&xh, g_xh); cudaGetSymbolAddress((void**)&xl, g_xl);
        cudaGetSymbolAddress((void**)&ah, g_ah);
        cudaGetSymbolAddress((void**)&fh, g_fh);
        cudaGetSymbolAddress((void**)&qkvh, g_qkvh); cudaGetSymbolAddress((void**)&qkvl, g_qkvl);
        cudaGetSymbolAddress((void**)&wih, g_wih);
        cudaGetSymbolAddress((void**)&woh, g_woh);
        cudaGetSymbolAddress((void**)&w1h, g_w1h);
        cudaGetSymbolAddress((void**)&w2h, g_w2h);
        cudaFuncSetAttribute(gemm_mma<true>, cudaFuncAttributeMaxDynamicSharedMemorySize, 4 * STGB);
        cudaFuncSetAttribute(gemm_mma<false>, cudaFuncAttributeMaxDynamicSharedMemorySize, 4 * STGB);
        cudaFuncSetAttribute(attn_fused, cudaFuncAttributeMaxDynamicSharedMemorySize, AF_SMEM);
        init = true;
    }

    // weights -> fp16 hi
    convert_h4<<<Ln * 3 * En * En / 1024, 256>>>((const float4*)in_w, (__half2*)wih);
    convert_h4<<<Ln * En * En / 1024, 256>>>((const float4*)outp_w, (__half2*)woh);
    convert_h4<<<Ln * FFn * En / 1024, 256>>>((const float4*)ff1_w, (__half2*)w1h);
    convert_h4<<<Ln * En * FFn / 1024, 256>>>((const float4*)ff2_w, (__half2*)w2h);

    pe_add_kernel<<<Bn * Tn * En / 256, 256>>>(src, x, xh, xl);

    for (int l = 0; l < Ln; l++) {
        size_t wo3 = (size_t)l * 3 * En * En, wo1 = (size_t)l * En * En;
        size_t wof = (size_t)l * FFn * En;
        // qkv (2-term A, fp16 hi/lo out)
        gemm_mma<true><<<dim3(3 * En / BN, Bn * Tn / BM), 256, 4 * STGB>>>(
            xh, xl, wih + wo3, in_b + (size_t)l * 3 * En,
            nullptr, qkvh, qkvl, En, 3 * En, 0);
        // fused attention (hi-only O)
        attn_fused<<<dim3(Tn / QT, Bn * Hn), 256, AF_SMEM>>>(qkvh, qkvl, ah);
        // out proj (1-term A)
        gemm_mma<false><<<dim3(En / BN, Bn * Tn / BM), 256, 4 * STGB>>>(
            ah, nullptr, woh + wo1, outp_b + (size_t)l * En,
            proj, nullptr, nullptr, En, En, 0);
        add_ln<<<Bn * Tn, 256>>>(x, proj, ln1_g + (size_t)l * En, ln1_b + (size_t)l * En, xh, xl);
        // ff1 (1-term A, relu, hi-only out)
        gemm_mma<false><<<dim3(FFn / BN, Bn * Tn / BM), 256, 4 * STGB>>>(
            xh, nullptr, w1h + wof, ff1_b + (size_t)l * FFn,
            nullptr, fh, nullptr, En, FFn, 1);
        // ff2 (1-term A)
        gemm_mma<false><<<dim3(En / BN, Bn * Tn / BM), 256, 4 * STGB>>>(
            fh, nullptr, w2h + wof, ff2_b + (size_t)l * En,
            proj, nullptr, nullptr, FFn, En, 0);
        add_ln<<<Bn * Tn, 256>>>(x, proj, ln2_g + (size_t)l * En, ln2_b + (size_t)l * En, xh, xl);
    }

    head_kernel<<<Bn, 256>>>(x, head_w, head_b, out);
}

// round 15
// speedup vs baseline: 2.1075x; 1.0076x over previous
#include <cuda_runtime.h>
#include <cuda_fp16.h>
#include <math.h>
#include <stdint.h>

#define Bn  8
#define Tn  512
#define En  1024
#define Hn  16
#define Dn  64
#define Ln  4
#define FFn 4096

// fp32 scratch
__device__ float g_x[Bn * Tn * En];
__device__ float g_proj[Bn * Tn * En];
// fp16 activations
__device__ __half g_xh[Bn * Tn * En],  g_xl[Bn * Tn * En];
__device__ __half g_ah[Bn * Tn * En];
__device__ __half g_fh[Bn * Tn * FFn];
__device__ __half g_qkvh[Bn * Tn * 3 * En], g_qkvl[Bn * Tn * 3 * En];
// fp16 weight (hi only)
__device__ __half g_wih[Ln * 3 * En * En];
__device__ __half g_woh[Ln * En * En];
__device__ __half g_w1h[Ln * FFn * En];
__device__ __half g_w2h[Ln * En * FFn];

// ---------------- PTX helpers (sm_80+ only) ----------------
__device__ __forceinline__ uint32_t smem_u32(const void* p) {
    uint32_t a;
    asm("{ .reg .u64 t; cvta.to.shared.u64 t, %1; cvt.u32.u64 %0, t; }" : "=r"(a) : "l"(p));
    return a;
}
__device__ __forceinline__ void cpasync16(uint32_t dst, const void* src) {
    asm volatile("cp.async.cg.shared.global [%0], [%1], 16;" :: "r"(dst), "l"(src));
}
__device__ __forceinline__ void cp_commit() { asm volatile("cp.async.commit_group;" ::: "memory"); }
template <int N> __device__ __forceinline__ void cp_wait() {
    asm volatile("cp.async.wait_group %0;" :: "n"(N) : "memory");
}
__device__ __forceinline__ void ldsm4(uint32_t& r0, uint32_t& r1, uint32_t& r2,
                                      uint32_t& r3, uint32_t a) {
    asm volatile("ldmatrix.sync.aligned.m8n8.x4.shared.b16 {%0,%1,%2,%3}, [%4];"
                 : "=r"(r0), "=r"(r1), "=r"(r2), "=r"(r3) : "r"(a));
}
__device__ __forceinline__ void mma16816(float* d, const uint32_t* a, uint32_t b0, uint32_t b1) {
    asm volatile("mma.sync.aligned.m16n8k16.row.col.f32.f16.f16.f32 "
                 "{%0,%1,%2,%3}, {%4,%5,%6,%7}, {%8,%9}, {%0,%1,%2,%3};"
                 : "+f"(d[0]), "+f"(d[1]), "+f"(d[2]), "+f"(d[3])
                 : "r"(a[0]), "r"(a[1]), "r"(a[2]), "r"(a[3]), "r"(b0), "r"(b1));
}
__device__ __forceinline__ void split_hl(float v, __half& h, __half& l) {
    h = __float2half_rn(v);
    l = __float2half_rn(v - __half2float(h));
}

// ---------------- reductions ----------------
__device__ __forceinline__ float warpSum(float v) {
#pragma unroll
    for (int o = 16; o; o >>= 1) v += __shfl_xor_sync(~0u, v, o);
    return v;
}
__device__ __forceinline__ float blockSum(float v) {
    __shared__ float sm[8];
    int lane = threadIdx.x & 31, wid = threadIdx.x >> 5;
    v = warpSum(v);
    __syncthreads();
    if (lane == 0) sm[wid] = v;
    __syncthreads();
    v = sm[lane & 7];
#pragma unroll
    for (int o = 4; o; o >>= 1) v += __shfl_xor_sync(~0u, v, o);
    return v;
}
__device__ __forceinline__ float2 blockSum2(float a, float b) {
    __shared__ float2 sm[8];
    int lane = threadIdx.x & 31, wid = threadIdx.x >> 5;
#pragma unroll
    for (int o = 16; o; o >>= 1) {
        a += __shfl_xor_sync(~0u, a, o);
        b += __shfl_xor_sync(~0u, b, o);
    }
    __syncthreads();
    if (lane == 0) sm[wid] = make_float2(a, b);
    __syncthreads();
    float2 v = sm[lane & 7];
#pragma unroll
    for (int o = 4; o; o >>= 1) {
        v.x += __shfl_xor_sync(~0u, v.x, o);
        v.y += __shfl_xor_sync(~0u, v.y, o);
    }
    return v;
}

// ---------------- small kernels ----------------
__global__ void convert_h4(const float4* __restrict__ s, __half2* __restrict__ h) {
    int i = blockIdx.x * 256 + threadIdx.x;
    float4 v = s[i];
    h[2 * i]     = __floats2half2_rn(v.x, v.y);
    h[2 * i + 1] = __floats2half2_rn(v.z, v.w);
}

__global__ void pe_add_kernel(const float* __restrict__ src, float* __restrict__ x,
                              __half* __restrict__ xh, __half* __restrict__ xl) {
    int idx = blockIdx.x * 256 + threadIdx.x;
    int e = idx & (En - 1);
    int b = idx / (Tn * En);
    float dv = expf((float)(e & ~1) * (-9.210340371976184f / (float)En));
    float ang = (float)b * dv;
    float pe = (e & 1) ? cosf(ang) : sinf(ang);
    float v = src[idx] + pe;
    x[idx] = v;
    split_hl(v, xh[idx], xl[idx]);
}

// ---------------- fp16 GEMM: C = (Ah[+Al]) @ Bh^T + bias ----------------
// Mainloop v2: fragment loads batched ahead of MMAs (breaks LDSM->MMA chains).
#define BM 128
#define BN 128
#define BK 32
#define RGB 8192
#define STGB (3 * RGB)

template <bool TWOA>
__global__ __launch_bounds__(256, 2) void gemm_mma(
    const __half* __restrict__ Ah, const __half* __restrict__ Al,
    const __half* __restrict__ Bh,
    const float* __restrict__ bias, float* __restrict__ Cf,
    __half* __restrict__ Ch, __half* __restrict__ Cl,
    int K, int N, int relu)
{
    extern __shared__ __align__(128) uint8_t dsm[];
    __shared__ float sh_bias[BN];

    const int tid = threadIdx.x;
    const uint32_t sbase = smem_u32(dsm);
    if (tid < BN) sh_bias[tid] = bias[blockIdx.x * BN + tid];

    const int wid = tid >> 5, lane = tid & 31;
    const int wm = wid >> 1, wn = wid & 1;

    const __half* Abh = Ah + (size_t)blockIdx.y * BM * K;
    const __half* Abl = TWOA ? Al + (size_t)blockIdx.y * BM * K : nullptr;
    const __half* Bbh = Bh + (size_t)blockIdx.x * BN * K;

    const int cps = K / BK;

    auto load_chunk = [&](int c, int st) {
        int kc = c * BK;
        uint32_t sg = sbase + (uint32_t)st * STGB;
#pragma unroll
        for (int j = 0; j < 2; j++) {
            int idx = tid + j * 256;
            int r = idx >> 2, cc = idx & 3;
            uint32_t off = r * 64 + ((cc ^ ((r >> 1) & 3)) << 4);
            size_t go = (size_t)r * K + kc + cc * 8;
            cpasync16(sg + off, Abh + go);
            if (TWOA) cpasync16(sg + RGB + off, Abl + go);
            cpasync16(sg + 2 * RGB + off, Bbh + go);
        }
        cp_commit();
    };

    float acc[2][8][4] = {};
    load_chunk(0, 0);
    load_chunk(1, 1);
    load_chunk(2, 2);

    int st = 0;
    for (int c = 0; c < cps; c++) {
        int rem = cps - 1 - c;
        if (rem >= 2)      cp_wait<2>();
        else if (rem == 1) cp_wait<1>();
        else               cp_wait<0>();
        __syncthreads();
        if (c + 3 < cps) {
            int ns = st + 3; if (ns >= 4) ns -= 4;
            load_chunk(c + 3, ns);
        }

        uint32_t sAh = sbase + (uint32_t)st * STGB;
        uint32_t sAl = sAh + RGB;
        uint32_t sBh = sAh + 2 * RGB;
#pragma unroll
        for (int ks = 0; ks < 2; ks++) {
            // --- batch A fragment loads ---
            uint32_t ah[2][4], al[2][4];
#pragma unroll
            for (int ti = 0; ti < 2; ti++) {
                int r = wm * 32 + ti * 16 + (lane & 15);
                int cc = 2 * ks + (lane >> 4);
                uint32_t off = r * 64 + ((cc ^ ((r >> 1) & 3)) << 4);
                ldsm4(ah[ti][0], ah[ti][1], ah[ti][2], ah[ti][3], sAh + off);
                if (TWOA) ldsm4(al[ti][0], al[ti][1], al[ti][2], al[ti][3], sAl + off);
            }
            if (TWOA) {
                // B in pairs (register-pressure safe): 2 ldsm, then 16 MMAs
#pragma unroll
                for (int tp = 0; tp < 2; tp++) {
                    uint32_t bf[2][4];
#pragma unroll
                    for (int q = 0; q < 2; q++) {
                        int tj = tp * 2 + q;
                        int r = wn * 64 + tj * 16 + (lane & 15);
                        int cc = 2 * ks + (lane >> 4);
                        uint32_t off = r * 64 + ((cc ^ ((r >> 1) & 3)) << 4);
                        ldsm4(bf[q][0], bf[q][1], bf[q][2], bf[q][3], sBh + off);
                    }
#pragma unroll
                    for (int q = 0; q < 2; q++) {
                        int tj = tp * 2 + q;
                        mma16816(acc[0][2 * tj],     ah[0], bf[q][0], bf[q][2]);
                        mma16816(acc[0][2 * tj + 1], ah[0], bf[q][1], bf[q][3]);
                        mma16816(acc[1][2 * tj],     ah[1], bf[q][0], bf[q][2]);
                        mma16816(acc[1][2 * tj + 1], ah[1], bf[q][1], bf[q][3]);
                        mma16816(acc[0][2 * tj],     al[0], bf[q][0], bf[q][2]);
                        mma16816(acc[0][2 * tj + 1], al[0], bf[q][1], bf[q][3]);
                        mma16816(acc[1][2 * tj],     al[1], bf[q][0], bf[q][2]);
                        mma16816(acc[1][2 * tj + 1], al[1], bf[q][1], bf[q][3]);
                    }
                }
            } else {
                // 1-term: batch all 4 B ldsm, then all 16 MMAs
                uint32_t bf[4][4];
#pragma unroll
                for (int tj = 0; tj < 4; tj++) {
                    int r = wn * 64 + tj * 16 + (lane & 15);
                    int cc = 2 * ks + (lane >> 4);
                    uint32_t off = r * 64 + ((cc ^ ((r >> 1) & 3)) << 4);
                    ldsm4(bf[tj][0], bf[tj][1], bf[tj][2], bf[tj][3], sBh + off);
                }
#pragma unroll
                for (int tj = 0; tj < 4; tj++) {
                    mma16816(acc[0][2 * tj],     ah[0], bf[tj][0], bf[tj][2]);
                    mma16816(acc[0][2 * tj + 1], ah[0], bf[tj][1], bf[tj][3]);
                    mma16816(acc[1][2 * tj],     ah[1], bf[tj][0], bf[tj][2]);
                    mma16816(acc[1][2 * tj + 1], ah[1], bf[tj][1], bf[tj][3]);
                }
            }
        }
        if (++st == 4) st = 0;
    }

    const int col0 = wn * 64;
    const int row0 = blockIdx.y * BM + wm * 32;
#pragma unroll
    for (int ti = 0; ti < 2; ti++) {
#pragma unroll
        for (int tj = 0; tj < 8; tj++) {
            int cl = col0 + tj * 8 + 2 * (lane & 3);
            int colg = blockIdx.x * BN + cl;
            float b0 = sh_bias[cl], b1 = sh_bias[cl + 1];
#pragma unroll
            for (int hh = 0; hh < 2; hh++) {
                int row = row0 + ti * 16 + (lane >> 2) + hh * 8;
                float v0 = acc[ti][tj][2 * hh + 0] + b0;
                float v1 = acc[ti][tj][2 * hh + 1] + b1;
                if (relu) { v0 = fmaxf(v0, 0.f); v1 = fmaxf(v1, 0.f); }
                size_t o = (size_t)row * N + colg;
                if (Cf) *(float2*)(Cf + o) = make_float2(v0, v1);
                if (Ch) {
                    if (Cl) {
                        __half h0, l0, h1, l1;
                        split_hl(v0, h0, l0);
                        split_hl(v1, h1, l1);
                        __half2 hv; hv.x = h0; hv.y = h1;
                        __half2 lv; lv.x = l0; lv.y = l1;
                        *(__half2*)(Ch + o) = hv;
                        *(__half2*)(Cl + o) = lv;
                    } else {
                        *(__half2*)(Ch + o) = __floats2half2_rn(v0, v1);
                    }
                }
            }
        }
    }
}

// ---------------- fused attention v2: q-tile 64, 2 CTA/SM, hi-only O ----------------
#define QT 64
#define AF_SQ 0
#define AF_SK 16384
#define AF_SV 49152
#define AF_SP 81920
#define AF_SZ 98304
#define AF_SMEM (98304 + 768)

__global__ __launch_bounds__(256, 2) void attn_fused(
    const __half* __restrict__ qkvh, const __half* __restrict__ qkvl,
    __half* __restrict__ oh)
{
    extern __shared__ __align__(128) uint8_t dsm[];
    const int tid = threadIdx.x;
    const uint32_t sbase = smem_u32(dsm);
    const int wid = tid >> 5, lane = tid & 31;
    const int wm = wid >> 2, wn = wid & 3;
    const int bh = blockIdx.y, b = bh >> 4, h = bh & 15;
    const int q0 = blockIdx.x * QT;
    const int LDQ = 3 * En;

    float* sZ = (float*)(dsm + AF_SZ);
    float* sG = (float*)(dsm + AF_SZ + 256);
    float* sInv = (float*)(dsm + AF_SZ + 512);

    const __half* Qhb = qkvh + (size_t)b * Tn * LDQ + h * Dn + (size_t)q0 * LDQ;
    const __half* Qlb = qkvl + (size_t)b * Tn * LDQ + h * Dn + (size_t)q0 * LDQ;
    const __half* Khb = qkvh + (size_t)b * Tn * LDQ + En + h * Dn;
    const __half* Klb = qkvl + (size_t)b * Tn * LDQ + En + h * Dn;
    const __half* Vhb = qkvh + (size_t)b * Tn * LDQ + 2 * En + h * Dn;
    const __half* Vlb = qkvl + (size_t)b * Tn * LDQ + 2 * En + h * Dn;

    auto loadQ = [&]() {
#pragma unroll
        for (int j = 0; j < 2; j++) {
            int idx = tid + j * 256;
            int r = idx >> 3, gg = idx & 7;
            int chunk = gg >> 2, grp = gg & 3;
            uint32_t off = (uint32_t)chunk * 4096 + r * 64 + ((grp ^ ((r >> 1) & 3)) << 4);
            size_t go = (size_t)r * LDQ + gg * 8;
            cpasync16(sbase + AF_SQ + off, Qhb + go);
            cpasync16(sbase + AF_SQ + 8192 + off, Qlb + go);
        }
        cp_commit();
    };

    auto loadK = [&](int kt) {
#pragma unroll
        for (int j = 0; j < 4; j++) {
            int idx = tid + j * 256;
            int r = idx >> 3, gg = idx & 7;
            int chunk = gg >> 2, grp = gg & 3;
            uint32_t off = (uint32_t)chunk * 8192 + r * 64 + ((grp ^ ((r >> 1) & 3)) << 4);
            size_t go = (size_t)(kt * 128 + r) * LDQ + gg * 8;
            cpasync16(sbase + AF_SK + off, Khb + go);
            cpasync16(sbase + AF_SK + 16384 + off, Klb + go);
        }
        cp_commit();
    };

    auto loadV = [&](int kt) {
#pragma unroll
        for (int p = 0; p < 4; p++) {
            int kk = tid >> 3;
            int d0 = (tid & 7) * 8;
            size_t go = (size_t)(kt * 128 + p * 32 + kk) * LDQ + d0;
            uint4 hv = *(const uint4*)(Vhb + go);
            uint4 lv = *(const uint4*)(Vlb + go);
            uint32_t h4[4] = {hv.x, hv.y, hv.z, hv.w};
            uint32_t l4[4] = {lv.x, lv.y, lv.z, lv.w};
#pragma unroll
            for (int i = 0; i < 8; i++) {
                uint16_t hb16 = (uint16_t)(h4[i >> 1] >> ((i & 1) * 16));
                uint16_t lb16 = (uint16_t)(l4[i >> 1] >> ((i & 1) * 16));
                int d = d0 + i;
                int fd = ((d >> 1) & 3) ^ ((d >> 3) & 3);
                uint32_t off = (uint32_t)p * 4096 + d * 64 + (((kk >> 3) ^ fd) << 4) + (kk & 7) * 2;
                *(uint16_t*)(dsm + AF_SV + off) = hb16;
                *(uint16_t*)(dsm + AF_SV + 16384 + off) = lb16;
            }
        }
    };

    loadQ();
    if (tid < QT) { sZ[tid] = 0.f; sG[tid] = 0.f; }

    float accO[2][2][4] = {};
    float zacc[4] = {}, gacc[4] = {};

    for (int kt = 0; kt < 4; kt++) {
        __syncthreads();
        loadK(kt);
        loadV(kt);
        cp_wait<0>();
        __syncthreads();

        float acc2[2][4][4] = {};
#pragma unroll
        for (int c = 0; c < 2; c++) {
            uint32_t sAh = sbase + AF_SQ + (uint32_t)c * 4096, sAl = sAh + 8192;
            uint32_t sBh = sbase + AF_SK + (uint32_t)c * 8192, sBl = sBh + 16384;
#pragma unroll
            for (int ks = 0; ks < 2; ks++) {
                uint32_t ah[2][4], al[2][4];
#pragma unroll
                for (int ti = 0; ti < 2; ti++) {
                    int r = wm * 32 + ti * 16 + (lane & 15);
                    int cc = 2 * ks + (lane >> 4);
                    uint32_t off = r * 64 + ((cc ^ ((r >> 1) & 3)) << 4);
                    ldsm4(ah[ti][0], ah[ti][1], ah[ti][2], ah[ti][3], sAh + off);
                    ldsm4(al[ti][0], al[ti][1], al[ti][2], al[ti][3], sAl + off);
                }
#pragma unroll
                for (int tjj = 0; tjj < 2; tjj++) {
                    int r = wn * 32 + tjj * 16 + (lane & 15);
                    int cc = 2 * ks + (lane >> 4);
                    uint32_t off = r * 64 + ((cc ^ ((r >> 1) & 3)) << 4);
                    uint32_t b0, b1, b2, b3, c0, c1, c2, c3;
                    ldsm4(b0, b1, b2, b3, sBh + off);
                    ldsm4(c0, c1, c2, c3, sBl + off);
#pragma unroll
                    for (int ti = 0; ti < 2; ti++) {
                        mma16816(acc2[ti][2 * tjj],     ah[ti], b0, b2);
                        mma16816(acc2[ti][2 * tjj + 1], ah[ti], b1, b3);
                        mma16816(acc2[ti][2 * tjj],     al[ti], b0, b2);
                        mma16816(acc2[ti][2 * tjj + 1], al[ti], b1, b3);
                        mma16816(acc2[ti][2 * tjj],     ah[ti], c0, c2);
                        mma16816(acc2[ti][2 * tjj + 1], ah[ti], c1, c3);
                    }
                }
            }
        }

#pragma unroll
        for (int ti = 0; ti < 2; ti++) {
#pragma unroll
            for (int hh = 0; hh < 2; hh++) {
                int rloc = wm * 32 + ti * 16 + (lane >> 2) + hh * 8;
                float qg = (float)(q0 + rloc);
                float zs = 0.f, gs = 0.f;
#pragma unroll
                for (int tj = 0; tj < 4; tj++) {
                    int kcl = wn * 32 + tj * 8 + 2 * (lane & 3);
                    float kg = (float)(kt * 128 + kcl);
                    float s0 = acc2[ti][tj][2 * hh + 0] * 0.125f;
                    float s1 = acc2[ti][tj][2 * hh + 1] * 0.125f;
                    float p0 = __expf(s0), p1 = __expf(s1);
                    float d0 = qg - kg, d1 = qg - (kg + 1.0f);
                    float g0 = __expf(-d0 * d0 * (1.0f / 32768.0f));
                    float g1 = __expf(-d1 * d1 * (1.0f / 32768.0f));
                    float pg0 = p0 * g0, pg1 = p1 * g1;
                    zs += p0 + p1;
                    gs += pg0 + pg1;
                    __half2 ph2 = __floats2half2_rn(pg0, pg1);
                    int chunk = kcl >> 5;
                    int c32 = kcl & 31;
                    uint32_t off = (uint32_t)chunk * 4096 + rloc * 64
                                 + (((c32 >> 3) ^ ((rloc >> 1) & 3)) << 4) + (c32 & 7) * 2;
                    *(__half2*)(dsm + AF_SP + off) = ph2;
                }
                zacc[ti * 2 + hh] += zs;
                gacc[ti * 2 + hh] += gs;
            }
        }
        __syncthreads();

#pragma unroll
        for (int ch = 0; ch < 4; ch++) {
            uint32_t sAh = sbase + AF_SP + (uint32_t)ch * 4096;
            uint32_t sBh = sbase + AF_SV + (uint32_t)ch * 4096, sBl = sBh + 16384;
#pragma unroll
            for (int ks = 0; ks < 2; ks++) {
                uint32_t ph[2][4];
#pragma unroll
                for (int ti = 0; ti < 2; ti++) {
                    int r = wm * 32 + ti * 16 + (lane & 15);
                    int cc = 2 * ks + (lane >> 4);
                    uint32_t off = r * 64 + ((cc ^ ((r >> 1) & 3)) << 4);
                    ldsm4(ph[ti][0], ph[ti][1], ph[ti][2], ph[ti][3], sAh + off);
                }
                int r = wn * 16 + (lane & 15);
                int cc = 2 * ks + (lane >> 4);
                int fd = ((r >> 1) & 3) ^ ((r >> 3) & 3);
                uint32_t off = r * 64 + ((cc ^ fd) << 4);
                uint32_t b0, b1, b2, b3, c0, c1, c2, c3;
                ldsm4(b0, b1, b2, b3, sBh + off);
                ldsm4(c0, c1, c2, c3, sBl + off);
#pragma unroll
                for (int ti = 0; ti < 2; ti++) {
                    mma16816(accO[ti][0], ph[ti], b0, b2);
                    mma16816(accO[ti][1], ph[ti], b1, b3);
                    mma16816(accO[ti][0], ph[ti], c0, c2);
                    mma16816(accO[ti][1], ph[ti], c1, c3);
                }
            }
        }
    }

#pragma unroll
    for (int s = 0; s < 4; s++) {
        zacc[s] += __shfl_xor_sync(~0u, zacc[s], 1);
        zacc[s] += __shfl_xor_sync(~0u, zacc[s], 2);
        gacc[s] += __shfl_xor_sync(~0u, gacc[s], 1);
        gacc[s] += __shfl_xor_sync(~0u, gacc[s], 2);
    }
    if ((lane & 3) == 0) {
#pragma unroll
        for (int ti = 0; ti < 2; ti++)
#pragma unroll
            for (int hh = 0; hh < 2; hh++) {
                int rloc = wm * 32 + ti * 16 + (lane >> 2) + hh * 8;
                atomicAdd(&sZ[rloc], zacc[ti * 2 + hh]);
                atomicAdd(&sG[rloc], gacc[ti * 2 + hh]);
            }
    }
    __syncthreads();
    if (tid < QT) sInv[tid] = 1.0f / (sG[tid] + 1e-5f * sZ[tid]);
    __syncthreads();

#pragma unroll
    for (int ti = 0; ti < 2; ti++) {
#pragma unroll
        for (int tj = 0; tj < 2; tj++) {
            int dl = wn * 16 + tj * 8 + 2 * (lane & 3);
            int colg = h * Dn + dl;
#pragma unroll
            for (int hh = 0; hh < 2; hh++) {
                int rloc = wm * 32 + ti * 16 + (lane >> 2) + hh * 8;
                float inv = sInv[rloc];
                float v0 = accO[ti][tj][2 * hh + 0] * inv;
                float v1 = accO[ti][tj][2 * hh + 1] * inv;
                size_t o = (size_t)b * Tn * En + (size_t)(q0 + rloc) * En + colg;
                *(__half2*)(oh + o) = __floats2half2_rn(v0, v1);
            }
        }
    }
}

// ---------------- residual + LN ----------------
__global__ __launch_bounds__(256) void add_ln(
    float* __restrict__ x, const float* __restrict__ r,
    const float* __restrict__ g, const float* __restrict__ bt,
    __half* __restrict__ xh, __half* __restrict__ xl)
{
    const size_t base = (size_t)blockIdx.x * En;
    const int tid = threadIdx.x;
    float v[4];
    float s = 0.f, sq = 0.f;
#pragma unroll
    for (int i = 0; i < 4; i++) {
        int c = tid + i * 256;
        v[i] = x[base + c] + r[base + c];
        s += v[i];
        sq += v[i] * v[i];
    }
    float2 t = blockSum2(s, sq);
    float mu = t.x * (1.0f / En);
    float var = fmaxf(t.y * (1.0f / En) - mu * mu, 0.f);
    float rs = rsqrtf(var + 1e-5f);
#pragma unroll
    for (int i = 0; i < 4; i++) {
        int c = tid + i * 256;
        float o = (v[i] - mu) * rs * g[c] + bt[c];
        x[base + c] = o;
        if (xl) {
            split_hl(o, xh[base + c], xl[base + c]);
        } else {
            xh[base + c] = __float2half_rn(o);
        }
    }
}

__global__ __launch_bounds__(256) void head_kernel(
    const float* __restrict__ x, const float* __restrict__ hw,
    const float* __restrict__ hb, float* __restrict__ out)
{
    const int b = blockIdx.x;
    const int tid = threadIdx.x;
    const float* row = x + (size_t)b * Tn * En + (size_t)(Tn - 1) * En;
    float s = 0.f;
    for (int c = tid; c < En; c += 256) s += row[c] * hw[c];
    s = blockSum(s);
    if (tid == 0) out[b] = s + hb[0];
}

// ---------------- launch ----------------
extern "C" void kernel_launch(void* const* d_in, const int* in_sizes, int n_in,
                              void* d_out, int out_size)
{
    const float* src    = (const float*)d_in[0];
    const float* in_w   = (const float*)d_in[1];
    const float* in_b   = (const float*)d_in[2];
    const float* outp_w = (const float*)d_in[3];
    const float* outp_b = (const float*)d_in[4];
    const float* ff1_w  = (const float*)d_in[5];
    const float* ff1_b  = (const float*)d_in[6];
    const float* ff2_w  = (const float*)d_in[7];
    const float* ff2_b  = (const float*)d_in[8];
    const float* ln1_g  = (const float*)d_in[9];
    const float* ln1_b  = (const float*)d_in[10];
    const float* ln2_g  = (const float*)d_in[11];
    const float* ln2_b  = (const float*)d_in[12];
    const float* head_w = (const float*)d_in[13];
    const float* head_b = (const float*)d_in[14];
    float* out = (float*)d_out;

    static bool init = false;
    static float *x, *proj;
    static __half *xh,*xl,*ah,*fh,*qkvh,*qkvl,*wih,*woh,*w1h,*w2h;
    if (!init) {
        cudaGetSymbolAddress((void**)&x, g_x);
        cudaGetSymbolAddress((void**)&proj, g_proj);
        cudaGetSymbolAddress((void**)&xh, g_xh); cudaGetSymbolAddress((void**)&xl, g_xl);
        cudaGetSymbolAddress((void**)&ah, g_ah);
        cudaGetSymbolAddress((void**)&fh, g_fh);
        cudaGetSymbolAddress((void**)&qkvh, g_qkvh); cudaGetSymbolAddress((void**)&qkvl, g_qkvl);
        cudaGetSymbolAddress((void**)&wih, g_wih);
        cudaGetSymbolAddress((void**)&woh, g_woh);
        cudaGetSymbolAddress((void**)&w1h, g_w1h);
        cudaGetSymbolAddress((void**)&w2h, g_w2h);
        cudaFuncSetAttribute(gemm_mma<true>, cudaFuncAttributeMaxDynamicSharedMemorySize, 4 * STGB);
        cudaFuncSetAttribute(gemm_mma<false>, cudaFuncAttributeMaxDynamicSharedMemorySize, 4 * STGB);
        cudaFuncSetAttribute(attn_fused, cudaFuncAttributeMaxDynamicSharedMemorySize, AF_SMEM);
        init = true;
    }

    // weights -> fp16 hi
    convert_h4<<<Ln * 3 * En * En / 1024, 256>>>((const float4*)in_w, (__half2*)wih);
    convert_h4<<<Ln * En * En / 1024, 256>>>((const float4*)outp_w, (__half2*)woh);
    convert_h4<<<Ln * FFn * En / 1024, 256>>>((const float4*)ff1_w, (__half2*)w1h);
    convert_h4<<<Ln * En * FFn / 1024, 256>>>((const float4*)ff2_w, (__half2*)w2h);

    pe_add_kernel<<<Bn * Tn * En / 256, 256>>>(src, x, xh, xl);

    for (int l = 0; l < Ln; l++) {
        size_t wo3 = (size_t)l * 3 * En * En, wo1 = (size_t)l * En * En;
        size_t wof = (size_t)l * FFn * En;
        // qkv (2-term A, fp16 hi/lo out)
        gemm_mma<true><<<dim3(3 * En / BN, Bn * Tn / BM), 256, 4 * STGB>>>(
            xh, xl, wih + wo3, in_b + (size_t)l * 3 * En,
            nullptr, qkvh, qkvl, En, 3 * En, 0);
        // fused attention (hi-only O)
        attn_fused<<<dim3(Tn / QT, Bn * Hn), 256, AF_SMEM>>>(qkvh, qkvl, ah);
        // out proj (1-term A)
        gemm_mma<false><<<dim3(En / BN, Bn * Tn / BM), 256, 4 * STGB>>>(
            ah, nullptr, woh + wo1, outp_b + (size_t)l * En,
            proj, nullptr, nullptr, En, En, 0);
        add_ln<<<Bn * Tn, 256>>>(x, proj, ln1_g + (size_t)l * En, ln1_b + (size_t)l * En, xh, xl);
        // ff1 (1-term A, relu, hi-only out)
        gemm_mma<false><<<dim3(FFn / BN, Bn * Tn / BM), 256, 4 * STGB>>>(
            xh, nullptr, w1h + wof, ff1_b + (size_t)l * FFn,
            nullptr, fh, nullptr, En, FFn, 1);
        // ff2 (1-term A)
        gemm_mma<false><<<dim3(En / BN, Bn * Tn / BM), 256, 4 * STGB>>>(
            fh, nullptr, w2h + wof, ff2_b + (size_t)l * En,
            proj, nullptr, nullptr, FFn, En, 0);
        add_ln<<<Bn * Tn, 256>>>(x, proj, ln2_g + (size_t)l * En, ln2_b + (size_t)l * En, xh, xl);
    }

    head_kernel<<<Bn, 256>>>(x, head_w, head_b, out);
}

// round 16
// speedup vs baseline: 2.1663x; 1.0279x over previous
#include <cuda_runtime.h>
#include <cuda_fp16.h>
#include <math.h>
#include <stdint.h>

#define Bn  8
#define Tn  512
#define En  1024
#define Hn  16
#define Dn  64
#define Ln  4
#define FFn 4096

// fp32 scratch
__device__ float g_x[Bn * Tn * En];
__device__ float g_proj[Bn * Tn * En];
// fp16 activations
__device__ __half g_xh[Bn * Tn * En],  g_xl[Bn * Tn * En];
__device__ __half g_ah[Bn * Tn * En];
__device__ __half g_fh[Bn * Tn * FFn];
__device__ __half g_qkvh[Bn * Tn * 3 * En], g_qkvl[Bn * Tn * 3 * En];
// fp16 weight (hi only)
__device__ __half g_wih[Ln * 3 * En * En];
__device__ __half g_woh[Ln * En * En];
__device__ __half g_w1h[Ln * FFn * En];
__device__ __half g_w2h[Ln * En * FFn];

// ---------------- PTX helpers (sm_80+ only) ----------------
__device__ __forceinline__ uint32_t smem_u32(const void* p) {
    uint32_t a;
    asm("{ .reg .u64 t; cvta.to.shared.u64 t, %1; cvt.u32.u64 %0, t; }" : "=r"(a) : "l"(p));
    return a;
}
__device__ __forceinline__ void cpasync16(uint32_t dst, const void* src) {
    asm volatile("cp.async.cg.shared.global [%0], [%1], 16;" :: "r"(dst), "l"(src));
}
__device__ __forceinline__ void cp_commit() { asm volatile("cp.async.commit_group;" ::: "memory"); }
template <int N> __device__ __forceinline__ void cp_wait() {
    asm volatile("cp.async.wait_group %0;" :: "n"(N) : "memory");
}
__device__ __forceinline__ void ldsm4(uint32_t& r0, uint32_t& r1, uint32_t& r2,
                                      uint32_t& r3, uint32_t a) {
    asm volatile("ldmatrix.sync.aligned.m8n8.x4.shared.b16 {%0,%1,%2,%3}, [%4];"
                 : "=r"(r0), "=r"(r1), "=r"(r2), "=r"(r3) : "r"(a));
}
__device__ __forceinline__ void mma16816(float* d, const uint32_t* a, uint32_t b0, uint32_t b1) {
    asm volatile("mma.sync.aligned.m16n8k16.row.col.f32.f16.f16.f32 "
                 "{%0,%1,%2,%3}, {%4,%5,%6,%7}, {%8,%9}, {%0,%1,%2,%3};"
                 : "+f"(d[0]), "+f"(d[1]), "+f"(d[2]), "+f"(d[3])
                 : "r"(a[0]), "r"(a[1]), "r"(a[2]), "r"(a[3]), "r"(b0), "r"(b1));
}
__device__ __forceinline__ void split_hl(float v, __half& h, __half& l) {
    h = __float2half_rn(v);
    l = __float2half_rn(v - __half2float(h));
}

// ---------------- reductions ----------------
__device__ __forceinline__ float warpSum(float v) {
#pragma unroll
    for (int o = 16; o; o >>= 1) v += __shfl_xor_sync(~0u, v, o);
    return v;
}
__device__ __forceinline__ float blockSum(float v) {
    __shared__ float sm[8];
    int lane = threadIdx.x & 31, wid = threadIdx.x >> 5;
    v = warpSum(v);
    __syncthreads();
    if (lane == 0) sm[wid] = v;
    __syncthreads();
    v = sm[lane & 7];
#pragma unroll
    for (int o = 4; o; o >>= 1) v += __shfl_xor_sync(~0u, v, o);
    return v;
}
__device__ __forceinline__ float2 blockSum2(float a, float b) {
    __shared__ float2 sm[8];
    int lane = threadIdx.x & 31, wid = threadIdx.x >> 5;
#pragma unroll
    for (int o = 16; o; o >>= 1) {
        a += __shfl_xor_sync(~0u, a, o);
        b += __shfl_xor_sync(~0u, b, o);
    }
    __syncthreads();
    if (lane == 0) sm[wid] = make_float2(a, b);
    __syncthreads();
    float2 v = sm[lane & 7];
#pragma unroll
    for (int o = 4; o; o >>= 1) {
        v.x += __shfl_xor_sync(~0u, v.x, o);
        v.y += __shfl_xor_sync(~0u, v.y, o);
    }
    return v;
}

// ---------------- small kernels ----------------
__global__ void convert_h4(const float4* __restrict__ s, __half2* __restrict__ h) {
    int i = blockIdx.x * 256 + threadIdx.x;
    float4 v = s[i];
    h[2 * i]     = __floats2half2_rn(v.x, v.y);
    h[2 * i + 1] = __floats2half2_rn(v.z, v.w);
}

__global__ void pe_add_kernel(const float* __restrict__ src, float* __restrict__ x,
                              __half* __restrict__ xh, __half* __restrict__ xl) {
    int idx = blockIdx.x * 256 + threadIdx.x;
    int e = idx & (En - 1);
    int b = idx / (Tn * En);
    float dv = expf((float)(e & ~1) * (-9.210340371976184f / (float)En));
    float ang = (float)b * dv;
    float pe = (e & 1) ? cosf(ang) : sinf(ang);
    float v = src[idx] + pe;
    x[idx] = v;
    split_hl(v, xh[idx], xl[idx]);
}

// ---------------- 2-term fp16 GEMM (QKV): unchanged R15 config ----------------
#define BM 128
#define BN 128
#define BK 32
#define RGB 8192
#define STGB (3 * RGB)

__global__ __launch_bounds__(256, 2) void gemm_mma2(
    const __half* __restrict__ Ah, const __half* __restrict__ Al,
    const __half* __restrict__ Bh,
    const float* __restrict__ bias,
    __half* __restrict__ Ch, __half* __restrict__ Cl,
    int K, int N)
{
    extern __shared__ __align__(128) uint8_t dsm[];
    __shared__ float sh_bias[BN];

    const int tid = threadIdx.x;
    const uint32_t sbase = smem_u32(dsm);
    if (tid < BN) sh_bias[tid] = bias[blockIdx.x * BN + tid];

    const int wid = tid >> 5, lane = tid & 31;
    const int wm = wid >> 1, wn = wid & 1;

    const __half* Abh = Ah + (size_t)blockIdx.y * BM * K;
    const __half* Abl = Al + (size_t)blockIdx.y * BM * K;
    const __half* Bbh = Bh + (size_t)blockIdx.x * BN * K;

    const int cps = K / BK;

    auto load_chunk = [&](int c, int st) {
        int kc = c * BK;
        uint32_t sg = sbase + (uint32_t)st * STGB;
#pragma unroll
        for (int j = 0; j < 2; j++) {
            int idx = tid + j * 256;
            int r = idx >> 2, cc = idx & 3;
            uint32_t off = r * 64 + ((cc ^ ((r >> 1) & 3)) << 4);
            size_t go = (size_t)r * K + kc + cc * 8;
            cpasync16(sg + off, Abh + go);
            cpasync16(sg + RGB + off, Abl + go);
            cpasync16(sg + 2 * RGB + off, Bbh + go);
        }
        cp_commit();
    };

    float acc[2][8][4] = {};
    load_chunk(0, 0);
    load_chunk(1, 1);
    load_chunk(2, 2);

    int st = 0;
    for (int c = 0; c < cps; c++) {
        int rem = cps - 1 - c;
        if (rem >= 2)      cp_wait<2>();
        else if (rem == 1) cp_wait<1>();
        else               cp_wait<0>();
        __syncthreads();
        if (c + 3 < cps) {
            int ns = st + 3; if (ns >= 4) ns -= 4;
            load_chunk(c + 3, ns);
        }

        uint32_t sAh = sbase + (uint32_t)st * STGB;
        uint32_t sAl = sAh + RGB;
        uint32_t sBh = sAh + 2 * RGB;
#pragma unroll
        for (int ks = 0; ks < 2; ks++) {
            uint32_t ah[2][4], al[2][4];
#pragma unroll
            for (int ti = 0; ti < 2; ti++) {
                int r = wm * 32 + ti * 16 + (lane & 15);
                int cc = 2 * ks + (lane >> 4);
                uint32_t off = r * 64 + ((cc ^ ((r >> 1) & 3)) << 4);
                ldsm4(ah[ti][0], ah[ti][1], ah[ti][2], ah[ti][3], sAh + off);
                ldsm4(al[ti][0], al[ti][1], al[ti][2], al[ti][3], sAl + off);
            }
#pragma unroll
            for (int tp = 0; tp < 2; tp++) {
                uint32_t bf[2][4];
#pragma unroll
                for (int q = 0; q < 2; q++) {
                    int tj = tp * 2 + q;
                    int r = wn * 64 + tj * 16 + (lane & 15);
                    int cc = 2 * ks + (lane >> 4);
                    uint32_t off = r * 64 + ((cc ^ ((r >> 1) & 3)) << 4);
                    ldsm4(bf[q][0], bf[q][1], bf[q][2], bf[q][3], sBh + off);
                }
#pragma unroll
                for (int q = 0; q < 2; q++) {
                    int tj = tp * 2 + q;
                    mma16816(acc[0][2 * tj],     ah[0], bf[q][0], bf[q][2]);
                    mma16816(acc[0][2 * tj + 1], ah[0], bf[q][1], bf[q][3]);
                    mma16816(acc[1][2 * tj],     ah[1], bf[q][0], bf[q][2]);
                    mma16816(acc[1][2 * tj + 1], ah[1], bf[q][1], bf[q][3]);
                    mma16816(acc[0][2 * tj],     al[0], bf[q][0], bf[q][2]);
                    mma16816(acc[0][2 * tj + 1], al[0], bf[q][1], bf[q][3]);
                    mma16816(acc[1][2 * tj],     al[1], bf[q][0], bf[q][2]);
                    mma16816(acc[1][2 * tj + 1], al[1], bf[q][1], bf[q][3]);
                }
            }
        }
        if (++st == 4) st = 0;
    }

    const int col0 = wn * 64;
    const int row0 = blockIdx.y * BM + wm * 32;
#pragma unroll
    for (int ti = 0; ti < 2; ti++) {
#pragma unroll
        for (int tj = 0; tj < 8; tj++) {
            int cl = col0 + tj * 8 + 2 * (lane & 3);
            int colg = blockIdx.x * BN + cl;
            float b0 = sh_bias[cl], b1 = sh_bias[cl + 1];
#pragma unroll
            for (int hh = 0; hh < 2; hh++) {
                int row = row0 + ti * 16 + (lane >> 2) + hh * 8;
                float v0 = acc[ti][tj][2 * hh + 0] + b0;
                float v1 = acc[ti][tj][2 * hh + 1] + b1;
                size_t o = (size_t)row * N + colg;
                __half h0, l0, h1, l1;
                split_hl(v0, h0, l0);
                split_hl(v1, h1, l1);
                __half2 hv; hv.x = h0; hv.y = h1;
                __half2 lv; lv.x = l0; lv.y = l1;
                *(__half2*)(Ch + o) = hv;
                *(__half2*)(Cl + o) = lv;
            }
        }
    }
}

// ---------------- 1-term fp16 GEMM, BK=64 (two 32-K sub-chunks per stage) ----------------
// Stage 32 KB = [A sub0 8K | A sub1 8K | B sub0 8K | B sub1 8K]; 3 stages, 2 CTA/SM.
#define STG1 32768

__global__ __launch_bounds__(256, 2) void gemm_mma1(
    const __half* __restrict__ Ah, const __half* __restrict__ Bh,
    const float* __restrict__ bias, float* __restrict__ Cf,
    __half* __restrict__ Ch, int K, int N, int relu)
{
    extern __shared__ __align__(128) uint8_t dsm[];
    __shared__ float sh_bias[BN];

    const int tid = threadIdx.x;
    const uint32_t sbase = smem_u32(dsm);
    if (tid < BN) sh_bias[tid] = bias[blockIdx.x * BN + tid];

    const int wid = tid >> 5, lane = tid & 31;
    const int wm = wid >> 1, wn = wid & 1;

    const __half* Abh = Ah + (size_t)blockIdx.y * BM * K;
    const __half* Bbh = Bh + (size_t)blockIdx.x * BN * K;

    const int cps = K / 64;

    auto load_chunk = [&](int c, int st) {
        int kc = c * 64;
        uint32_t sg = sbase + (uint32_t)st * STG1;
#pragma unroll
        for (int j = 0; j < 4; j++) {
            int idx = tid + j * 256;       // 0..1023
            int r = idx >> 3, gg = idx & 7;
            int sub = gg >> 2, grp = gg & 3;
            uint32_t off = (uint32_t)sub * 8192 + r * 64 + ((grp ^ ((r >> 1) & 3)) << 4);
            size_t go = (size_t)r * K + kc + gg * 8;
            cpasync16(sg + off, Abh + go);
            cpasync16(sg + 16384 + off, Bbh + go);
        }
        cp_commit();
    };

    float acc[2][8][4] = {};
    load_chunk(0, 0);
    load_chunk(1, 1);

    int st = 0;
    for (int c = 0; c < cps; c++) {
        if (c + 1 < cps) cp_wait<1>(); else cp_wait<0>();
        __syncthreads();
        if (c + 2 < cps) {
            int ns = st + 2; if (ns >= 3) ns -= 3;
            load_chunk(c + 2, ns);
        }

        uint32_t sg = sbase + (uint32_t)st * STG1;
#pragma unroll
        for (int sub = 0; sub < 2; sub++) {
            uint32_t sAh = sg + (uint32_t)sub * 8192;
            uint32_t sBh = sg + 16384 + (uint32_t)sub * 8192;
#pragma unroll
            for (int ks = 0; ks < 2; ks++) {
                uint32_t ah[2][4];
#pragma unroll
                for (int ti = 0; ti < 2; ti++) {
                    int r = wm * 32 + ti * 16 + (lane & 15);
                    int cc = 2 * ks + (lane >> 4);
                    uint32_t off = r * 64 + ((cc ^ ((r >> 1) & 3)) << 4);
                    ldsm4(ah[ti][0], ah[ti][1], ah[ti][2], ah[ti][3], sAh + off);
                }
                uint32_t bf[4][4];
#pragma unroll
                for (int tj = 0; tj < 4; tj++) {
                    int r = wn * 64 + tj * 16 + (lane & 15);
                    int cc = 2 * ks + (lane >> 4);
                    uint32_t off = r * 64 + ((cc ^ ((r >> 1) & 3)) << 4);
                    ldsm4(bf[tj][0], bf[tj][1], bf[tj][2], bf[tj][3], sBh + off);
                }
#pragma unroll
                for (int tj = 0; tj < 4; tj++) {
                    mma16816(acc[0][2 * tj],     ah[0], bf[tj][0], bf[tj][2]);
                    mma16816(acc[0][2 * tj + 1], ah[0], bf[tj][1], bf[tj][3]);
                    mma16816(acc[1][2 * tj],     ah[1], bf[tj][0], bf[tj][2]);
                    mma16816(acc[1][2 * tj + 1], ah[1], bf[tj][1], bf[tj][3]);
                }
            }
        }
        if (++st == 3) st = 0;
    }

    const int col0 = wn * 64;
    const int row0 = blockIdx.y * BM + wm * 32;
#pragma unroll
    for (int ti = 0; ti < 2; ti++) {
#pragma unroll
        for (int tj = 0; tj < 8; tj++) {
            int cl = col0 + tj * 8 + 2 * (lane & 3);
            int colg = blockIdx.x * BN + cl;
            float b0 = sh_bias[cl], b1 = sh_bias[cl + 1];
#pragma unroll
            for (int hh = 0; hh < 2; hh++) {
                int row = row0 + ti * 16 + (lane >> 2) + hh * 8;
                float v0 = acc[ti][tj][2 * hh + 0] + b0;
                float v1 = acc[ti][tj][2 * hh + 1] + b1;
                if (relu) { v0 = fmaxf(v0, 0.f); v1 = fmaxf(v1, 0.f); }
                size_t o = (size_t)row * N + colg;
                if (Cf) *(float2*)(Cf + o) = make_float2(v0, v1);
                if (Ch) *(__half2*)(Ch + o) = __floats2half2_rn(v0, v1);
            }
        }
    }
}

// ---------------- fused attention v3: V LDG hoisted over K wait ----------------
#define QT 64
#define AF_SQ 0
#define AF_SK 16384
#define AF_SV 49152
#define AF_SP 81920
#define AF_SZ 98304
#define AF_SMEM (98304 + 768)

__global__ __launch_bounds__(256, 2) void attn_fused(
    const __half* __restrict__ qkvh, const __half* __restrict__ qkvl,
    __half* __restrict__ oh)
{
    extern __shared__ __align__(128) uint8_t dsm[];
    const int tid = threadIdx.x;
    const uint32_t sbase = smem_u32(dsm);
    const int wid = tid >> 5, lane = tid & 31;
    const int wm = wid >> 2, wn = wid & 3;
    const int bh = blockIdx.y, b = bh >> 4, h = bh & 15;
    const int q0 = blockIdx.x * QT;
    const int LDQ = 3 * En;

    float* sZ = (float*)(dsm + AF_SZ);
    float* sG = (float*)(dsm + AF_SZ + 256);
    float* sInv = (float*)(dsm + AF_SZ + 512);

    const __half* Qhb = qkvh + (size_t)b * Tn * LDQ + h * Dn + (size_t)q0 * LDQ;
    const __half* Qlb = qkvl + (size_t)b * Tn * LDQ + h * Dn + (size_t)q0 * LDQ;
    const __half* Khb = qkvh + (size_t)b * Tn * LDQ + En + h * Dn;
    const __half* Klb = qkvl + (size_t)b * Tn * LDQ + En + h * Dn;
    const __half* Vhb = qkvh + (size_t)b * Tn * LDQ + 2 * En + h * Dn;
    const __half* Vlb = qkvl + (size_t)b * Tn * LDQ + 2 * En + h * Dn;

    auto loadQ = [&]() {
#pragma unroll
        for (int j = 0; j < 2; j++) {
            int idx = tid + j * 256;
            int r = idx >> 3, gg = idx & 7;
            int chunk = gg >> 2, grp = gg & 3;
            uint32_t off = (uint32_t)chunk * 4096 + r * 64 + ((grp ^ ((r >> 1) & 3)) << 4);
            size_t go = (size_t)r * LDQ + gg * 8;
            cpasync16(sbase + AF_SQ + off, Qhb + go);
            cpasync16(sbase + AF_SQ + 8192 + off, Qlb + go);
        }
        cp_commit();
    };

    auto loadK = [&](int kt) {
#pragma unroll
        for (int j = 0; j < 4; j++) {
            int idx = tid + j * 256;
            int r = idx >> 3, gg = idx & 7;
            int chunk = gg >> 2, grp = gg & 3;
            uint32_t off = (uint32_t)chunk * 8192 + r * 64 + ((grp ^ ((r >> 1) & 3)) << 4);
            size_t go = (size_t)(kt * 128 + r) * LDQ + gg * 8;
            cpasync16(sbase + AF_SK + off, Khb + go);
            cpasync16(sbase + AF_SK + 16384 + off, Klb + go);
        }
        cp_commit();
    };

    uint4 vh4[4], vl4[4];
    auto ldgV = [&](int kt) {
        int kk = tid >> 3;
        int d0 = (tid & 7) * 8;
#pragma unroll
        for (int p = 0; p < 4; p++) {
            size_t go = (size_t)(kt * 128 + p * 32 + kk) * LDQ + d0;
            vh4[p] = *(const uint4*)(Vhb + go);
            vl4[p] = *(const uint4*)(Vlb + go);
        }
    };
    auto stsV = [&]() {
        int kk = tid >> 3;
        int d0 = (tid & 7) * 8;
#pragma unroll
        for (int p = 0; p < 4; p++) {
            uint32_t h4[4] = {vh4[p].x, vh4[p].y, vh4[p].z, vh4[p].w};
            uint32_t l4[4] = {vl4[p].x, vl4[p].y, vl4[p].z, vl4[p].w};
#pragma unroll
            for (int i = 0; i < 8; i++) {
                uint16_t hb16 = (uint16_t)(h4[i >> 1] >> ((i & 1) * 16));
                uint16_t lb16 = (uint16_t)(l4[i >> 1] >> ((i & 1) * 16));
                int d = d0 + i;
                int fd = ((d >> 1) & 3) ^ ((d >> 3) & 3);
                uint32_t off = (uint32_t)p * 4096 + d * 64 + (((kk >> 3) ^ fd) << 4) + (kk & 7) * 2;
                *(uint16_t*)(dsm + AF_SV + off) = hb16;
                *(uint16_t*)(dsm + AF_SV + 16384 + off) = lb16;
            }
        }
    };

    loadQ();
    if (tid < QT) { sZ[tid] = 0.f; sG[tid] = 0.f; }

    float accO[2][2][4] = {};
    float zacc[4] = {}, gacc[4] = {};

    for (int kt = 0; kt < 4; kt++) {
        __syncthreads();          // prev iteration consumed K/V/P; sZ init visible
        loadK(kt);
        ldgV(kt);                 // LDG latency overlaps K cp.async wait
        cp_wait<0>();
        __syncthreads();
        stsV();                   // publish V before the P-store barrier

        float acc2[2][4][4] = {};
#pragma unroll
        for (int c = 0; c < 2; c++) {
            uint32_t sAh = sbase + AF_SQ + (uint32_t)c * 4096, sAl = sAh + 8192;
            uint32_t sBh = sbase + AF_SK + (uint32_t)c * 8192, sBl = sBh + 16384;
#pragma unroll
            for (int ks = 0; ks < 2; ks++) {
                uint32_t ah[2][4], al[2][4];
#pragma unroll
                for (int ti = 0; ti < 2; ti++) {
                    int r = wm * 32 + ti * 16 + (lane & 15);
                    int cc = 2 * ks + (lane >> 4);
                    uint32_t off = r * 64 + ((cc ^ ((r >> 1) & 3)) << 4);
                    ldsm4(ah[ti][0], ah[ti][1], ah[ti][2], ah[ti][3], sAh + off);
                    ldsm4(al[ti][0], al[ti][1], al[ti][2], al[ti][3], sAl + off);
                }
#pragma unroll
                for (int tjj = 0; tjj < 2; tjj++) {
                    int r = wn * 32 + tjj * 16 + (lane & 15);
                    int cc = 2 * ks + (lane >> 4);
                    uint32_t off = r * 64 + ((cc ^ ((r >> 1) & 3)) << 4);
                    uint32_t b0, b1, b2, b3, c0, c1, c2, c3;
                    ldsm4(b0, b1, b2, b3, sBh + off);
                    ldsm4(c0, c1, c2, c3, sBl + off);
#pragma unroll
                    for (int ti = 0; ti < 2; ti++) {
                        mma16816(acc2[ti][2 * tjj],     ah[ti], b0, b2);
                        mma16816(acc2[ti][2 * tjj + 1], ah[ti], b1, b3);
                        mma16816(acc2[ti][2 * tjj],     al[ti], b0, b2);
                        mma16816(acc2[ti][2 * tjj + 1], al[ti], b1, b3);
                        mma16816(acc2[ti][2 * tjj],     ah[ti], c0, c2);
                        mma16816(acc2[ti][2 * tjj + 1], ah[ti], c1, c3);
                    }
                }
            }
        }

#pragma unroll
        for (int ti = 0; ti < 2; ti++) {
#pragma unroll
            for (int hh = 0; hh < 2; hh++) {
                int rloc = wm * 32 + ti * 16 + (lane >> 2) + hh * 8;
                float qg = (float)(q0 + rloc);
                float zs = 0.f, gs = 0.f;
#pragma unroll
                for (int tj = 0; tj < 4; tj++) {
                    int kcl = wn * 32 + tj * 8 + 2 * (lane & 3);
                    float kg = (float)(kt * 128 + kcl);
                    float s0 = acc2[ti][tj][2 * hh + 0] * 0.125f;
                    float s1 = acc2[ti][tj][2 * hh + 1] * 0.125f;
                    float p0 = __expf(s0), p1 = __expf(s1);
                    float d0 = qg - kg, d1 = qg - (kg + 1.0f);
                    float g0 = __expf(-d0 * d0 * (1.0f / 32768.0f));
                    float g1 = __expf(-d1 * d1 * (1.0f / 32768.0f));
                    float pg0 = p0 * g0, pg1 = p1 * g1;
                    zs += p0 + p1;
                    gs += pg0 + pg1;
                    __half2 ph2 = __floats2half2_rn(pg0, pg1);
                    int chunk = kcl >> 5;
                    int c32 = kcl & 31;
                    uint32_t off = (uint32_t)chunk * 4096 + rloc * 64
                                 + (((c32 >> 3) ^ ((rloc >> 1) & 3)) << 4) + (c32 & 7) * 2;
                    *(__half2*)(dsm + AF_SP + off) = ph2;
                }
                zacc[ti * 2 + hh] += zs;
                gacc[ti * 2 + hh] += gs;
            }
        }
        __syncthreads();

#pragma unroll
        for (int ch = 0; ch < 4; ch++) {
            uint32_t sAh = sbase + AF_SP + (uint32_t)ch * 4096;
            uint32_t sBh = sbase + AF_SV + (uint32_t)ch * 4096, sBl = sBh + 16384;
#pragma unroll
            for (int ks = 0; ks < 2; ks++) {
                uint32_t ph[2][4];
#pragma unroll
                for (int ti = 0; ti < 2; ti++) {
                    int r = wm * 32 + ti * 16 + (lane & 15);
                    int cc = 2 * ks + (lane >> 4);
                    uint32_t off = r * 64 + ((cc ^ ((r >> 1) & 3)) << 4);
                    ldsm4(ph[ti][0], ph[ti][1], ph[ti][2], ph[ti][3], sAh + off);
                }
                int r = wn * 16 + (lane & 15);
                int cc = 2 * ks + (lane >> 4);
                int fd = ((r >> 1) & 3) ^ ((r >> 3) & 3);
                uint32_t off = r * 64 + ((cc ^ fd) << 4);
                uint32_t b0, b1, b2, b3, c0, c1, c2, c3;
                ldsm4(b0, b1, b2, b3, sBh + off);
                ldsm4(c0, c1, c2, c3, sBl + off);
#pragma unroll
                for (int ti = 0; ti < 2; ti++) {
                    mma16816(accO[ti][0], ph[ti], b0, b2);
                    mma16816(accO[ti][1], ph[ti], b1, b3);
                    mma16816(accO[ti][0], ph[ti], c0, c2);
                    mma16816(accO[ti][1], ph[ti], c1, c3);
                }
            }
        }
    }

#pragma unroll
    for (int s = 0; s < 4; s++) {
        zacc[s] += __shfl_xor_sync(~0u, zacc[s], 1);
        zacc[s] += __shfl_xor_sync(~0u, zacc[s], 2);
        gacc[s] += __shfl_xor_sync(~0u, gacc[s], 1);
        gacc[s] += __shfl_xor_sync(~0u, gacc[s], 2);
    }
    if ((lane & 3) == 0) {
#pragma unroll
        for (int ti = 0; ti < 2; ti++)
#pragma unroll
            for (int hh = 0; hh < 2; hh++) {
                int rloc = wm * 32 + ti * 16 + (lane >> 2) + hh * 8;
                atomicAdd(&sZ[rloc], zacc[ti * 2 + hh]);
                atomicAdd(&sG[rloc], gacc[ti * 2 + hh]);
            }
    }
    __syncthreads();
    if (tid < QT) sInv[tid] = 1.0f / (sG[tid] + 1e-5f * sZ[tid]);
    __syncthreads();

#pragma unroll
    for (int ti = 0; ti < 2; ti++) {
#pragma unroll
        for (int tj = 0; tj < 2; tj++) {
            int dl = wn * 16 + tj * 8 + 2 * (lane & 3);
            int colg = h * Dn + dl;
#pragma unroll
            for (int hh = 0; hh < 2; hh++) {
                int rloc = wm * 32 + ti * 16 + (lane >> 2) + hh * 8;
                float inv = sInv[rloc];
                float v0 = accO[ti][tj][2 * hh + 0] * inv;
                float v1 = accO[ti][tj][2 * hh + 1] * inv;
                size_t o = (size_t)b * Tn * En + (size_t)(q0 + rloc) * En + colg;
                *(__half2*)(oh + o) = __floats2half2_rn(v0, v1);
            }
        }
    }
}

// ---------------- residual + LN ----------------
__global__ __launch_bounds__(256) void add_ln(
    float* __restrict__ x, const float* __restrict__ r,
    const float* __restrict__ g, const float* __restrict__ bt,
    __half* __restrict__ xh, __half* __restrict__ xl)
{
    const size_t base = (size_t)blockIdx.x * En;
    const int tid = threadIdx.x;
    float v[4];
    float s = 0.f, sq = 0.f;
#pragma unroll
    for (int i = 0; i < 4; i++) {
        int c = tid + i * 256;
        v[i] = x[base + c] + r[base + c];
        s += v[i];
        sq += v[i] * v[i];
    }
    float2 t = blockSum2(s, sq);
    float mu = t.x * (1.0f / En);
    float var = fmaxf(t.y * (1.0f / En) - mu * mu, 0.f);
    float rs = rsqrtf(var + 1e-5f);
#pragma unroll
    for (int i = 0; i < 4; i++) {
        int c = tid + i * 256;
        float o = (v[i] - mu) * rs * g[c] + bt[c];
        x[base + c] = o;
        if (xl) {
            split_hl(o, xh[base + c], xl[base + c]);
        } else {
            xh[base + c] = __float2half_rn(o);
        }
    }
}

__global__ __launch_bounds__(256) void head_kernel(
    const float* __restrict__ x, const float* __restrict__ hw,
    const float* __restrict__ hb, float* __restrict__ out)
{
    const int b = blockIdx.x;
    const int tid = threadIdx.x;
    const float* row = x + (size_t)b * Tn * En + (size_t)(Tn - 1) * En;
    float s = 0.f;
    for (int c = tid; c < En; c += 256) s += row[c] * hw[c];
    s = blockSum(s);
    if (tid == 0) out[b] = s + hb[0];
}

// ---------------- launch ----------------
extern "C" void kernel_launch(void* const* d_in, const int* in_sizes, int n_in,
                              void* d_out, int out_size)
{
    const float* src    = (const float*)d_in[0];
    const float* in_w   = (const float*)d_in[1];
    const float* in_b   = (const float*)d_in[2];
    const float* outp_w = (const float*)d_in[3];
    const float* outp_b = (const float*)d_in[4];
    const float* ff1_w  = (const float*)d_in[5];
    const float* ff1_b  = (const float*)d_in[6];
    const float* ff2_w  = (const float*)d_in[7];
    const float* ff2_b  = (const float*)d_in[8];
    const float* ln1_g  = (const float*)d_in[9];
    const float* ln1_b  = (const float*)d_in[10];
    const float* ln2_g  = (const float*)d_in[11];
    const float* ln2_b  = (const float*)d_in[12];
    const float* head_w = (const float*)d_in[13];
    const float* head_b = (const float*)d_in[14];
    float* out = (float*)d_out;

    static bool init = false;
    static float *x, *proj;
    static __half *xh,*xl,*ah,*fh,*qkvh,*qkvl,*wih,*woh,*w1h,*w2h;
    if (!init) {
        cudaGetSymbolAddress((void**)&x, g_x);
        cudaGetSymbolAddress((void**)&proj, g_proj);
        cudaGetSymbolAddress((void**)&xh, g_xh); cudaGetSymbolAddress((void**)&xl, g_xl);
        cudaGetSymbolAddress((void**)&ah, g_ah);
        cudaGetSymbolAddress((void**)&fh, g_fh);
        cudaGetSymbolAddress((void**)&qkvh, g_qkvh); cudaGetSymbolAddress((void**)&qkvl, g_qkvl);
        cudaGetSymbolAddress((void**)&wih, g_wih);
        cudaGetSymbolAddress((void**)&woh, g_woh);
        cudaGetSymbolAddress((void**)&w1h, g_w1h);
        cudaGetSymbolAddress((void**)&w2h, g_w2h);
        cudaFuncSetAttribute(gemm_mma2, cudaFuncAttributeMaxDynamicSharedMemorySize, 4 * STGB);
        cudaFuncSetAttribute(gemm_mma1, cudaFuncAttributeMaxDynamicSharedMemorySize, 3 * STG1);
        cudaFuncSetAttribute(attn_fused, cudaFuncAttributeMaxDynamicSharedMemorySize, AF_SMEM);
        init = true;
    }

    // weights -> fp16 hi
    convert_h4<<<Ln * 3 * En * En / 1024, 256>>>((const float4*)in_w, (__half2*)wih);
    convert_h4<<<Ln * En * En / 1024, 256>>>((const float4*)outp_w, (__half2*)woh);
    convert_h4<<<Ln * FFn * En / 1024, 256>>>((const float4*)ff1_w, (__half2*)w1h);
    convert_h4<<<Ln * En * FFn / 1024, 256>>>((const float4*)ff2_w, (__half2*)w2h);

    pe_add_kernel<<<Bn * Tn * En / 256, 256>>>(src, x, xh, xl);

    for (int l = 0; l < Ln; l++) {
        size_t wo3 = (size_t)l * 3 * En * En, wo1 = (size_t)l * En * En;
        size_t wof = (size_t)l * FFn * En;
        // qkv (2-term A, fp16 hi/lo out)
        gemm_mma2<<<dim3(3 * En / BN, Bn * Tn / BM), 256, 4 * STGB>>>(
            xh, xl, wih + wo3, in_b + (size_t)l * 3 * En,
            qkvh, qkvl, En, 3 * En);
        // fused attention (hi-only O)
        attn_fused<<<dim3(Tn / QT, Bn * Hn), 256, AF_SMEM>>>(qkvh, qkvl, ah);
        // out proj (1-term, BK=64)
        gemm_mma1<<<dim3(En / BN, Bn * Tn / BM), 256, 3 * STG1>>>(
            ah, woh + wo1, outp_b + (size_t)l * En, proj, nullptr, En, En, 0);
        add_ln<<<Bn * Tn, 256>>>(x, proj, ln1_g + (size_t)l * En, ln1_b + (size_t)l * En, xh, xl);
        // ff1 (1-term, BK=64, relu, hi out)
        gemm_mma1<<<dim3(FFn / BN, Bn * Tn / BM), 256, 3 * STG1>>>(
            xh, w1h + wof, ff1_b + (size_t)l * FFn, nullptr, fh, En, FFn, 1);
        // ff2 (1-term, BK=64)
        gemm_mma1<<<dim3(En / BN, Bn * Tn / BM), 256, 3 * STG1>>>(
            fh, w2h + wof, ff2_b + (size_t)l * En, proj, nullptr, FFn, En, 0);
        add_ln<<<Bn * Tn, 256>>>(x, proj, ln2_g + (size_t)l * En, ln2_b + (size_t)l * En, xh, xl);
    }

    head_kernel<<<Bn, 256>>>(x, head_w, head_b, out);
}

// round 17
// speedup vs baseline: 2.1793x; 1.0060x over previous
#include <cuda_runtime.h>
#include <cuda_fp16.h>
#include <math.h>
#include <stdint.h>

#define Bn  8
#define Tn  512
#define En  1024
#define Hn  16
#define Dn  64
#define Ln  4
#define FFn 4096

// fp32 scratch
__device__ float g_x[Bn * Tn * En];
__device__ float g_proj[Bn * Tn * En];
__device__ float g_pe[Bn * En];
// fp16 activations
__device__ __half g_xh[Bn * Tn * En],  g_xl[Bn * Tn * En];
__device__ __half g_ah[Bn * Tn * En];
__device__ __half g_fh[Bn * Tn * FFn];
__device__ __half g_qkvh[Bn * Tn * 3 * En], g_qkvl[Bn * Tn * 3 * En];
// fp16 weight (hi only)
__device__ __half g_wih[Ln * 3 * En * En];
__device__ __half g_woh[Ln * En * En];
__device__ __half g_w1h[Ln * FFn * En];
__device__ __half g_w2h[Ln * En * FFn];

// ---------------- PTX helpers (sm_80+ only) ----------------
__device__ __forceinline__ uint32_t smem_u32(const void* p) {
    uint32_t a;
    asm("{ .reg .u64 t; cvta.to.shared.u64 t, %1; cvt.u32.u64 %0, t; }" : "=r"(a) : "l"(p));
    return a;
}
__device__ __forceinline__ void cpasync16(uint32_t dst, const void* src) {
    asm volatile("cp.async.cg.shared.global [%0], [%1], 16;" :: "r"(dst), "l"(src));
}
__device__ __forceinline__ void cp_commit() { asm volatile("cp.async.commit_group;" ::: "memory"); }
template <int N> __device__ __forceinline__ void cp_wait() {
    asm volatile("cp.async.wait_group %0;" :: "n"(N) : "memory");
}
__device__ __forceinline__ void ldsm4(uint32_t& r0, uint32_t& r1, uint32_t& r2,
                                      uint32_t& r3, uint32_t a) {
    asm volatile("ldmatrix.sync.aligned.m8n8.x4.shared.b16 {%0,%1,%2,%3}, [%4];"
                 : "=r"(r0), "=r"(r1), "=r"(r2), "=r"(r3) : "r"(a));
}
__device__ __forceinline__ void mma16816(float* d, const uint32_t* a, uint32_t b0, uint32_t b1) {
    asm volatile("mma.sync.aligned.m16n8k16.row.col.f32.f16.f16.f32 "
                 "{%0,%1,%2,%3}, {%4,%5,%6,%7}, {%8,%9}, {%0,%1,%2,%3};"
                 : "+f"(d[0]), "+f"(d[1]), "+f"(d[2]), "+f"(d[3])
                 : "r"(a[0]), "r"(a[1]), "r"(a[2]), "r"(a[3]), "r"(b0), "r"(b1));
}
__device__ __forceinline__ void split_hl(float v, __half& h, __half& l) {
    h = __float2half_rn(v);
    l = __float2half_rn(v - __half2float(h));
}

// ---------------- reductions ----------------
__device__ __forceinline__ float warpSum(float v) {
#pragma unroll
    for (int o = 16; o; o >>= 1) v += __shfl_xor_sync(~0u, v, o);
    return v;
}
__device__ __forceinline__ float blockSum(float v) {
    __shared__ float sm[8];
    int lane = threadIdx.x & 31, wid = threadIdx.x >> 5;
    v = warpSum(v);
    __syncthreads();
    if (lane == 0) sm[wid] = v;
    __syncthreads();
    v = sm[lane & 7];
#pragma unroll
    for (int o = 4; o; o >>= 1) v += __shfl_xor_sync(~0u, v, o);
    return v;
}
__device__ __forceinline__ float2 blockSum2(float a, float b) {
    __shared__ float2 sm[8];
    int lane = threadIdx.x & 31, wid = threadIdx.x >> 5;
#pragma unroll
    for (int o = 16; o; o >>= 1) {
        a += __shfl_xor_sync(~0u, a, o);
        b += __shfl_xor_sync(~0u, b, o);
    }
    __syncthreads();
    if (lane == 0) sm[wid] = make_float2(a, b);
    __syncthreads();
    float2 v = sm[lane & 7];
#pragma unroll
    for (int o = 4; o; o >>= 1) {
        v.x += __shfl_xor_sync(~0u, v.x, o);
        v.y += __shfl_xor_sync(~0u, v.y, o);
    }
    return v;
}

// ---------------- small kernels ----------------
// merged weight conversion: 4 segments, sizes in float4 units
#define CW1 (Ln * 3 * En * En / 4)
#define CW2 (Ln * En * En / 4)
#define CW3 (Ln * FFn * En / 4)
#define CW4 (Ln * En * FFn / 4)
__global__ void convert_all(const float4* __restrict__ s1, const float4* __restrict__ s2,
                            const float4* __restrict__ s3, const float4* __restrict__ s4,
                            __half2* __restrict__ d1, __half2* __restrict__ d2,
                            __half2* __restrict__ d3, __half2* __restrict__ d4) {
    long long i = (long long)blockIdx.x * 256 + threadIdx.x;
    const float4* s; __half2* d; long long o;
    if (i < CW1)                       { s = s1; d = d1; o = i; }
    else if (i < CW1 + CW2)            { s = s2; d = d2; o = i - CW1; }
    else if (i < CW1 + CW2 + CW3)      { s = s3; d = d3; o = i - CW1 - CW2; }
    else                               { s = s4; d = d4; o = i - CW1 - CW2 - CW3; }
    float4 v = s[o];
    d[2 * o]     = __floats2half2_rn(v.x, v.y);
    d[2 * o + 1] = __floats2half2_rn(v.z, v.w);
}

__global__ void pe_table(float* __restrict__ pe) {
    int i = blockIdx.x * 256 + threadIdx.x;   // Bn*En = 8192
    int e = i & (En - 1);
    int b = i >> 10;
    float dv = expf((float)(e & ~1) * (-9.210340371976184f / (float)En));
    float ang = (float)b * dv;
    pe[i] = (e & 1) ? cosf(ang) : sinf(ang);
}

__global__ void pe_add_kernel(const float4* __restrict__ src, const float* __restrict__ pe,
                              float4* __restrict__ x,
                              __half2* __restrict__ xh, __half2* __restrict__ xl) {
    int i = blockIdx.x * 256 + threadIdx.x;   // float4 index; total Bn*Tn*En/4
    int e4 = i & (En / 4 - 1);
    int b = i / (Tn * En / 4);
    float4 v = src[i];
    const float4 p = *(const float4*)(pe + b * En + e4 * 4);
    v.x += p.x; v.y += p.y; v.z += p.z; v.w += p.w;
    x[i] = v;
    __half h0, l0, h1, l1, h2, l2, h3, l3;
    split_hl(v.x, h0, l0); split_hl(v.y, h1, l1);
    split_hl(v.z, h2, l2); split_hl(v.w, h3, l3);
    __half2 ha; ha.x = h0; ha.y = h1;
    __half2 hb; hb.x = h2; hb.y = h3;
    __half2 la; la.x = l0; la.y = l1;
    __half2 lb; lb.x = l2; lb.y = l3;
    xh[2 * i] = ha; xh[2 * i + 1] = hb;
    xl[2 * i] = la; xl[2 * i + 1] = lb;
}

// ---------------- 2-term fp16 GEMM (QKV): unchanged R16 config ----------------
#define BM 128
#define BN 128
#define BK 32
#define RGB 8192
#define STGB (3 * RGB)

__global__ __launch_bounds__(256, 2) void gemm_mma2(
    const __half* __restrict__ Ah, const __half* __restrict__ Al,
    const __half* __restrict__ Bh,
    const float* __restrict__ bias,
    __half* __restrict__ Ch, __half* __restrict__ Cl,
    int K, int N)
{
    extern __shared__ __align__(128) uint8_t dsm[];
    __shared__ float sh_bias[BN];

    const int tid = threadIdx.x;
    const uint32_t sbase = smem_u32(dsm);
    if (tid < BN) sh_bias[tid] = bias[blockIdx.x * BN + tid];

    const int wid = tid >> 5, lane = tid & 31;
    const int wm = wid >> 1, wn = wid & 1;

    const __half* Abh = Ah + (size_t)blockIdx.y * BM * K;
    const __half* Abl = Al + (size_t)blockIdx.y * BM * K;
    const __half* Bbh = Bh + (size_t)blockIdx.x * BN * K;

    const int cps = K / BK;

    auto load_chunk = [&](int c, int st) {
        int kc = c * BK;
        uint32_t sg = sbase + (uint32_t)st * STGB;
#pragma unroll
        for (int j = 0; j < 2; j++) {
            int idx = tid + j * 256;
            int r = idx >> 2, cc = idx & 3;
            uint32_t off = r * 64 + ((cc ^ ((r >> 1) & 3)) << 4);
            size_t go = (size_t)r * K + kc + cc * 8;
            cpasync16(sg + off, Abh + go);
            cpasync16(sg + RGB + off, Abl + go);
            cpasync16(sg + 2 * RGB + off, Bbh + go);
        }
        cp_commit();
    };

    float acc[2][8][4] = {};
    load_chunk(0, 0);
    load_chunk(1, 1);
    load_chunk(2, 2);

    int st = 0;
    for (int c = 0; c < cps; c++) {
        int rem = cps - 1 - c;
        if (rem >= 2)      cp_wait<2>();
        else if (rem == 1) cp_wait<1>();
        else               cp_wait<0>();
        __syncthreads();
        if (c + 3 < cps) {
            int ns = st + 3; if (ns >= 4) ns -= 4;
            load_chunk(c + 3, ns);
        }

        uint32_t sAh = sbase + (uint32_t)st * STGB;
        uint32_t sAl = sAh + RGB;
        uint32_t sBh = sAh + 2 * RGB;
#pragma unroll
        for (int ks = 0; ks < 2; ks++) {
            uint32_t ah[2][4], al[2][4];
#pragma unroll
            for (int ti = 0; ti < 2; ti++) {
                int r = wm * 32 + ti * 16 + (lane & 15);
                int cc = 2 * ks + (lane >> 4);
                uint32_t off = r * 64 + ((cc ^ ((r >> 1) & 3)) << 4);
                ldsm4(ah[ti][0], ah[ti][1], ah[ti][2], ah[ti][3], sAh + off);
                ldsm4(al[ti][0], al[ti][1], al[ti][2], al[ti][3], sAl + off);
            }
#pragma unroll
            for (int tp = 0; tp < 2; tp++) {
                uint32_t bf[2][4];
#pragma unroll
                for (int q = 0; q < 2; q++) {
                    int tj = tp * 2 + q;
                    int r = wn * 64 + tj * 16 + (lane & 15);
                    int cc = 2 * ks + (lane >> 4);
                    uint32_t off = r * 64 + ((cc ^ ((r >> 1) & 3)) << 4);
                    ldsm4(bf[q][0], bf[q][1], bf[q][2], bf[q][3], sBh + off);
                }
#pragma unroll
                for (int q = 0; q < 2; q++) {
                    int tj = tp * 2 + q;
                    mma16816(acc[0][2 * tj],     ah[0], bf[q][0], bf[q][2]);
                    mma16816(acc[0][2 * tj + 1], ah[0], bf[q][1], bf[q][3]);
                    mma16816(acc[1][2 * tj],     ah[1], bf[q][0], bf[q][2]);
                    mma16816(acc[1][2 * tj + 1], ah[1], bf[q][1], bf[q][3]);
                    mma16816(acc[0][2 * tj],     al[0], bf[q][0], bf[q][2]);
                    mma16816(acc[0][2 * tj + 1], al[0], bf[q][1], bf[q][3]);
                    mma16816(acc[1][2 * tj],     al[1], bf[q][0], bf[q][2]);
                    mma16816(acc[1][2 * tj + 1], al[1], bf[q][1], bf[q][3]);
                }
            }
        }
        if (++st == 4) st = 0;
    }

    const int col0 = wn * 64;
    const int row0 = blockIdx.y * BM + wm * 32;
#pragma unroll
    for (int ti = 0; ti < 2; ti++) {
#pragma unroll
        for (int tj = 0; tj < 8; tj++) {
            int cl = col0 + tj * 8 + 2 * (lane & 3);
            int colg = blockIdx.x * BN + cl;
            float b0 = sh_bias[cl], b1 = sh_bias[cl + 1];
#pragma unroll
            for (int hh = 0; hh < 2; hh++) {
                int row = row0 + ti * 16 + (lane >> 2) + hh * 8;
                float v0 = acc[ti][tj][2 * hh + 0] + b0;
                float v1 = acc[ti][tj][2 * hh + 1] + b1;
                size_t o = (size_t)row * N + colg;
                __half h0, l0, h1, l1;
                split_hl(v0, h0, l0);
                split_hl(v1, h1, l1);
                __half2 hv; hv.x = h0; hv.y = h1;
                __half2 lv; lv.x = l0; lv.y = l1;
                *(__half2*)(Ch + o) = hv;
                *(__half2*)(Cl + o) = lv;
            }
        }
    }
}

// ---------------- 1-term fp16 GEMM, BK=64 (unchanged R16) ----------------
#define STG1 32768

__global__ __launch_bounds__(256, 2) void gemm_mma1(
    const __half* __restrict__ Ah, const __half* __restrict__ Bh,
    const float* __restrict__ bias, float* __restrict__ Cf,
    __half* __restrict__ Ch, int K, int N, int relu)
{
    extern __shared__ __align__(128) uint8_t dsm[];
    __shared__ float sh_bias[BN];

    const int tid = threadIdx.x;
    const uint32_t sbase = smem_u32(dsm);
    if (tid < BN) sh_bias[tid] = bias[blockIdx.x * BN + tid];

    const int wid = tid >> 5, lane = tid & 31;
    const int wm = wid >> 1, wn = wid & 1;

    const __half* Abh = Ah + (size_t)blockIdx.y * BM * K;
    const __half* Bbh = Bh + (size_t)blockIdx.x * BN * K;

    const int cps = K / 64;

    auto load_chunk = [&](int c, int st) {
        int kc = c * 64;
        uint32_t sg = sbase + (uint32_t)st * STG1;
#pragma unroll
        for (int j = 0; j < 4; j++) {
            int idx = tid + j * 256;
            int r = idx >> 3, gg = idx & 7;
            int sub = gg >> 2, grp = gg & 3;
            uint32_t off = (uint32_t)sub * 8192 + r * 64 + ((grp ^ ((r >> 1) & 3)) << 4);
            size_t go = (size_t)r * K + kc + gg * 8;
            cpasync16(sg + off, Abh + go);
            cpasync16(sg + 16384 + off, Bbh + go);
        }
        cp_commit();
    };

    float acc[2][8][4] = {};
    load_chunk(0, 0);
    load_chunk(1, 1);

    int st = 0;
    for (int c = 0; c < cps; c++) {
        if (c + 1 < cps) cp_wait<1>(); else cp_wait<0>();
        __syncthreads();
        if (c + 2 < cps) {
            int ns = st + 2; if (ns >= 3) ns -= 3;
            load_chunk(c + 2, ns);
        }

        uint32_t sg = sbase + (uint32_t)st * STG1;
#pragma unroll
        for (int sub = 0; sub < 2; sub++) {
            uint32_t sAh = sg + (uint32_t)sub * 8192;
            uint32_t sBh = sg + 16384 + (uint32_t)sub * 8192;
#pragma unroll
            for (int ks = 0; ks < 2; ks++) {
                uint32_t ah[2][4];
#pragma unroll
                for (int ti = 0; ti < 2; ti++) {
                    int r = wm * 32 + ti * 16 + (lane & 15);
                    int cc = 2 * ks + (lane >> 4);
                    uint32_t off = r * 64 + ((cc ^ ((r >> 1) & 3)) << 4);
                    ldsm4(ah[ti][0], ah[ti][1], ah[ti][2], ah[ti][3], sAh + off);
                }
                uint32_t bf[4][4];
#pragma unroll
                for (int tj = 0; tj < 4; tj++) {
                    int r = wn * 64 + tj * 16 + (lane & 15);
                    int cc = 2 * ks + (lane >> 4);
                    uint32_t off = r * 64 + ((cc ^ ((r >> 1) & 3)) << 4);
                    ldsm4(bf[tj][0], bf[tj][1], bf[tj][2], bf[tj][3], sBh + off);
                }
#pragma unroll
                for (int tj = 0; tj < 4; tj++) {
                    mma16816(acc[0][2 * tj],     ah[0], bf[tj][0], bf[tj][2]);
                    mma16816(acc[0][2 * tj + 1], ah[0], bf[tj][1], bf[tj][3]);
                    mma16816(acc[1][2 * tj],     ah[1], bf[tj][0], bf[tj][2]);
                    mma16816(acc[1][2 * tj + 1], ah[1], bf[tj][1], bf[tj][3]);
                }
            }
        }
        if (++st == 3) st = 0;
    }

    const int col0 = wn * 64;
    const int row0 = blockIdx.y * BM + wm * 32;
#pragma unroll
    for (int ti = 0; ti < 2; ti++) {
#pragma unroll
        for (int tj = 0; tj < 8; tj++) {
            int cl = col0 + tj * 8 + 2 * (lane & 3);
            int colg = blockIdx.x * BN + cl;
            float b0 = sh_bias[cl], b1 = sh_bias[cl + 1];
#pragma unroll
            for (int hh = 0; hh < 2; hh++) {
                int row = row0 + ti * 16 + (lane >> 2) + hh * 8;
                float v0 = acc[ti][tj][2 * hh + 0] + b0;
                float v1 = acc[ti][tj][2 * hh + 1] + b1;
                if (relu) { v0 = fmaxf(v0, 0.f); v1 = fmaxf(v1, 0.f); }
                size_t o = (size_t)row * N + colg;
                if (Cf) *(float2*)(Cf + o) = make_float2(v0, v1);
                if (Ch) *(__half2*)(Ch + o) = __floats2half2_rn(v0, v1);
            }
        }
    }
}

// ---------------- fused attention v3 (unchanged R16) ----------------
#define QT 64
#define AF_SQ 0
#define AF_SK 16384
#define AF_SV 49152
#define AF_SP 81920
#define AF_SZ 98304
#define AF_SMEM (98304 + 768)

__global__ __launch_bounds__(256, 2) void attn_fused(
    const __half* __restrict__ qkvh, const __half* __restrict__ qkvl,
    __half* __restrict__ oh)
{
    extern __shared__ __align__(128) uint8_t dsm[];
    const int tid = threadIdx.x;
    const uint32_t sbase = smem_u32(dsm);
    const int wid = tid >> 5, lane = tid & 31;
    const int wm = wid >> 2, wn = wid & 3;
    const int bh = blockIdx.y, b = bh >> 4, h = bh & 15;
    const int q0 = blockIdx.x * QT;
    const int LDQ = 3 * En;

    float* sZ = (float*)(dsm + AF_SZ);
    float* sG = (float*)(dsm + AF_SZ + 256);
    float* sInv = (float*)(dsm + AF_SZ + 512);

    const __half* Qhb = qkvh + (size_t)b * Tn * LDQ + h * Dn + (size_t)q0 * LDQ;
    const __half* Qlb = qkvl + (size_t)b * Tn * LDQ + h * Dn + (size_t)q0 * LDQ;
    const __half* Khb = qkvh + (size_t)b * Tn * LDQ + En + h * Dn;
    const __half* Klb = qkvl + (size_t)b * Tn * LDQ + En + h * Dn;
    const __half* Vhb = qkvh + (size_t)b * Tn * LDQ + 2 * En + h * Dn;
    const __half* Vlb = qkvl + (size_t)b * Tn * LDQ + 2 * En + h * Dn;

    auto loadQ = [&]() {
#pragma unroll
        for (int j = 0; j < 2; j++) {
            int idx = tid + j * 256;
            int r = idx >> 3, gg = idx & 7;
            int chunk = gg >> 2, grp = gg & 3;
            uint32_t off = (uint32_t)chunk * 4096 + r * 64 + ((grp ^ ((r >> 1) & 3)) << 4);
            size_t go = (size_t)r * LDQ + gg * 8;
            cpasync16(sbase + AF_SQ + off, Qhb + go);
            cpasync16(sbase + AF_SQ + 8192 + off, Qlb + go);
        }
        cp_commit();
    };

    auto loadK = [&](int kt) {
#pragma unroll
        for (int j = 0; j < 4; j++) {
            int idx = tid + j * 256;
            int r = idx >> 3, gg = idx & 7;
            int chunk = gg >> 2, grp = gg & 3;
            uint32_t off = (uint32_t)chunk * 8192 + r * 64 + ((grp ^ ((r >> 1) & 3)) << 4);
            size_t go = (size_t)(kt * 128 + r) * LDQ + gg * 8;
            cpasync16(sbase + AF_SK + off, Khb + go);
            cpasync16(sbase + AF_SK + 16384 + off, Klb + go);
        }
        cp_commit();
    };

    uint4 vh4[4], vl4[4];
    auto ldgV = [&](int kt) {
        int kk = tid >> 3;
        int d0 = (tid & 7) * 8;
#pragma unroll
        for (int p = 0; p < 4; p++) {
            size_t go = (size_t)(kt * 128 + p * 32 + kk) * LDQ + d0;
            vh4[p] = *(const uint4*)(Vhb + go);
            vl4[p] = *(const uint4*)(Vlb + go);
        }
    };
    auto stsV = [&]() {
        int kk = tid >> 3;
        int d0 = (tid & 7) * 8;
#pragma unroll
        for (int p = 0; p < 4; p++) {
            uint32_t h4[4] = {vh4[p].x, vh4[p].y, vh4[p].z, vh4[p].w};
            uint32_t l4[4] = {vl4[p].x, vl4[p].y, vl4[p].z, vl4[p].w};
#pragma unroll
            for (int i = 0; i < 8; i++) {
                uint16_t hb16 = (uint16_t)(h4[i >> 1] >> ((i & 1) * 16));
                uint16_t lb16 = (uint16_t)(l4[i >> 1] >> ((i & 1) * 16));
                int d = d0 + i;
                int fd = ((d >> 1) & 3) ^ ((d >> 3) & 3);
                uint32_t off = (uint32_t)p * 4096 + d * 64 + (((kk >> 3) ^ fd) << 4) + (kk & 7) * 2;
                *(uint16_t*)(dsm + AF_SV + off) = hb16;
                *(uint16_t*)(dsm + AF_SV + 16384 + off) = lb16;
            }
        }
    };

    loadQ();
    if (tid < QT) { sZ[tid] = 0.f; sG[tid] = 0.f; }

    float accO[2][2][4] = {};
    float zacc[4] = {}, gacc[4] = {};

    for (int kt = 0; kt < 4; kt++) {
        __syncthreads();
        loadK(kt);
        ldgV(kt);
        cp_wait<0>();
        __syncthreads();
        stsV();

        float acc2[2][4][4] = {};
#pragma unroll
        for (int c = 0; c < 2; c++) {
            uint32_t sAh = sbase + AF_SQ + (uint32_t)c * 4096, sAl = sAh + 8192;
            uint32_t sBh = sbase + AF_SK + (uint32_t)c * 8192, sBl = sBh + 16384;
#pragma unroll
            for (int ks = 0; ks < 2; ks++) {
                uint32_t ah[2][4], al[2][4];
#pragma unroll
                for (int ti = 0; ti < 2; ti++) {
                    int r = wm * 32 + ti * 16 + (lane & 15);
                    int cc = 2 * ks + (lane >> 4);
                    uint32_t off = r * 64 + ((cc ^ ((r >> 1) & 3)) << 4);
                    ldsm4(ah[ti][0], ah[ti][1], ah[ti][2], ah[ti][3], sAh + off);
                    ldsm4(al[ti][0], al[ti][1], al[ti][2], al[ti][3], sAl + off);
                }
#pragma unroll
                for (int tjj = 0; tjj < 2; tjj++) {
                    int r = wn * 32 + tjj * 16 + (lane & 15);
                    int cc = 2 * ks + (lane >> 4);
                    uint32_t off = r * 64 + ((cc ^ ((r >> 1) & 3)) << 4);
                    uint32_t b0, b1, b2, b3, c0, c1, c2, c3;
                    ldsm4(b0, b1, b2, b3, sBh + off);
                    ldsm4(c0, c1, c2, c3, sBl + off);
#pragma unroll
                    for (int ti = 0; ti < 2; ti++) {
                        mma16816(acc2[ti][2 * tjj],     ah[ti], b0, b2);
                        mma16816(acc2[ti][2 * tjj + 1], ah[ti], b1, b3);
                        mma16816(acc2[ti][2 * tjj],     al[ti], b0, b2);
                        mma16816(acc2[ti][2 * tjj + 1], al[ti], b1, b3);
                        mma16816(acc2[ti][2 * tjj],     ah[ti], c0, c2);
                        mma16816(acc2[ti][2 * tjj + 1], ah[ti], c1, c3);
                    }
                }
            }
        }

#pragma unroll
        for (int ti = 0; ti < 2; ti++) {
#pragma unroll
            for (int hh = 0; hh < 2; hh++) {
                int rloc = wm * 32 + ti * 16 + (lane >> 2) + hh * 8;
                float qg = (float)(q0 + rloc);
                float zs = 0.f, gs = 0.f;
#pragma unroll
                for (int tj = 0; tj < 4; tj++) {
                    int kcl = wn * 32 + tj * 8 + 2 * (lane & 3);
                    float kg = (float)(kt * 128 + kcl);
                    float s0 = acc2[ti][tj][2 * hh + 0] * 0.125f;
                    float s1 = acc2[ti][tj][2 * hh + 1] * 0.125f;
                    float p0 = __expf(s0), p1 = __expf(s1);
                    float d0 = qg - kg, d1 = qg - (kg + 1.0f);
                    float g0 = __expf(-d0 * d0 * (1.0f / 32768.0f));
                    float g1 = __expf(-d1 * d1 * (1.0f / 32768.0f));
                    float pg0 = p0 * g0, pg1 = p1 * g1;
                    zs += p0 + p1;
                    gs += pg0 + pg1;
                    __half2 ph2 = __floats2half2_rn(pg0, pg1);
                    int chunk = kcl >> 5;
                    int c32 = kcl & 31;
                    uint32_t off = (uint32_t)chunk * 4096 + rloc * 64
                                 + (((c32 >> 3) ^ ((rloc >> 1) & 3)) << 4) + (c32 & 7) * 2;
                    *(__half2*)(dsm + AF_SP + off) = ph2;
                }
                zacc[ti * 2 + hh] += zs;
                gacc[ti * 2 + hh] += gs;
            }
        }
        __syncthreads();

#pragma unroll
        for (int ch = 0; ch < 4; ch++) {
            uint32_t sAh = sbase + AF_SP + (uint32_t)ch * 4096;
            uint32_t sBh = sbase + AF_SV + (uint32_t)ch * 4096, sBl = sBh + 16384;
#pragma unroll
            for (int ks = 0; ks < 2; ks++) {
                uint32_t ph[2][4];
#pragma unroll
                for (int ti = 0; ti < 2; ti++) {
                    int r = wm * 32 + ti * 16 + (lane & 15);
                    int cc = 2 * ks + (lane >> 4);
                    uint32_t off = r * 64 + ((cc ^ ((r >> 1) & 3)) << 4);
                    ldsm4(ph[ti][0], ph[ti][1], ph[ti][2], ph[ti][3], sAh + off);
                }
                int r = wn * 16 + (lane & 15);
                int cc = 2 * ks + (lane >> 4);
                int fd = ((r >> 1) & 3) ^ ((r >> 3) & 3);
                uint32_t off = r * 64 + ((cc ^ fd) << 4);
                uint32_t b0, b1, b2, b3, c0, c1, c2, c3;
                ldsm4(b0, b1, b2, b3, sBh + off);
                ldsm4(c0, c1, c2, c3, sBl + off);
#pragma unroll
                for (int ti = 0; ti < 2; ti++) {
                    mma16816(accO[ti][0], ph[ti], b0, b2);
                    mma16816(accO[ti][1], ph[ti], b1, b3);
                    mma16816(accO[ti][0], ph[ti], c0, c2);
                    mma16816(accO[ti][1], ph[ti], c1, c3);
                }
            }
        }
    }

#pragma unroll
    for (int s = 0; s < 4; s++) {
        zacc[s] += __shfl_xor_sync(~0u, zacc[s], 1);
        zacc[s] += __shfl_xor_sync(~0u, zacc[s], 2);
        gacc[s] += __shfl_xor_sync(~0u, gacc[s], 1);
        gacc[s] += __shfl_xor_sync(~0u, gacc[s], 2);
    }
    if ((lane & 3) == 0) {
#pragma unroll
        for (int ti = 0; ti < 2; ti++)
#pragma unroll
            for (int hh = 0; hh < 2; hh++) {
                int rloc = wm * 32 + ti * 16 + (lane >> 2) + hh * 8;
                atomicAdd(&sZ[rloc], zacc[ti * 2 + hh]);
                atomicAdd(&sG[rloc], gacc[ti * 2 + hh]);
            }
    }
    __syncthreads();
    if (tid < QT) sInv[tid] = 1.0f / (sG[tid] + 1e-5f * sZ[tid]);
    __syncthreads();

#pragma unroll
    for (int ti = 0; ti < 2; ti++) {
#pragma unroll
        for (int tj = 0; tj < 2; tj++) {
            int dl = wn * 16 + tj * 8 + 2 * (lane & 3);
            int colg = h * Dn + dl;
#pragma unroll
            for (int hh = 0; hh < 2; hh++) {
                int rloc = wm * 32 + ti * 16 + (lane >> 2) + hh * 8;
                float inv = sInv[rloc];
                float v0 = accO[ti][tj][2 * hh + 0] * inv;
                float v1 = accO[ti][tj][2 * hh + 1] * inv;
                size_t o = (size_t)b * Tn * En + (size_t)(q0 + rloc) * En + colg;
                *(__half2*)(oh + o) = __floats2half2_rn(v0, v1);
            }
        }
    }
}

// ---------------- residual + LN (float4 vectorized) ----------------
__global__ __launch_bounds__(256) void add_ln(
    const float4* __restrict__ x4, const float4* __restrict__ r4,
    float4* __restrict__ xo4,
    const float* __restrict__ g, const float* __restrict__ bt,
    __half2* __restrict__ xh, __half2* __restrict__ xl)
{
    const size_t base = (size_t)blockIdx.x * (En / 4);
    const int tid = threadIdx.x;
    float4 a = x4[base + tid];
    float4 r = r4[base + tid];
    a.x += r.x; a.y += r.y; a.z += r.z; a.w += r.w;
    float s = a.x + a.y + a.z + a.w;
    float sq = a.x * a.x + a.y * a.y + a.z * a.z + a.w * a.w;
    float2 t = blockSum2(s, sq);
    float mu = t.x * (1.0f / En);
    float var = fmaxf(t.y * (1.0f / En) - mu * mu, 0.f);
    float rs = rsqrtf(var + 1e-5f);
    const float4 gg = *(const float4*)(g + tid * 4);
    const float4 bb = *(const float4*)(bt + tid * 4);
    float4 o;
    o.x = (a.x - mu) * rs * gg.x + bb.x;
    o.y = (a.y - mu) * rs * gg.y + bb.y;
    o.z = (a.z - mu) * rs * gg.z + bb.z;
    o.w = (a.w - mu) * rs * gg.w + bb.w;
    xo4[base + tid] = o;
    __half h0, l0, h1, l1, h2, l2, h3, l3;
    split_hl(o.x, h0, l0); split_hl(o.y, h1, l1);
    split_hl(o.z, h2, l2); split_hl(o.w, h3, l3);
    __half2 ha; ha.x = h0; ha.y = h1;
    __half2 hb; hb.x = h2; hb.y = h3;
    xh[base * 2 + tid * 2] = ha;
    xh[base * 2 + tid * 2 + 1] = hb;
    if (xl) {
        __half2 la; la.x = l0; la.y = l1;
        __half2 lb; lb.x = l2; lb.y = l3;
        xl[base * 2 + tid * 2] = la;
        xl[base * 2 + tid * 2 + 1] = lb;
    }
}

__global__ __launch_bounds__(256) void head_kernel(
    const float* __restrict__ x, const float* __restrict__ hw,
    const float* __restrict__ hb, float* __restrict__ out)
{
    const int b = blockIdx.x;
    const int tid = threadIdx.x;
    const float* row = x + (size_t)b * Tn * En + (size_t)(Tn - 1) * En;
    float s = 0.f;
    for (int c = tid; c < En; c += 256) s += row[c] * hw[c];
    s = blockSum(s);
    if (tid == 0) out[b] = s + hb[0];
}

// ---------------- launch ----------------
extern "C" void kernel_launch(void* const* d_in, const int* in_sizes, int n_in,
                              void* d_out, int out_size)
{
    const float* src    = (const float*)d_in[0];
    const float* in_w   = (const float*)d_in[1];
    const float* in_b   = (const float*)d_in[2];
    const float* outp_w = (const float*)d_in[3];
    const float* outp_b = (const float*)d_in[4];
    const float* ff1_w  = (const float*)d_in[5];
    const float* ff1_b  = (const float*)d_in[6];
    const float* ff2_w  = (const float*)d_in[7];
    const float* ff2_b  = (const float*)d_in[8];
    const float* ln1_g  = (const float*)d_in[9];
    const float* ln1_b  = (const float*)d_in[10];
    const float* ln2_g  = (const float*)d_in[11];
    const float* ln2_b  = (const float*)d_in[12];
    const float* head_w = (const float*)d_in[13];
    const float* head_b = (const float*)d_in[14];
    float* out = (float*)d_out;

    static bool init = false;
    static float *x, *proj, *pe;
    static __half *xh,*xl,*ah,*fh,*qkvh,*qkvl,*wih,*woh,*w1h,*w2h;
    if (!init) {
        cudaGetSymbolAddress((void**)&x, g_x);
        cudaGetSymbolAddress((void**)&proj, g_proj);
        cudaGetSymbolAddress((void**)&pe, g_pe);
        cudaGetSymbolAddress((void**)&xh, g_xh); cudaGetSymbolAddress((void**)&xl, g_xl);
        cudaGetSymbolAddress((void**)&ah, g_ah);
        cudaGetSymbolAddress((void**)&fh, g_fh);
        cudaGetSymbolAddress((void**)&qkvh, g_qkvh); cudaGetSymbolAddress((void**)&qkvl, g_qkvl);
        cudaGetSymbolAddress((void**)&wih, g_wih);
        cudaGetSymbolAddress((void**)&woh, g_woh);
        cudaGetSymbolAddress((void**)&w1h, g_w1h);
        cudaGetSymbolAddress((void**)&w2h, g_w2h);
        cudaFuncSetAttribute(gemm_mma2, cudaFuncAttributeMaxDynamicSharedMemorySize, 4 * STGB);
        cudaFuncSetAttribute(gemm_mma1, cudaFuncAttributeMaxDynamicSharedMemorySize, 3 * STG1);
        cudaFuncSetAttribute(attn_fused, cudaFuncAttributeMaxDynamicSharedMemorySize, AF_SMEM);
        init = true;
    }

    // weights -> fp16 hi (single merged launch)
    convert_all<<<(CW1 + CW2 + CW3 + CW4) / 256, 256>>>(
        (const float4*)in_w, (const float4*)outp_w, (const float4*)ff1_w, (const float4*)ff2_w,
        (__half2*)wih, (__half2*)woh, (__half2*)w1h, (__half2*)w2h);

    pe_table<<<Bn * En / 256, 256>>>(pe);
    pe_add_kernel<<<Bn * Tn * En / 1024, 256>>>(
        (const float4*)src, pe, (float4*)x, (__half2*)xh, (__half2*)xl);

    for (int l = 0; l < Ln; l++) {
        size_t wo3 = (size_t)l * 3 * En * En, wo1 = (size_t)l * En * En;
        size_t wof = (size_t)l * FFn * En;
        // qkv (2-term A, fp16 hi/lo out)
        gemm_mma2<<<dim3(3 * En / BN, Bn * Tn / BM), 256, 4 * STGB>>>(
            xh, xl, wih + wo3, in_b + (size_t)l * 3 * En,
            qkvh, qkvl, En, 3 * En);
        // fused attention (hi-only O)
        attn_fused<<<dim3(Tn / QT, Bn * Hn), 256, AF_SMEM>>>(qkvh, qkvl, ah);
        // out proj (1-term, BK=64)
        gemm_mma1<<<dim3(En / BN, Bn * Tn / BM), 256, 3 * STG1>>>(
            ah, woh + wo1, outp_b + (size_t)l * En, proj, nullptr, En, En, 0);
        add_ln<<<Bn * Tn, 256>>>((const float4*)x, (const float4*)proj, (float4*)x,
            ln1_g + (size_t)l * En, ln1_b + (size_t)l * En, (__half2*)xh, (__half2*)xl);
        // ff1 (1-term, BK=64, relu, hi out)
        gemm_mma1<<<dim3(FFn / BN, Bn * Tn / BM), 256, 3 * STG1>>>(
            xh, w1h + wof, ff1_b + (size_t)l * FFn, nullptr, fh, En, FFn, 1);
        // ff2 (1-term, BK=64)
        gemm_mma1<<<dim3(En / BN, Bn * Tn / BM), 256, 3 * STG1>>>(
            fh, w2h + wof, ff2_b + (size_t)l * En, proj, nullptr, FFn, En, 0);
        add_ln<<<Bn * Tn, 256>>>((const float4*)x, (const float4*)proj, (float4*)x,
            ln2_g + (size_t)l * En, ln2_b + (size_t)l * En, (__half2*)xh, (__half2*)xl);
    }

    head_kernel<<<Bn, 256>>>(x, head_w, head_b, out);
}